// round 1
// baseline (speedup 1.0000x reference)
#include <cuda_runtime.h>
#include <cuda_bf16.h>
#include <math.h>

#define B_ 2
#define S_ 2048
#define D_ 1024
#define L_ 6
#define H_ 16
#define HD_ 64
#define FF_ 4096
#define V_ 32000
#define TOK_ (B_ * S_)          // 4096 token rows

// ---------------- scratch (static device globals; no allocation) ----------
__device__ float g_x[TOK_ * D_];        // 16 MB  activations
__device__ float g_tmp[TOK_ * FF_];     // 64 MB  qkv (3072 cols) / ffn hidden (4096 cols) / o-proj (1024)
__device__ float g_o[TOK_ * D_];        // 16 MB  attention / ffn output

// ---------------- embedding + sinusoidal positional encoding --------------
__global__ void embed_kernel(const int* __restrict__ tokens,
                             const float* __restrict__ emb,
                             float* __restrict__ x) {
    int row = blockIdx.x;              // 0 .. TOK_-1
    int s   = row & (S_ - 1);          // position within sequence
    int tok = tokens[row];
    const float* erow = emb + (size_t)tok * D_;
    float* xrow = x + (size_t)row * D_;
    const float kfac = -0.00899447301950812f;   // -ln(10000)/1024
    #pragma unroll
    for (int j = 0; j < 4; ++j) {
        int c = threadIdx.x + j * 256;
        float freq = expf(kfac * (float)(c & ~1));
        float arg  = (float)s * freq;
        float pe   = (c & 1) ? cosf(arg) : sinf(arg);
        xrow[c] = erow[c] + pe;
    }
}

// ---------------- generic tiled fp32 GEMM: C = A[MxK] @ W[KxN] + bias -----
// BM=BN=64, BK=16, 256 threads, 4x4 per thread. M,N %64==0, K %16==0.
__global__ void gemm_kernel(const float* __restrict__ A,
                            const float* __restrict__ W,
                            const float* __restrict__ bias,
                            float* __restrict__ C,
                            int M, int N, int K, int relu) {
    __shared__ float As[16][64];
    __shared__ float Bs[16][64];

    int tid = threadIdx.x;
    int tx = tid & 15;          // 0..15 -> col group
    int ty = tid >> 4;          // 0..15 -> row group
    int bx = blockIdx.x, by = blockIdx.y;

    // A-load mapping: m = tid/4 (0..63), kq = (tid%4)*4
    int am = tid >> 2;
    int ak = (tid & 3) << 2;
    // B-load mapping: k = tid/16 (0..15), nq = (tid%16)*4
    int bk = tid >> 4;
    int bn = (tid & 15) << 2;

    const float* Ab = A + (size_t)(by * 64 + am) * K + ak;
    const float* Wb = W + (size_t)bk * N + bx * 64 + bn;

    float acc[4][4];
    #pragma unroll
    for (int i = 0; i < 4; ++i)
        #pragma unroll
        for (int j = 0; j < 4; ++j) acc[i][j] = 0.f;

    for (int k0 = 0; k0 < K; k0 += 16) {
        float4 av = *(const float4*)(Ab + k0);
        As[ak + 0][am] = av.x;
        As[ak + 1][am] = av.y;
        As[ak + 2][am] = av.z;
        As[ak + 3][am] = av.w;
        float4 bv = *(const float4*)(Wb + (size_t)k0 * N);
        *(float4*)&Bs[bk][bn] = bv;
        __syncthreads();

        #pragma unroll
        for (int k = 0; k < 16; ++k) {
            float4 a = *(const float4*)&As[k][ty << 2];
            float4 b = *(const float4*)&Bs[k][tx << 2];
            float ar[4] = {a.x, a.y, a.z, a.w};
            float br[4] = {b.x, b.y, b.z, b.w};
            #pragma unroll
            for (int i = 0; i < 4; ++i)
                #pragma unroll
                for (int j = 0; j < 4; ++j)
                    acc[i][j] = fmaf(ar[i], br[j], acc[i][j]);
        }
        __syncthreads();
    }

    int r0 = by * 64 + (ty << 2);
    int c0 = bx * 64 + (tx << 2);
    #pragma unroll
    for (int i = 0; i < 4; ++i) {
        float* crow = C + (size_t)(r0 + i) * N + c0;
        #pragma unroll
        for (int j = 0; j < 4; ++j) {
            float v = acc[i][j] + bias[c0 + j];
            if (relu) v = fmaxf(v, 0.f);
            crow[j] = v;
        }
    }
}

// ---------------- causal attention, one warp per query row ----------------
// qkv layout: [TOK_, 3*D_], cols split [3][H][HD]: q@h*64, k@1024+h*64, v@2048+h*64
__global__ void attn_kernel(const float* __restrict__ qkv,
                            float* __restrict__ o) {
    int w = blockIdx.x * 4 + (threadIdx.x >> 5);   // global warp = query id
    int lane = threadIdx.x & 31;
    int s  = w & (S_ - 1);
    int bh = w >> 11;                // w / S_
    int h  = bh & (H_ - 1);
    int b  = bh >> 4;                // bh / H_

    int t = b * S_ + s;
    const float* qrow = qkv + (size_t)t * 3072 + h * 64;
    float q0 = qrow[lane];
    float q1 = qrow[lane + 32];
    const float scale = 0.125f;      // 1/sqrt(64)

    float m = -INFINITY, denom = 0.f, acc0 = 0.f, acc1 = 0.f;
    const float* kbase = qkv + (size_t)(b * S_) * 3072 + 1024 + h * 64;
    const float* vbase = kbase + 1024;

    for (int j = 0; j <= s; ++j) {
        const float* krow = kbase + (size_t)j * 3072;
        float dot = q0 * krow[lane] + q1 * krow[lane + 32];
        #pragma unroll
        for (int off = 16; off > 0; off >>= 1)
            dot += __shfl_xor_sync(0xffffffffu, dot, off);
        dot *= scale;
        float mn = fmaxf(m, dot);
        float corr = expf(m - mn);
        float p = expf(dot - mn);
        const float* vrow = vbase + (size_t)j * 3072;
        acc0 = acc0 * corr + p * vrow[lane];
        acc1 = acc1 * corr + p * vrow[lane + 32];
        denom = denom * corr + p;
        m = mn;
    }
    float inv = 1.f / denom;
    float* orow = o + (size_t)t * D_ + h * 64;
    orow[lane]      = acc0 * inv;
    orow[lane + 32] = acc1 * inv;
}

// ---------------- fused residual add + LayerNorm (in place on x) ----------
__global__ void add_ln_kernel(float* __restrict__ x,
                              const float* __restrict__ r,
                              const float* __restrict__ g,
                              const float* __restrict__ bb) {
    int row = blockIdx.x;
    int tid = threadIdx.x;
    size_t base = (size_t)row * D_;
    float v[4];
    float s = 0.f;
    #pragma unroll
    for (int j = 0; j < 4; ++j) {
        int c = tid + j * 256;
        v[j] = x[base + c] + r[base + c];
        s += v[j];
    }
    __shared__ float sh[8];
    // reduce sum
    #pragma unroll
    for (int off = 16; off > 0; off >>= 1) s += __shfl_xor_sync(0xffffffffu, s, off);
    if ((tid & 31) == 0) sh[tid >> 5] = s;
    __syncthreads();
    if (tid < 32) {
        float t = (tid < 8) ? sh[tid] : 0.f;
        #pragma unroll
        for (int off = 4; off > 0; off >>= 1) t += __shfl_xor_sync(0xffffffffu, t, off);
        if (tid == 0) sh[0] = t;
    }
    __syncthreads();
    float mu = sh[0] * (1.f / 1024.f);
    __syncthreads();
    // reduce sum of squared deviations
    float ss = 0.f;
    #pragma unroll
    for (int j = 0; j < 4; ++j) { float d = v[j] - mu; ss += d * d; }
    #pragma unroll
    for (int off = 16; off > 0; off >>= 1) ss += __shfl_xor_sync(0xffffffffu, ss, off);
    if ((tid & 31) == 0) sh[tid >> 5] = ss;
    __syncthreads();
    if (tid < 32) {
        float t = (tid < 8) ? sh[tid] : 0.f;
        #pragma unroll
        for (int off = 4; off > 0; off >>= 1) t += __shfl_xor_sync(0xffffffffu, t, off);
        if (tid == 0) sh[0] = t;
    }
    __syncthreads();
    float var = sh[0] * (1.f / 1024.f);
    float rstd = rsqrtf(var + 1e-5f);
    #pragma unroll
    for (int j = 0; j < 4; ++j) {
        int c = tid + j * 256;
        x[base + c] = (v[j] - mu) * rstd * g[c] + bb[c];
    }
}

// ---------------------------------------------------------------------------
extern "C" void kernel_launch(void* const* d_in, const int* in_sizes, int n_in,
                              void* d_out, int out_size) {
    const int*   tokens = (const int*)  d_in[0];
    const float* emb    = (const float*)d_in[1];
    const float* qkv_w  = (const float*)d_in[2];
    const float* qkv_b  = (const float*)d_in[3];
    const float* out_w  = (const float*)d_in[4];
    const float* out_b  = (const float*)d_in[5];
    const float* fc1_w  = (const float*)d_in[6];
    const float* fc1_b  = (const float*)d_in[7];
    const float* fc2_w  = (const float*)d_in[8];
    const float* fc2_b  = (const float*)d_in[9];
    const float* ln1_g  = (const float*)d_in[10];
    const float* ln1_b  = (const float*)d_in[11];
    const float* ln2_g  = (const float*)d_in[12];
    const float* ln2_b  = (const float*)d_in[13];
    const float* w_out  = (const float*)d_in[14];
    const float* b_out  = (const float*)d_in[15];
    float* out = (float*)d_out;

    float *x, *tmp, *o;
    cudaGetSymbolAddress((void**)&x,   g_x);
    cudaGetSymbolAddress((void**)&tmp, g_tmp);
    cudaGetSymbolAddress((void**)&o,   g_o);

    embed_kernel<<<TOK_, 256>>>(tokens, emb, x);

    for (int l = 0; l < L_; ++l) {
        // qkv = x @ qkv_w[l] + qkv_b[l]        [4096 x 3072]
        gemm_kernel<<<dim3(3072 / 64, TOK_ / 64), 256>>>(
            x, qkv_w + (size_t)l * D_ * 3 * D_, qkv_b + (size_t)l * 3 * D_,
            tmp, TOK_, 3 * D_, D_, 0);
        // attention -> o  [4096 x 1024]
        attn_kernel<<<(B_ * H_ * S_) / 4, 128>>>(tmp, o);
        // out proj -> tmp [4096 x 1024]
        gemm_kernel<<<dim3(D_ / 64, TOK_ / 64), 256>>>(
            o, out_w + (size_t)l * D_ * D_, out_b + (size_t)l * D_,
            tmp, TOK_, D_, D_, 0);
        // x = LN(x + tmp)
        add_ln_kernel<<<TOK_, 256>>>(x, tmp, ln1_g + l * D_, ln1_b + l * D_);
        // h = relu(x @ fc1 + b) -> tmp [4096 x 4096]
        gemm_kernel<<<dim3(FF_ / 64, TOK_ / 64), 256>>>(
            x, fc1_w + (size_t)l * D_ * FF_, fc1_b + (size_t)l * FF_,
            tmp, TOK_, FF_, D_, 1);
        // o = h @ fc2 + b  [4096 x 1024]
        gemm_kernel<<<dim3(D_ / 64, TOK_ / 64), 256>>>(
            tmp, fc2_w + (size_t)l * FF_ * D_, fc2_b + (size_t)l * D_,
            o, TOK_, D_, FF_, 0);
        // x = LN(x + o)
        add_ln_kernel<<<TOK_, 256>>>(x, o, ln2_g + l * D_, ln2_b + l * D_);
    }

    // logits = x @ w_out + b_out   [4096 x 32000]
    gemm_kernel<<<dim3(V_ / 64, TOK_ / 64), 256>>>(
        x, w_out, b_out, out, TOK_, V_, D_, 0);
}

// round 2
// speedup vs baseline: 1.9738x; 1.9738x over previous
#include <cuda_runtime.h>
#include <cuda_bf16.h>
#include <math.h>

#define B_ 2
#define S_ 2048
#define D_ 1024
#define L_ 6
#define H_ 16
#define HD_ 64
#define FF_ 4096
#define V_ 32000
#define TOK_ (B_ * S_)          // 4096 token rows

// ---------------- scratch (static device globals; no allocation) ----------
__device__ float g_x[TOK_ * D_];        // 16 MB  activations
__device__ float g_tmp[TOK_ * FF_];     // 64 MB  qkv / ffn hidden / o-proj
__device__ float g_o[TOK_ * D_];        // 16 MB  attention / ffn output

// ---------------- embedding + sinusoidal positional encoding --------------
__global__ void embed_kernel(const int* __restrict__ tokens,
                             const float* __restrict__ emb,
                             float* __restrict__ x) {
    int row = blockIdx.x;              // 0 .. TOK_-1
    int s   = row & (S_ - 1);          // position within sequence
    int tok = tokens[row];
    const float* erow = emb + (size_t)tok * D_;
    float* xrow = x + (size_t)row * D_;
    const float kfac = -0.00899447301950812f;   // -ln(10000)/1024
    #pragma unroll
    for (int j = 0; j < 4; ++j) {
        int c = threadIdx.x + j * 256;
        float freq = expf(kfac * (float)(c & ~1));
        float arg  = (float)s * freq;
        float pe   = (c & 1) ? cosf(arg) : sinf(arg);
        xrow[c] = erow[c] + pe;
    }
}

// ---------------- tiled fp32 GEMM: C = A[MxK] @ W[KxN] + bias -------------
// BM=BN=128, BK=16, 256 threads, 8x8 per thread, double-buffered smem.
// Requires M,N % 128 == 0, K % 16 == 0.
__global__ void __launch_bounds__(256, 2)
gemm_kernel(const float* __restrict__ A,
            const float* __restrict__ W,
            const float* __restrict__ bias,
            float* __restrict__ C,
            int M, int N, int K, int relu) {
    __shared__ float As[2][16][128];
    __shared__ float Bs[2][16][128];

    int tid = threadIdx.x;
    int tx = tid & 15;          // 0..15 -> col group of 8
    int ty = tid >> 4;          // 0..15 -> row group of 8
    int bx = blockIdx.x, by = blockIdx.y;

    // A-tile load mapping (2 float4 per thread): slot = tid, tid+256
    int arow = tid >> 2;              // 0..63 (second slot +64)
    int acol = (tid & 3) << 2;        // 0,4,8,12
    // B-tile load mapping: slot = tid, tid+256
    int bkr = tid >> 5;               // 0..7 (second slot +8)
    int bnc = (tid & 31) << 2;        // 0..124

    const float* Ap0 = A + (size_t)(by * 128 + arow) * K + acol;
    const float* Ap1 = A + (size_t)(by * 128 + arow + 64) * K + acol;
    const float* Bp0 = W + (size_t)bkr * N + bx * 128 + bnc;
    const float* Bp1 = W + (size_t)(bkr + 8) * N + bx * 128 + bnc;

    float acc[8][8];
    #pragma unroll
    for (int i = 0; i < 8; ++i)
        #pragma unroll
        for (int j = 0; j < 8; ++j) acc[i][j] = 0.f;

    // prologue: load tile k0=0 into buffer 0
    {
        float4 a0 = *(const float4*)(Ap0);
        float4 a1 = *(const float4*)(Ap1);
        As[0][acol + 0][arow] = a0.x;  As[0][acol + 1][arow] = a0.y;
        As[0][acol + 2][arow] = a0.z;  As[0][acol + 3][arow] = a0.w;
        As[0][acol + 0][arow + 64] = a1.x;  As[0][acol + 1][arow + 64] = a1.y;
        As[0][acol + 2][arow + 64] = a1.z;  As[0][acol + 3][arow + 64] = a1.w;
        *(float4*)&Bs[0][bkr][bnc]     = *(const float4*)(Bp0);
        *(float4*)&Bs[0][bkr + 8][bnc] = *(const float4*)(Bp1);
    }
    __syncthreads();

    int buf = 0;
    for (int k0 = 0; k0 < K; k0 += 16) {
        int nxt = k0 + 16;
        float4 a0, a1, b0, b1;
        if (nxt < K) {
            a0 = *(const float4*)(Ap0 + nxt);
            a1 = *(const float4*)(Ap1 + nxt);
            b0 = *(const float4*)(Bp0 + (size_t)nxt * N);
            b1 = *(const float4*)(Bp1 + (size_t)nxt * N);
        }
        #pragma unroll
        for (int k = 0; k < 16; ++k) {
            float ar[8], br[8];
            float4 t;
            t = *(const float4*)&As[buf][k][ty << 3];
            ar[0] = t.x; ar[1] = t.y; ar[2] = t.z; ar[3] = t.w;
            t = *(const float4*)&As[buf][k][(ty << 3) + 4];
            ar[4] = t.x; ar[5] = t.y; ar[6] = t.z; ar[7] = t.w;
            t = *(const float4*)&Bs[buf][k][tx << 3];
            br[0] = t.x; br[1] = t.y; br[2] = t.z; br[3] = t.w;
            t = *(const float4*)&Bs[buf][k][(tx << 3) + 4];
            br[4] = t.x; br[5] = t.y; br[6] = t.z; br[7] = t.w;
            #pragma unroll
            for (int i = 0; i < 8; ++i)
                #pragma unroll
                for (int j = 0; j < 8; ++j)
                    acc[i][j] = fmaf(ar[i], br[j], acc[i][j]);
        }
        if (nxt < K) {
            int nb = buf ^ 1;
            As[nb][acol + 0][arow] = a0.x;  As[nb][acol + 1][arow] = a0.y;
            As[nb][acol + 2][arow] = a0.z;  As[nb][acol + 3][arow] = a0.w;
            As[nb][acol + 0][arow + 64] = a1.x;  As[nb][acol + 1][arow + 64] = a1.y;
            As[nb][acol + 2][arow + 64] = a1.z;  As[nb][acol + 3][arow + 64] = a1.w;
            *(float4*)&Bs[nb][bkr][bnc]     = b0;
            *(float4*)&Bs[nb][bkr + 8][bnc] = b1;
        }
        __syncthreads();
        buf ^= 1;
    }

    int r0 = by * 128 + (ty << 3);
    int c0 = bx * 128 + (tx << 3);
    float bv[8];
    #pragma unroll
    for (int j = 0; j < 8; ++j) bv[j] = bias[c0 + j];
    #pragma unroll
    for (int i = 0; i < 8; ++i) {
        float* crow = C + (size_t)(r0 + i) * N + c0;
        float4 o0, o1;
        float v0 = acc[i][0] + bv[0], v1 = acc[i][1] + bv[1];
        float v2 = acc[i][2] + bv[2], v3 = acc[i][3] + bv[3];
        float v4 = acc[i][4] + bv[4], v5 = acc[i][5] + bv[5];
        float v6 = acc[i][6] + bv[6], v7 = acc[i][7] + bv[7];
        if (relu) {
            v0 = fmaxf(v0, 0.f); v1 = fmaxf(v1, 0.f); v2 = fmaxf(v2, 0.f); v3 = fmaxf(v3, 0.f);
            v4 = fmaxf(v4, 0.f); v5 = fmaxf(v5, 0.f); v6 = fmaxf(v6, 0.f); v7 = fmaxf(v7, 0.f);
        }
        o0.x = v0; o0.y = v1; o0.z = v2; o0.w = v3;
        o1.x = v4; o1.y = v5; o1.z = v6; o1.w = v7;
        *(float4*)(crow)     = o0;
        *(float4*)(crow + 4) = o1;
    }
}

// ---------------- tiled causal flash attention -----------------------------
// Block: 256 threads, 64 queries of one (b,h). Key tiles of 32.
// qkv layout: [TOK_, 3072], q@h*64, k@1024+h*64, v@2048+h*64
#define KT_ 32
__global__ void __launch_bounds__(256)
attn_kernel(const float* __restrict__ qkv, float* __restrict__ o) {
    int qb = gridDim.x - 1 - blockIdx.x;   // heavy blocks first
    int bh = blockIdx.y;
    int h = bh & (H_ - 1), b = bh >> 4;
    int tid = threadIdx.x;
    int tx = tid & 15;          // d/key group
    int ty = tid >> 4;          // query group

    __shared__ float Qt[64][68];       // [d][q]
    __shared__ float Kt[64][34];       // [d][k]
    __shared__ float Vs[KT_][64];      // [k][d]
    __shared__ float Ps[KT_][68];      // [k][q]  scores -> probs
    __shared__ float m_s[64], d_s[64], corr_s[64];

    const float* qbase = qkv + (size_t)(b * S_ + qb * 64) * 3072 + h * 64;
    const float* kvbase = qkv + (size_t)(b * S_) * 3072 + h * 64;

    // load Q tile (transposed into Qt)
    #pragma unroll
    for (int t = 0; t < 4; ++t) {
        int slot = tid + t * 256;
        int row = slot >> 4;            // 0..63
        int cq  = (slot & 15) << 2;     // 0..60
        float4 v = *(const float4*)(qbase + (size_t)row * 3072 + cq);
        Qt[cq + 0][row] = v.x;
        Qt[cq + 1][row] = v.y;
        Qt[cq + 2][row] = v.z;
        Qt[cq + 3][row] = v.w;
    }
    if (tid < 64) { m_s[tid] = -1e30f; d_s[tid] = 0.f; }

    float O[4][4];
    #pragma unroll
    for (int i = 0; i < 4; ++i)
        #pragma unroll
        for (int j = 0; j < 4; ++j) O[i][j] = 0.f;

    __syncthreads();

    int ntiles = 2 * qb + 2;
    for (int kt = 0; kt < ntiles; ++kt) {
        int j0 = kt * KT_;
        // load K (transposed) and V tiles
        #pragma unroll
        for (int t = 0; t < 2; ++t) {
            int slot = tid + t * 256;
            int j  = slot >> 4;             // 0..31
            int cq = (slot & 15) << 2;
            const float* src = kvbase + (size_t)(j0 + j) * 3072;
            float4 kv = *(const float4*)(src + 1024 + cq);
            Kt[cq + 0][j] = kv.x;
            Kt[cq + 1][j] = kv.y;
            Kt[cq + 2][j] = kv.z;
            Kt[cq + 3][j] = kv.w;
            *(float4*)&Vs[j][cq] = *(const float4*)(src + 2048 + cq);
        }
        __syncthreads();

        // scores: 4 queries x 2 keys per thread
        float sc[4][2];
        #pragma unroll
        for (int i = 0; i < 4; ++i) { sc[i][0] = 0.f; sc[i][1] = 0.f; }
        #pragma unroll 4
        for (int d = 0; d < 64; ++d) {
            float4 q4 = *(const float4*)&Qt[d][ty << 2];
            float2 k2 = *(const float2*)&Kt[d][tx << 1];
            sc[0][0] = fmaf(q4.x, k2.x, sc[0][0]);
            sc[1][0] = fmaf(q4.y, k2.x, sc[1][0]);
            sc[2][0] = fmaf(q4.z, k2.x, sc[2][0]);
            sc[3][0] = fmaf(q4.w, k2.x, sc[3][0]);
            sc[0][1] = fmaf(q4.x, k2.y, sc[0][1]);
            sc[1][1] = fmaf(q4.y, k2.y, sc[1][1]);
            sc[2][1] = fmaf(q4.z, k2.y, sc[2][1]);
            sc[3][1] = fmaf(q4.w, k2.y, sc[3][1]);
        }
        int qg = qb * 64 + (ty << 2);
        int kg = j0 + (tx << 1);
        #pragma unroll
        for (int i = 0; i < 4; ++i)
            #pragma unroll
            for (int jj = 0; jj < 2; ++jj) {
                float s = sc[i][jj] * 0.125f;
                if (kg + jj > qg + i) s = -1e30f;
                Ps[(tx << 1) + jj][(ty << 2) + i] = s;
            }
        __syncthreads();

        // softmax update: 4 threads per query (each handles 8 keys)
        {
            int q = tid >> 2, part = tid & 3;
            float mold = m_s[q];
            float mx = mold;
            float vals[8];
            #pragma unroll
            for (int jj = 0; jj < 8; ++jj) {
                vals[jj] = Ps[(part << 3) + jj][q];
                mx = fmaxf(mx, vals[jj]);
            }
            mx = fmaxf(mx, __shfl_xor_sync(0xffffffffu, mx, 1));
            mx = fmaxf(mx, __shfl_xor_sync(0xffffffffu, mx, 2));
            float sum = 0.f;
            #pragma unroll
            for (int jj = 0; jj < 8; ++jj) {
                float p = __expf(vals[jj] - mx);
                Ps[(part << 3) + jj][q] = p;
                sum += p;
            }
            sum += __shfl_xor_sync(0xffffffffu, sum, 1);
            sum += __shfl_xor_sync(0xffffffffu, sum, 2);
            if (part == 0) {
                float corr = __expf(mold - mx);
                d_s[q] = d_s[q] * corr + sum;
                m_s[q] = mx;
                corr_s[q] = corr;
            }
        }
        __syncthreads();

        // O update: O[q][d] = O*corr + sum_j P[j][q] * V[j][d]
        {
            float c0 = corr_s[(ty << 2) + 0];
            float c1 = corr_s[(ty << 2) + 1];
            float c2 = corr_s[(ty << 2) + 2];
            float c3 = corr_s[(ty << 2) + 3];
            #pragma unroll
            for (int j4 = 0; j4 < 4; ++j4) {
                O[0][j4] *= c0; O[1][j4] *= c1; O[2][j4] *= c2; O[3][j4] *= c3;
            }
            #pragma unroll 4
            for (int j = 0; j < KT_; ++j) {
                float4 p4 = *(const float4*)&Ps[j][ty << 2];
                float4 v4 = *(const float4*)&Vs[j][tx << 2];
                O[0][0] = fmaf(p4.x, v4.x, O[0][0]);
                O[0][1] = fmaf(p4.x, v4.y, O[0][1]);
                O[0][2] = fmaf(p4.x, v4.z, O[0][2]);
                O[0][3] = fmaf(p4.x, v4.w, O[0][3]);
                O[1][0] = fmaf(p4.y, v4.x, O[1][0]);
                O[1][1] = fmaf(p4.y, v4.y, O[1][1]);
                O[1][2] = fmaf(p4.y, v4.z, O[1][2]);
                O[1][3] = fmaf(p4.y, v4.w, O[1][3]);
                O[2][0] = fmaf(p4.z, v4.x, O[2][0]);
                O[2][1] = fmaf(p4.z, v4.y, O[2][1]);
                O[2][2] = fmaf(p4.z, v4.z, O[2][2]);
                O[2][3] = fmaf(p4.z, v4.w, O[2][3]);
                O[3][0] = fmaf(p4.w, v4.x, O[3][0]);
                O[3][1] = fmaf(p4.w, v4.y, O[3][1]);
                O[3][2] = fmaf(p4.w, v4.z, O[3][2]);
                O[3][3] = fmaf(p4.w, v4.w, O[3][3]);
            }
        }
        __syncthreads();
    }

    // normalize and write
    #pragma unroll
    for (int i = 0; i < 4; ++i) {
        int q = (ty << 2) + i;
        float inv = 1.f / d_s[q];
        float4 v;
        v.x = O[i][0] * inv; v.y = O[i][1] * inv;
        v.z = O[i][2] * inv; v.w = O[i][3] * inv;
        float* orow = o + (size_t)(b * S_ + qb * 64 + q) * D_ + h * 64 + (tx << 2);
        *(float4*)orow = v;
    }
}

// ---------------- fused residual add + LayerNorm (in place on x) ----------
__global__ void add_ln_kernel(float* __restrict__ x,
                              const float* __restrict__ r,
                              const float* __restrict__ g,
                              const float* __restrict__ bb) {
    int row = blockIdx.x;
    int tid = threadIdx.x;
    size_t base = (size_t)row * D_;
    float v[4];
    float s = 0.f;
    #pragma unroll
    for (int j = 0; j < 4; ++j) {
        int c = tid + j * 256;
        v[j] = x[base + c] + r[base + c];
        s += v[j];
    }
    __shared__ float sh[8];
    #pragma unroll
    for (int off = 16; off > 0; off >>= 1) s += __shfl_xor_sync(0xffffffffu, s, off);
    if ((tid & 31) == 0) sh[tid >> 5] = s;
    __syncthreads();
    if (tid < 32) {
        float t = (tid < 8) ? sh[tid] : 0.f;
        #pragma unroll
        for (int off = 4; off > 0; off >>= 1) t += __shfl_xor_sync(0xffffffffu, t, off);
        if (tid == 0) sh[0] = t;
    }
    __syncthreads();
    float mu = sh[0] * (1.f / 1024.f);
    __syncthreads();
    float ss = 0.f;
    #pragma unroll
    for (int j = 0; j < 4; ++j) { float d = v[j] - mu; ss += d * d; }
    #pragma unroll
    for (int off = 16; off > 0; off >>= 1) ss += __shfl_xor_sync(0xffffffffu, ss, off);
    if ((tid & 31) == 0) sh[tid >> 5] = ss;
    __syncthreads();
    if (tid < 32) {
        float t = (tid < 8) ? sh[tid] : 0.f;
        #pragma unroll
        for (int off = 4; off > 0; off >>= 1) t += __shfl_xor_sync(0xffffffffu, t, off);
        if (tid == 0) sh[0] = t;
    }
    __syncthreads();
    float var = sh[0] * (1.f / 1024.f);
    float rstd = rsqrtf(var + 1e-5f);
    #pragma unroll
    for (int j = 0; j < 4; ++j) {
        int c = tid + j * 256;
        x[base + c] = (v[j] - mu) * rstd * g[c] + bb[c];
    }
}

// ---------------------------------------------------------------------------
extern "C" void kernel_launch(void* const* d_in, const int* in_sizes, int n_in,
                              void* d_out, int out_size) {
    const int*   tokens = (const int*)  d_in[0];
    const float* emb    = (const float*)d_in[1];
    const float* qkv_w  = (const float*)d_in[2];
    const float* qkv_b  = (const float*)d_in[3];
    const float* out_w  = (const float*)d_in[4];
    const float* out_b  = (const float*)d_in[5];
    const float* fc1_w  = (const float*)d_in[6];
    const float* fc1_b  = (const float*)d_in[7];
    const float* fc2_w  = (const float*)d_in[8];
    const float* fc2_b  = (const float*)d_in[9];
    const float* ln1_g  = (const float*)d_in[10];
    const float* ln1_b  = (const float*)d_in[11];
    const float* ln2_g  = (const float*)d_in[12];
    const float* ln2_b  = (const float*)d_in[13];
    const float* w_out  = (const float*)d_in[14];
    const float* b_out  = (const float*)d_in[15];
    float* out = (float*)d_out;

    float *x, *tmp, *o;
    cudaGetSymbolAddress((void**)&x,   g_x);
    cudaGetSymbolAddress((void**)&tmp, g_tmp);
    cudaGetSymbolAddress((void**)&o,   g_o);

    embed_kernel<<<TOK_, 256>>>(tokens, emb, x);

    for (int l = 0; l < L_; ++l) {
        // qkv = x @ qkv_w[l] + qkv_b[l]        [4096 x 3072]
        gemm_kernel<<<dim3(3072 / 128, TOK_ / 128), 256>>>(
            x, qkv_w + (size_t)l * D_ * 3 * D_, qkv_b + (size_t)l * 3 * D_,
            tmp, TOK_, 3 * D_, D_, 0);
        // attention -> o  [4096 x 1024]
        attn_kernel<<<dim3(S_ / 64, B_ * H_), 256>>>(tmp, o);
        // out proj -> tmp [4096 x 1024]
        gemm_kernel<<<dim3(D_ / 128, TOK_ / 128), 256>>>(
            o, out_w + (size_t)l * D_ * D_, out_b + (size_t)l * D_,
            tmp, TOK_, D_, D_, 0);
        // x = LN(x + tmp)
        add_ln_kernel<<<TOK_, 256>>>(x, tmp, ln1_g + l * D_, ln1_b + l * D_);
        // h = relu(x @ fc1 + b) -> tmp [4096 x 4096]
        gemm_kernel<<<dim3(FF_ / 128, TOK_ / 128), 256>>>(
            x, fc1_w + (size_t)l * D_ * FF_, fc1_b + (size_t)l * FF_,
            tmp, TOK_, FF_, D_, 1);
        // o = h @ fc2 + b  [4096 x 1024]
        gemm_kernel<<<dim3(D_ / 128, TOK_ / 128), 256>>>(
            tmp, fc2_w + (size_t)l * FF_ * D_, fc2_b + (size_t)l * D_,
            o, TOK_, D_, FF_, 0);
        // x = LN(x + o)
        add_ln_kernel<<<TOK_, 256>>>(x, o, ln2_g + l * D_, ln2_b + l * D_);
    }

    // logits = x @ w_out + b_out   [4096 x 32000]
    gemm_kernel<<<dim3(V_ / 128, TOK_ / 128), 256>>>(
        x, w_out, b_out, out, TOK_, V_, D_, 0);
}

// round 3
// speedup vs baseline: 2.0188x; 1.0228x over previous
#include <cuda_runtime.h>
#include <cuda_bf16.h>
#include <math.h>
#include <stdint.h>

#define B_ 2
#define S_ 2048
#define D_ 1024
#define L_ 6
#define H_ 16
#define HD_ 64
#define FF_ 4096
#define V_ 32000
#define TOK_ (B_ * S_)          // 4096 token rows

// ---------------- scratch (static device globals; no allocation) ----------
__device__ float g_x[TOK_ * D_];        // activations
__device__ float g_tmp[TOK_ * FF_];     // qkv / ffn hidden / o-proj
__device__ float g_o[TOK_ * D_];        // attention / ffn output

// ---------------- embedding + sinusoidal positional encoding --------------
__global__ void embed_kernel(const int* __restrict__ tokens,
                             const float* __restrict__ emb,
                             float* __restrict__ x) {
    int row = blockIdx.x;
    int s   = row & (S_ - 1);
    int tok = tokens[row];
    const float* erow = emb + (size_t)tok * D_;
    float* xrow = x + (size_t)row * D_;
    const float kfac = -0.00899447301950812f;   // -ln(10000)/1024
    #pragma unroll
    for (int j = 0; j < 4; ++j) {
        int c = threadIdx.x + j * 256;
        float freq = expf(kfac * (float)(c & ~1));
        float arg  = (float)s * freq;
        float pe   = (c & 1) ? cosf(arg) : sinf(arg);
        xrow[c] = erow[c] + pe;
    }
}

// ===================== tensor-core GEMM (bf16 hi/lo split, fp32 acc) =======
// C = A[MxK] @ W[KxN] + bias, M,N %128==0, K %32==0.
// 512 threads = 16 warps in 4x4 grid; warp tile 32x32; block tile 128x128x32.
// smem: As_hi/lo [2][128][40], Bs_hi/lo [2][128][40] (B stored [n][k]).

__device__ __forceinline__ uint32_t sptr(const void* p) {
    return (uint32_t)__cvta_generic_to_shared(p);
}
__device__ __forceinline__ void cv2(__nv_bfloat16* h, __nv_bfloat16* l, float x) {
    __nv_bfloat16 hb = __float2bfloat16(x);
    *h = hb;
    *l = __float2bfloat16(x - __bfloat162float(hb));
}

#define LDSM4(R0, R1, R2, R3, ADDR) \
    asm volatile("ldmatrix.sync.aligned.m8n8.x4.shared.b16 {%0,%1,%2,%3}, [%4];" \
                 : "=r"(R0), "=r"(R1), "=r"(R2), "=r"(R3) : "r"(ADDR))

#define MMA16816(Cv, Ar, Bb0, Bb1) \
    asm volatile("mma.sync.aligned.m16n8k16.row.col.f32.bf16.bf16.f32 " \
                 "{%0,%1,%2,%3},{%4,%5,%6,%7},{%8,%9},{%0,%1,%2,%3};" \
                 : "+f"(Cv[0]), "+f"(Cv[1]), "+f"(Cv[2]), "+f"(Cv[3]) \
                 : "r"(Ar[0]), "r"(Ar[1]), "r"(Ar[2]), "r"(Ar[3]), \
                   "r"(Bb0), "r"(Bb1))

#define TSTRIDE 40          // padded k-stride in elements
#define BUFELEM 5120        // 128*40 per buffer

__global__ void __launch_bounds__(512, 1)
mma_gemm(const float* __restrict__ A,
         const float* __restrict__ W,
         const float* __restrict__ bias,
         float* __restrict__ C,
         int M, int N, int K, int relu) {
    extern __shared__ __nv_bfloat16 sm[];
    __nv_bfloat16* AH = sm;                 // [2][128][40]
    __nv_bfloat16* AL = sm + 2 * BUFELEM;
    __nv_bfloat16* BH = sm + 4 * BUFELEM;   // [n][k]
    __nv_bfloat16* BL = sm + 6 * BUFELEM;

    const int tid = threadIdx.x;
    const int wid = tid >> 5, lane = tid & 31;
    const int wm = (wid >> 2) << 5;     // warp m offset 0..96
    const int wn = (wid & 3) << 5;      // warp n offset 0..96
    const int bx = blockIdx.x, by = blockIdx.y;

    // global load mappings (2 float4 each for A and W per iter)
    const int ar0 = tid >> 3;               // A row 0..63 (+64 second)
    const int ac0 = (tid & 7) << 2;         // A k col 0..28
    const int wk  = tid >> 5;               // W k row 0..15 (+16 second)
    const int wc  = (tid & 31) << 2;        // W n col 0..124

    const float* Ap0 = A + (size_t)(by * 128 + ar0) * K + ac0;
    const float* Ap1 = A + (size_t)(by * 128 + ar0 + 64) * K + ac0;
    const float* Wp0 = W + (size_t)wk * N + bx * 128 + wc;
    const float* Wp1 = W + (size_t)(wk + 16) * N + bx * 128 + wc;

    float acc[2][4][4];
    #pragma unroll
    for (int i = 0; i < 2; ++i)
        #pragma unroll
        for (int j = 0; j < 4; ++j)
            #pragma unroll
            for (int t = 0; t < 4; ++t) acc[i][j][t] = 0.f;

    float4 sa0, sa1, sw0, sw1;

    // ---- prologue: stage k0=0, store to buf 0
    sa0 = *(const float4*)(Ap0);
    sa1 = *(const float4*)(Ap1);
    sw0 = *(const float4*)(Wp0);
    sw1 = *(const float4*)(Wp1);
    {
        int ab0 = ar0 * TSTRIDE + ac0;
        int ab1 = (ar0 + 64) * TSTRIDE + ac0;
        cv2(AH + ab0 + 0, AL + ab0 + 0, sa0.x);
        cv2(AH + ab0 + 1, AL + ab0 + 1, sa0.y);
        cv2(AH + ab0 + 2, AL + ab0 + 2, sa0.z);
        cv2(AH + ab0 + 3, AL + ab0 + 3, sa0.w);
        cv2(AH + ab1 + 0, AL + ab1 + 0, sa1.x);
        cv2(AH + ab1 + 1, AL + ab1 + 1, sa1.y);
        cv2(AH + ab1 + 2, AL + ab1 + 2, sa1.z);
        cv2(AH + ab1 + 3, AL + ab1 + 3, sa1.w);
        float v0[4] = {sw0.x, sw0.y, sw0.z, sw0.w};
        float v1[4] = {sw1.x, sw1.y, sw1.z, sw1.w};
        #pragma unroll
        for (int j = 0; j < 4; ++j) {
            int nb = (wc + j) * TSTRIDE;
            cv2(BH + nb + wk,      BL + nb + wk,      v0[j]);
            cv2(BH + nb + wk + 16, BL + nb + wk + 16, v1[j]);
        }
    }
    __syncthreads();

    int buf = 0;
    for (int k0 = 0; k0 < K; k0 += 32) {
        int nk = k0 + 32;
        bool has = nk < K;
        if (has) {
            sa0 = *(const float4*)(Ap0 + nk);
            sa1 = *(const float4*)(Ap1 + nk);
            sw0 = *(const float4*)(Wp0 + (size_t)nk * N);
            sw1 = *(const float4*)(Wp1 + (size_t)nk * N);
        }

        // ---- MMA over the 2 k16 chunks of this buffer
        const __nv_bfloat16* ah = AH + buf * BUFELEM;
        const __nv_bfloat16* al = AL + buf * BUFELEM;
        const __nv_bfloat16* bh = BH + buf * BUFELEM;
        const __nv_bfloat16* bl = BL + buf * BUFELEM;
        #pragma unroll
        for (int kc = 0; kc < 2; ++kc) {
            uint32_t a_hi[2][4], a_lo[2][4], b_hi[4][2], b_lo[4][2];
            // A fragments (2 m-tiles)
            #pragma unroll
            for (int mt = 0; mt < 2; ++mt) {
                int row = wm + mt * 16 + (lane & 15);
                int col = kc * 16 + ((lane >> 4) << 3);
                uint32_t ad = sptr(ah + row * TSTRIDE + col);
                LDSM4(a_hi[mt][0], a_hi[mt][1], a_hi[mt][2], a_hi[mt][3], ad);
                ad = sptr(al + row * TSTRIDE + col);
                LDSM4(a_lo[mt][0], a_lo[mt][1], a_lo[mt][2], a_lo[mt][3], ad);
            }
            // B fragments (4 n-tiles via 2 x4 loads per hi/lo)
            #pragma unroll
            for (int p = 0; p < 2; ++p) {
                int g = lane >> 3;
                int nrow = wn + p * 16 + ((g >> 1) << 3) + (lane & 7);
                int kcol = kc * 16 + ((g & 1) << 3);
                uint32_t bd = sptr(bh + nrow * TSTRIDE + kcol);
                LDSM4(b_hi[2*p][0], b_hi[2*p][1], b_hi[2*p+1][0], b_hi[2*p+1][1], bd);
                bd = sptr(bl + nrow * TSTRIDE + kcol);
                LDSM4(b_lo[2*p][0], b_lo[2*p][1], b_lo[2*p+1][0], b_lo[2*p+1][1], bd);
            }
            #pragma unroll
            for (int mt = 0; mt < 2; ++mt)
                #pragma unroll
                for (int nt = 0; nt < 4; ++nt) {
                    MMA16816(acc[mt][nt], a_hi[mt], b_hi[nt][0], b_hi[nt][1]);
                    MMA16816(acc[mt][nt], a_hi[mt], b_lo[nt][0], b_lo[nt][1]);
                    MMA16816(acc[mt][nt], a_lo[mt], b_hi[nt][0], b_hi[nt][1]);
                }
        }

        if (has) {
            int nb2 = (buf ^ 1) * BUFELEM;
            int ab0 = nb2 + ar0 * TSTRIDE + ac0;
            int ab1 = nb2 + (ar0 + 64) * TSTRIDE + ac0;
            cv2(AH + ab0 + 0, AL + ab0 + 0, sa0.x);
            cv2(AH + ab0 + 1, AL + ab0 + 1, sa0.y);
            cv2(AH + ab0 + 2, AL + ab0 + 2, sa0.z);
            cv2(AH + ab0 + 3, AL + ab0 + 3, sa0.w);
            cv2(AH + ab1 + 0, AL + ab1 + 0, sa1.x);
            cv2(AH + ab1 + 1, AL + ab1 + 1, sa1.y);
            cv2(AH + ab1 + 2, AL + ab1 + 2, sa1.z);
            cv2(AH + ab1 + 3, AL + ab1 + 3, sa1.w);
            float v0[4] = {sw0.x, sw0.y, sw0.z, sw0.w};
            float v1[4] = {sw1.x, sw1.y, sw1.z, sw1.w};
            #pragma unroll
            for (int j = 0; j < 4; ++j) {
                int nb = nb2 + (wc + j) * TSTRIDE;
                cv2(BH + nb + wk,      BL + nb + wk,      v0[j]);
                cv2(BH + nb + wk + 16, BL + nb + wk + 16, v1[j]);
            }
        }
        __syncthreads();
        buf ^= 1;
    }

    // ---- epilogue: bias (+relu), write fp32
    #pragma unroll
    for (int mt = 0; mt < 2; ++mt) {
        int row = by * 128 + wm + mt * 16 + (lane >> 2);
        #pragma unroll
        for (int nt = 0; nt < 4; ++nt) {
            int col = bx * 128 + wn + nt * 8 + ((lane & 3) << 1);
            float2 bv = *(const float2*)(bias + col);
            float v0 = acc[mt][nt][0] + bv.x;
            float v1 = acc[mt][nt][1] + bv.y;
            float v2 = acc[mt][nt][2] + bv.x;
            float v3 = acc[mt][nt][3] + bv.y;
            if (relu) {
                v0 = fmaxf(v0, 0.f); v1 = fmaxf(v1, 0.f);
                v2 = fmaxf(v2, 0.f); v3 = fmaxf(v3, 0.f);
            }
            float2 o0 = {v0, v1}, o1 = {v2, v3};
            *(float2*)(C + (size_t)row * N + col)       = o0;
            *(float2*)(C + (size_t)(row + 8) * N + col) = o1;
        }
    }
}

// ---------------- tiled causal flash attention -----------------------------
#define KT_ 32
__global__ void __launch_bounds__(256)
attn_kernel(const float* __restrict__ qkv, float* __restrict__ o) {
    int qb = gridDim.x - 1 - blockIdx.x;   // heavy blocks first
    int bh = blockIdx.y;
    int h = bh & (H_ - 1), b = bh >> 4;
    int tid = threadIdx.x;
    int tx = tid & 15;
    int ty = tid >> 4;

    __shared__ float Qt[64][68];
    __shared__ float Kt[64][34];
    __shared__ float Vs[KT_][64];
    __shared__ float Ps[KT_][68];
    __shared__ float m_s[64], d_s[64], corr_s[64];

    const float* qbase = qkv + (size_t)(b * S_ + qb * 64) * 3072 + h * 64;
    const float* kvbase = qkv + (size_t)(b * S_) * 3072 + h * 64;

    #pragma unroll
    for (int t = 0; t < 4; ++t) {
        int slot = tid + t * 256;
        int row = slot >> 4;
        int cq  = (slot & 15) << 2;
        float4 v = *(const float4*)(qbase + (size_t)row * 3072 + cq);
        Qt[cq + 0][row] = v.x;
        Qt[cq + 1][row] = v.y;
        Qt[cq + 2][row] = v.z;
        Qt[cq + 3][row] = v.w;
    }
    if (tid < 64) { m_s[tid] = -1e30f; d_s[tid] = 0.f; }

    float O[4][4];
    #pragma unroll
    for (int i = 0; i < 4; ++i)
        #pragma unroll
        for (int j = 0; j < 4; ++j) O[i][j] = 0.f;

    __syncthreads();

    int ntiles = 2 * qb + 2;
    for (int kt = 0; kt < ntiles; ++kt) {
        int j0 = kt * KT_;
        #pragma unroll
        for (int t = 0; t < 2; ++t) {
            int slot = tid + t * 256;
            int j  = slot >> 4;
            int cq = (slot & 15) << 2;
            const float* src = kvbase + (size_t)(j0 + j) * 3072;
            float4 kv = *(const float4*)(src + 1024 + cq);
            Kt[cq + 0][j] = kv.x;
            Kt[cq + 1][j] = kv.y;
            Kt[cq + 2][j] = kv.z;
            Kt[cq + 3][j] = kv.w;
            *(float4*)&Vs[j][cq] = *(const float4*)(src + 2048 + cq);
        }
        __syncthreads();

        float sc[4][2];
        #pragma unroll
        for (int i = 0; i < 4; ++i) { sc[i][0] = 0.f; sc[i][1] = 0.f; }
        #pragma unroll 4
        for (int d = 0; d < 64; ++d) {
            float4 q4 = *(const float4*)&Qt[d][ty << 2];
            float2 k2 = *(const float2*)&Kt[d][tx << 1];
            sc[0][0] = fmaf(q4.x, k2.x, sc[0][0]);
            sc[1][0] = fmaf(q4.y, k2.x, sc[1][0]);
            sc[2][0] = fmaf(q4.z, k2.x, sc[2][0]);
            sc[3][0] = fmaf(q4.w, k2.x, sc[3][0]);
            sc[0][1] = fmaf(q4.x, k2.y, sc[0][1]);
            sc[1][1] = fmaf(q4.y, k2.y, sc[1][1]);
            sc[2][1] = fmaf(q4.z, k2.y, sc[2][1]);
            sc[3][1] = fmaf(q4.w, k2.y, sc[3][1]);
        }
        int qg = qb * 64 + (ty << 2);
        int kg = j0 + (tx << 1);
        #pragma unroll
        for (int i = 0; i < 4; ++i)
            #pragma unroll
            for (int jj = 0; jj < 2; ++jj) {
                float s = sc[i][jj] * 0.125f;
                if (kg + jj > qg + i) s = -1e30f;
                Ps[(tx << 1) + jj][(ty << 2) + i] = s;
            }
        __syncthreads();

        {
            int q = tid >> 2, part = tid & 3;
            float mold = m_s[q];
            float mx = mold;
            float vals[8];
            #pragma unroll
            for (int jj = 0; jj < 8; ++jj) {
                vals[jj] = Ps[(part << 3) + jj][q];
                mx = fmaxf(mx, vals[jj]);
            }
            mx = fmaxf(mx, __shfl_xor_sync(0xffffffffu, mx, 1));
            mx = fmaxf(mx, __shfl_xor_sync(0xffffffffu, mx, 2));
            float sum = 0.f;
            #pragma unroll
            for (int jj = 0; jj < 8; ++jj) {
                float p = __expf(vals[jj] - mx);
                Ps[(part << 3) + jj][q] = p;
                sum += p;
            }
            sum += __shfl_xor_sync(0xffffffffu, sum, 1);
            sum += __shfl_xor_sync(0xffffffffu, sum, 2);
            if (part == 0) {
                float corr = __expf(mold - mx);
                d_s[q] = d_s[q] * corr + sum;
                m_s[q] = mx;
                corr_s[q] = corr;
            }
        }
        __syncthreads();

        {
            float c0 = corr_s[(ty << 2) + 0];
            float c1 = corr_s[(ty << 2) + 1];
            float c2 = corr_s[(ty << 2) + 2];
            float c3 = corr_s[(ty << 2) + 3];
            #pragma unroll
            for (int j4 = 0; j4 < 4; ++j4) {
                O[0][j4] *= c0; O[1][j4] *= c1; O[2][j4] *= c2; O[3][j4] *= c3;
            }
            #pragma unroll 4
            for (int j = 0; j < KT_; ++j) {
                float4 p4 = *(const float4*)&Ps[j][ty << 2];
                float4 v4 = *(const float4*)&Vs[j][tx << 2];
                O[0][0] = fmaf(p4.x, v4.x, O[0][0]);
                O[0][1] = fmaf(p4.x, v4.y, O[0][1]);
                O[0][2] = fmaf(p4.x, v4.z, O[0][2]);
                O[0][3] = fmaf(p4.x, v4.w, O[0][3]);
                O[1][0] = fmaf(p4.y, v4.x, O[1][0]);
                O[1][1] = fmaf(p4.y, v4.y, O[1][1]);
                O[1][2] = fmaf(p4.y, v4.z, O[1][2]);
                O[1][3] = fmaf(p4.y, v4.w, O[1][3]);
                O[2][0] = fmaf(p4.z, v4.x, O[2][0]);
                O[2][1] = fmaf(p4.z, v4.y, O[2][1]);
                O[2][2] = fmaf(p4.z, v4.z, O[2][2]);
                O[2][3] = fmaf(p4.z, v4.w, O[2][3]);
                O[3][0] = fmaf(p4.w, v4.x, O[3][0]);
                O[3][1] = fmaf(p4.w, v4.y, O[3][1]);
                O[3][2] = fmaf(p4.w, v4.z, O[3][2]);
                O[3][3] = fmaf(p4.w, v4.w, O[3][3]);
            }
        }
        __syncthreads();
    }

    #pragma unroll
    for (int i = 0; i < 4; ++i) {
        int q = (ty << 2) + i;
        float inv = 1.f / d_s[q];
        float4 v;
        v.x = O[i][0] * inv; v.y = O[i][1] * inv;
        v.z = O[i][2] * inv; v.w = O[i][3] * inv;
        float* orow = o + (size_t)(b * S_ + qb * 64 + q) * D_ + h * 64 + (tx << 2);
        *(float4*)orow = v;
    }
}

// ---------------- fused residual add + LayerNorm (in place on x) ----------
__global__ void add_ln_kernel(float* __restrict__ x,
                              const float* __restrict__ r,
                              const float* __restrict__ g,
                              const float* __restrict__ bb) {
    int row = blockIdx.x;
    int tid = threadIdx.x;
    size_t base = (size_t)row * D_;
    float v[4];
    float s = 0.f;
    #pragma unroll
    for (int j = 0; j < 4; ++j) {
        int c = tid + j * 256;
        v[j] = x[base + c] + r[base + c];
        s += v[j];
    }
    __shared__ float sh[8];
    #pragma unroll
    for (int off = 16; off > 0; off >>= 1) s += __shfl_xor_sync(0xffffffffu, s, off);
    if ((tid & 31) == 0) sh[tid >> 5] = s;
    __syncthreads();
    if (tid < 32) {
        float t = (tid < 8) ? sh[tid] : 0.f;
        #pragma unroll
        for (int off = 4; off > 0; off >>= 1) t += __shfl_xor_sync(0xffffffffu, t, off);
        if (tid == 0) sh[0] = t;
    }
    __syncthreads();
    float mu = sh[0] * (1.f / 1024.f);
    __syncthreads();
    float ss = 0.f;
    #pragma unroll
    for (int j = 0; j < 4; ++j) { float d = v[j] - mu; ss += d * d; }
    #pragma unroll
    for (int off = 16; off > 0; off >>= 1) ss += __shfl_xor_sync(0xffffffffu, ss, off);
    if ((tid & 31) == 0) sh[tid >> 5] = ss;
    __syncthreads();
    if (tid < 32) {
        float t = (tid < 8) ? sh[tid] : 0.f;
        #pragma unroll
        for (int off = 4; off > 0; off >>= 1) t += __shfl_xor_sync(0xffffffffu, t, off);
        if (tid == 0) sh[0] = t;
    }
    __syncthreads();
    float var = sh[0] * (1.f / 1024.f);
    float rstd = rsqrtf(var + 1e-5f);
    #pragma unroll
    for (int j = 0; j < 4; ++j) {
        int c = tid + j * 256;
        x[base + c] = (v[j] - mu) * rstd * g[c] + bb[c];
    }
}

// ---------------------------------------------------------------------------
#define GEMM_SMEM (8 * BUFELEM * 2)   // 81920 bytes

extern "C" void kernel_launch(void* const* d_in, const int* in_sizes, int n_in,
                              void* d_out, int out_size) {
    const int*   tokens = (const int*)  d_in[0];
    const float* emb    = (const float*)d_in[1];
    const float* qkv_w  = (const float*)d_in[2];
    const float* qkv_b  = (const float*)d_in[3];
    const float* out_w  = (const float*)d_in[4];
    const float* out_b  = (const float*)d_in[5];
    const float* fc1_w  = (const float*)d_in[6];
    const float* fc1_b  = (const float*)d_in[7];
    const float* fc2_w  = (const float*)d_in[8];
    const float* fc2_b  = (const float*)d_in[9];
    const float* ln1_g  = (const float*)d_in[10];
    const float* ln1_b  = (const float*)d_in[11];
    const float* ln2_g  = (const float*)d_in[12];
    const float* ln2_b  = (const float*)d_in[13];
    const float* w_out  = (const float*)d_in[14];
    const float* b_out  = (const float*)d_in[15];
    float* out = (float*)d_out;

    float *x, *tmp, *o;
    cudaGetSymbolAddress((void**)&x,   g_x);
    cudaGetSymbolAddress((void**)&tmp, g_tmp);
    cudaGetSymbolAddress((void**)&o,   g_o);

    cudaFuncSetAttribute(mma_gemm, cudaFuncAttributeMaxDynamicSharedMemorySize,
                         GEMM_SMEM);

    embed_kernel<<<TOK_, 256>>>(tokens, emb, x);

    for (int l = 0; l < L_; ++l) {
        mma_gemm<<<dim3(3072 / 128, TOK_ / 128), 512, GEMM_SMEM>>>(
            x, qkv_w + (size_t)l * D_ * 3 * D_, qkv_b + (size_t)l * 3 * D_,
            tmp, TOK_, 3 * D_, D_, 0);
        attn_kernel<<<dim3(S_ / 64, B_ * H_), 256>>>(tmp, o);
        mma_gemm<<<dim3(D_ / 128, TOK_ / 128), 512, GEMM_SMEM>>>(
            o, out_w + (size_t)l * D_ * D_, out_b + (size_t)l * D_,
            tmp, TOK_, D_, D_, 0);
        add_ln_kernel<<<TOK_, 256>>>(x, tmp, ln1_g + l * D_, ln1_b + l * D_);
        mma_gemm<<<dim3(FF_ / 128, TOK_ / 128), 512, GEMM_SMEM>>>(
            x, fc1_w + (size_t)l * D_ * FF_, fc1_b + (size_t)l * FF_,
            tmp, TOK_, FF_, D_, 1);
        mma_gemm<<<dim3(D_ / 128, TOK_ / 128), 512, GEMM_SMEM>>>(
            tmp, fc2_w + (size_t)l * FF_ * D_, fc2_b + (size_t)l * D_,
            o, TOK_, D_, FF_, 0);
        add_ln_kernel<<<TOK_, 256>>>(x, o, ln2_g + l * D_, ln2_b + l * D_);
    }

    mma_gemm<<<dim3(V_ / 128, TOK_ / 128), 512, GEMM_SMEM>>>(
        x, w_out, b_out, out, TOK_, V_, D_, 0);
}

// round 4
// speedup vs baseline: 3.8056x; 1.8851x over previous
#include <cuda_runtime.h>
#include <cuda_bf16.h>
#include <math.h>
#include <stdint.h>

#define B_ 2
#define S_ 2048
#define D_ 1024
#define L_ 6
#define H_ 16
#define HD_ 64
#define FF_ 4096
#define V_ 32000
#define TOK_ (B_ * S_)          // 4096 token rows

// ---------------- scratch (static device globals; no allocation) ----------
__device__ float g_x[TOK_ * D_];                    // fp32 residual stream
__device__ float g_tmp[TOK_ * FF_];                 // qkv fp32 / out-proj out
__device__ float g_o[TOK_ * D_];                    // fc2 out (pre-LN2)
__device__ __nv_bfloat16 g_xh[TOK_ * D_];           // x split
__device__ __nv_bfloat16 g_xl[TOK_ * D_];
__device__ __nv_bfloat16 g_oh[TOK_ * D_];           // attention out split
__device__ __nv_bfloat16 g_ol[TOK_ * D_];
__device__ __nv_bfloat16 g_hh[TOK_ * FF_];          // ffn hidden split
__device__ __nv_bfloat16 g_hl[TOK_ * FF_];
__device__ __nv_bfloat16 g_wh[(size_t)D_ * V_];     // weight split (reused)
__device__ __nv_bfloat16 g_wl[(size_t)D_ * V_];

__device__ __forceinline__ void split1(float x, __nv_bfloat16& h, __nv_bfloat16& l) {
    h = __float2bfloat16(x);
    l = __float2bfloat16(x - __bfloat162float(h));
}

// ---------------- weight split: fp32 -> bf16 hi/lo (same layout) ----------
__global__ void split_kernel(const float* __restrict__ in,
                             __nv_bfloat16* __restrict__ hi,
                             __nv_bfloat16* __restrict__ lo, int n) {
    int i = (blockIdx.x * 256 + threadIdx.x) * 4;
    if (i >= n) return;
    float4 v = *(const float4*)(in + i);
    __nv_bfloat16 h[4], l[4];
    split1(v.x, h[0], l[0]); split1(v.y, h[1], l[1]);
    split1(v.z, h[2], l[2]); split1(v.w, h[3], l[3]);
    *(__nv_bfloat162*)(hi + i)     = __nv_bfloat162{h[0], h[1]};
    *(__nv_bfloat162*)(hi + i + 2) = __nv_bfloat162{h[2], h[3]};
    *(__nv_bfloat162*)(lo + i)     = __nv_bfloat162{l[0], l[1]};
    *(__nv_bfloat162*)(lo + i + 2) = __nv_bfloat162{l[2], l[3]};
}

// ---------------- embedding + positional encoding (+ split out) -----------
__global__ void embed_kernel(const int* __restrict__ tokens,
                             const float* __restrict__ emb,
                             float* __restrict__ x,
                             __nv_bfloat16* __restrict__ xh,
                             __nv_bfloat16* __restrict__ xl) {
    int row = blockIdx.x;
    int s   = row & (S_ - 1);
    int tok = tokens[row];
    const float* erow = emb + (size_t)tok * D_;
    size_t base = (size_t)row * D_;
    const float kfac = -0.00899447301950812f;   // -ln(10000)/1024
    #pragma unroll
    for (int j = 0; j < 4; ++j) {
        int c = threadIdx.x + j * 256;
        float freq = expf(kfac * (float)(c & ~1));
        float arg  = (float)s * freq;
        float pe   = (c & 1) ? cosf(arg) : sinf(arg);
        float v = erow[c] + pe;
        x[base + c] = v;
        __nv_bfloat16 h, l; split1(v, h, l);
        xh[base + c] = h; xl[base + c] = l;
    }
}

// ===================== bf16 hi/lo tensor-core GEMM =========================
// C = (Ah+Al)[MxK] @ (Bh+Bl)[KxN] + bias (3-term split, fp32 acc).
// 512 threads = 16 warps (4x4), warp tile 32x32, block tile 128x128x32.
// cp.async 3-stage pipeline. A smem [128][40] bf16, B smem [32][136] bf16.
// mode 0: store fp32 C.  mode 1: relu, store bf16 hi/lo to Ch/Cl.

__device__ __forceinline__ uint32_t sptr(const void* p) {
    return (uint32_t)__cvta_generic_to_shared(p);
}

#define LDSM4(R0, R1, R2, R3, ADDR) \
    asm volatile("ldmatrix.sync.aligned.m8n8.x4.shared.b16 {%0,%1,%2,%3}, [%4];" \
                 : "=r"(R0), "=r"(R1), "=r"(R2), "=r"(R3) : "r"(ADDR))
#define LDSM4T(R0, R1, R2, R3, ADDR) \
    asm volatile("ldmatrix.sync.aligned.m8n8.x4.trans.shared.b16 {%0,%1,%2,%3}, [%4];" \
                 : "=r"(R0), "=r"(R1), "=r"(R2), "=r"(R3) : "r"(ADDR))
#define MMA16816(Cv, Ar, Bb0, Bb1) \
    asm volatile("mma.sync.aligned.m16n8k16.row.col.f32.bf16.bf16.f32 " \
                 "{%0,%1,%2,%3},{%4,%5,%6,%7},{%8,%9},{%0,%1,%2,%3};" \
                 : "+f"(Cv[0]), "+f"(Cv[1]), "+f"(Cv[2]), "+f"(Cv[3]) \
                 : "r"(Ar[0]), "r"(Ar[1]), "r"(Ar[2]), "r"(Ar[3]), \
                   "r"(Bb0), "r"(Bb1))
#define CP16(DST, SRC) \
    asm volatile("cp.async.cg.shared.global [%0], [%1], 16;" :: "r"(DST), "l"(SRC))
#define CPCOMMIT() asm volatile("cp.async.commit_group;")
#define CPWAIT1()  asm volatile("cp.async.wait_group 1;")

#define AST 40            // A smem stride (elems); 80B rows, conflict-free LDSM
#define BST 136           // B smem stride (elems); 272B rows, conflict-free
#define A_ELEM (128 * AST)            // 5120
#define B_ELEM (32 * BST)             // 4352
#define STAGE_E (2 * A_ELEM + 2 * B_ELEM)  // 18944 elems per stage
#define GEMM_SMEM (3 * STAGE_E * 2)        // 113664 bytes

// issue one pipeline stage: 4 x cp.async.128 per thread
#define ISSUE_STAGE(SIDX, K0) do {                                          \
    __nv_bfloat16* _b = sm + (SIDX) * STAGE_E;                              \
    uint32_t _da = sptr(_b + arow * AST + ak);                              \
    CP16(_da,                 gAh + (K0));                                  \
    CP16(_da + A_ELEM * 2,    gAl + (K0));                                  \
    uint32_t _db = sptr(_b + 2 * A_ELEM + brow * BST + bn);                 \
    CP16(_db,                 gBh + (size_t)(K0) * N);                      \
    CP16(_db + B_ELEM * 2,    gBl + (size_t)(K0) * N);                      \
} while (0)

__global__ void __launch_bounds__(512, 1)
mma_gemm(const __nv_bfloat16* __restrict__ Ah, const __nv_bfloat16* __restrict__ Al,
         const __nv_bfloat16* __restrict__ Bh, const __nv_bfloat16* __restrict__ Bl,
         const float* __restrict__ bias,
         float* __restrict__ C,
         __nv_bfloat16* __restrict__ Ch, __nv_bfloat16* __restrict__ Cl,
         int M, int N, int K, int mode) {
    extern __shared__ __nv_bfloat16 sm[];

    const int tid = threadIdx.x;
    const int wid = tid >> 5, lane = tid & 31;
    const int wm = (wid >> 2) << 5;     // warp m offset
    const int wn = (wid & 3) << 5;      // warp n offset
    const int bx = blockIdx.x, by = blockIdx.y;

    // cp.async mappings
    const int arow = tid >> 2;          // 0..127
    const int ak   = (tid & 3) << 3;    // 0,8,16,24
    const int brow = tid >> 4;          // 0..31
    const int bn   = (tid & 15) << 3;   // 0..120

    const __nv_bfloat16* gAh = Ah + (size_t)(by * 128 + arow) * K + ak;
    const __nv_bfloat16* gAl = Al + (size_t)(by * 128 + arow) * K + ak;
    const __nv_bfloat16* gBh = Bh + (size_t)brow * N + bx * 128 + bn;
    const __nv_bfloat16* gBl = Bl + (size_t)brow * N + bx * 128 + bn;

    float acc[2][4][4];
    #pragma unroll
    for (int i = 0; i < 2; ++i)
        #pragma unroll
        for (int j = 0; j < 4; ++j)
            #pragma unroll
            for (int t = 0; t < 4; ++t) acc[i][j][t] = 0.f;

    // prologue: stages 0 and 1
    ISSUE_STAGE(0, 0); CPCOMMIT();
    ISSUE_STAGE(1, 32); CPCOMMIT();

    const int ntile = K >> 5;
    int buf = 0;
    for (int it = 0; it < ntile; ++it) {
        CPWAIT1();
        __syncthreads();

        // issue stage it+2 (into buffer computed at it-1)
        int nk = (it + 2) << 5;
        if (nk < K) {
            int s = (buf + 2) % 3;
            ISSUE_STAGE(s, nk);
        }
        CPCOMMIT();

        const __nv_bfloat16* ah = sm + buf * STAGE_E;
        const __nv_bfloat16* al = ah + A_ELEM;
        const __nv_bfloat16* bh = ah + 2 * A_ELEM;
        const __nv_bfloat16* bl = bh + B_ELEM;

        #pragma unroll
        for (int kc = 0; kc < 2; ++kc) {
            uint32_t a_h[2][4], a_l[2][4], b_h[4][2], b_l[4][2];
            int af = (lane & 15);
            int ac = kc * 16 + ((lane >> 4) << 3);
            #pragma unroll
            for (int mt = 0; mt < 2; ++mt) {
                uint32_t ad = sptr(ah + (wm + mt * 16 + af) * AST + ac);
                LDSM4(a_h[mt][0], a_h[mt][1], a_h[mt][2], a_h[mt][3], ad);
                ad = sptr(al + (wm + mt * 16 + af) * AST + ac);
                LDSM4(a_l[mt][0], a_l[mt][1], a_l[mt][2], a_l[mt][3], ad);
            }
            int bkr = kc * 16 + (lane & 15);
            #pragma unroll
            for (int p = 0; p < 2; ++p) {
                int bnc = wn + p * 16 + ((lane >> 4) << 3);
                uint32_t bd = sptr(bh + bkr * BST + bnc);
                LDSM4T(b_h[2*p][0], b_h[2*p][1], b_h[2*p+1][0], b_h[2*p+1][1], bd);
                bd = sptr(bl + bkr * BST + bnc);
                LDSM4T(b_l[2*p][0], b_l[2*p][1], b_l[2*p+1][0], b_l[2*p+1][1], bd);
            }
            #pragma unroll
            for (int mt = 0; mt < 2; ++mt)
                #pragma unroll
                for (int nt = 0; nt < 4; ++nt) {
                    MMA16816(acc[mt][nt], a_h[mt], b_h[nt][0], b_h[nt][1]);
                    MMA16816(acc[mt][nt], a_h[mt], b_l[nt][0], b_l[nt][1]);
                    MMA16816(acc[mt][nt], a_l[mt], b_h[nt][0], b_h[nt][1]);
                }
        }
        buf = (buf + 1) % 3;
        __syncthreads();
    }

    // ---- epilogue
    #pragma unroll
    for (int mt = 0; mt < 2; ++mt) {
        int row = by * 128 + wm + mt * 16 + (lane >> 2);
        #pragma unroll
        for (int nt = 0; nt < 4; ++nt) {
            int col = bx * 128 + wn + nt * 8 + ((lane & 3) << 1);
            float2 bv = *(const float2*)(bias + col);
            float v0 = acc[mt][nt][0] + bv.x;
            float v1 = acc[mt][nt][1] + bv.y;
            float v2 = acc[mt][nt][2] + bv.x;
            float v3 = acc[mt][nt][3] + bv.y;
            if (mode == 0) {
                float2 o0 = {v0, v1}, o1 = {v2, v3};
                *(float2*)(C + (size_t)row * N + col)       = o0;
                *(float2*)(C + (size_t)(row + 8) * N + col) = o1;
            } else {
                v0 = fmaxf(v0, 0.f); v1 = fmaxf(v1, 0.f);
                v2 = fmaxf(v2, 0.f); v3 = fmaxf(v3, 0.f);
                __nv_bfloat16 h0, l0, h1, l1, h2, l2, h3, l3;
                split1(v0, h0, l0); split1(v1, h1, l1);
                split1(v2, h2, l2); split1(v3, h3, l3);
                *(__nv_bfloat162*)(Ch + (size_t)row * N + col)       = __nv_bfloat162{h0, h1};
                *(__nv_bfloat162*)(Ch + (size_t)(row + 8) * N + col) = __nv_bfloat162{h2, h3};
                *(__nv_bfloat162*)(Cl + (size_t)row * N + col)       = __nv_bfloat162{l0, l1};
                *(__nv_bfloat162*)(Cl + (size_t)(row + 8) * N + col) = __nv_bfloat162{l2, l3};
            }
        }
    }
}

// ---------------- tiled causal flash attention (fp32, split output) -------
#define KT_ 32
__global__ void __launch_bounds__(256)
attn_kernel(const float* __restrict__ qkv,
            __nv_bfloat16* __restrict__ oh, __nv_bfloat16* __restrict__ ol) {
    int qb = gridDim.x - 1 - blockIdx.x;   // heavy blocks first
    int bh = blockIdx.y;
    int h = bh & (H_ - 1), b = bh >> 4;
    int tid = threadIdx.x;
    int tx = tid & 15;
    int ty = tid >> 4;

    __shared__ float Qt[64][68];
    __shared__ float Kt[64][34];
    __shared__ float Vs[KT_][64];
    __shared__ float Ps[KT_][68];
    __shared__ float m_s[64], d_s[64], corr_s[64];

    const float* qbase = qkv + (size_t)(b * S_ + qb * 64) * 3072 + h * 64;
    const float* kvbase = qkv + (size_t)(b * S_) * 3072 + h * 64;

    #pragma unroll
    for (int t = 0; t < 4; ++t) {
        int slot = tid + t * 256;
        int row = slot >> 4;
        int cq  = (slot & 15) << 2;
        float4 v = *(const float4*)(qbase + (size_t)row * 3072 + cq);
        Qt[cq + 0][row] = v.x;
        Qt[cq + 1][row] = v.y;
        Qt[cq + 2][row] = v.z;
        Qt[cq + 3][row] = v.w;
    }
    if (tid < 64) { m_s[tid] = -1e30f; d_s[tid] = 0.f; }

    float O[4][4];
    #pragma unroll
    for (int i = 0; i < 4; ++i)
        #pragma unroll
        for (int j = 0; j < 4; ++j) O[i][j] = 0.f;

    __syncthreads();

    int ntiles = 2 * qb + 2;
    for (int kt = 0; kt < ntiles; ++kt) {
        int j0 = kt * KT_;
        #pragma unroll
        for (int t = 0; t < 2; ++t) {
            int slot = tid + t * 256;
            int j  = slot >> 4;
            int cq = (slot & 15) << 2;
            const float* src = kvbase + (size_t)(j0 + j) * 3072;
            float4 kv = *(const float4*)(src + 1024 + cq);
            Kt[cq + 0][j] = kv.x;
            Kt[cq + 1][j] = kv.y;
            Kt[cq + 2][j] = kv.z;
            Kt[cq + 3][j] = kv.w;
            *(float4*)&Vs[j][cq] = *(const float4*)(src + 2048 + cq);
        }
        __syncthreads();

        float sc[4][2];
        #pragma unroll
        for (int i = 0; i < 4; ++i) { sc[i][0] = 0.f; sc[i][1] = 0.f; }
        #pragma unroll 4
        for (int d = 0; d < 64; ++d) {
            float4 q4 = *(const float4*)&Qt[d][ty << 2];
            float2 k2 = *(const float2*)&Kt[d][tx << 1];
            sc[0][0] = fmaf(q4.x, k2.x, sc[0][0]);
            sc[1][0] = fmaf(q4.y, k2.x, sc[1][0]);
            sc[2][0] = fmaf(q4.z, k2.x, sc[2][0]);
            sc[3][0] = fmaf(q4.w, k2.x, sc[3][0]);
            sc[0][1] = fmaf(q4.x, k2.y, sc[0][1]);
            sc[1][1] = fmaf(q4.y, k2.y, sc[1][1]);
            sc[2][1] = fmaf(q4.z, k2.y, sc[2][1]);
            sc[3][1] = fmaf(q4.w, k2.y, sc[3][1]);
        }
        int qg = qb * 64 + (ty << 2);
        int kg = j0 + (tx << 1);
        #pragma unroll
        for (int i = 0; i < 4; ++i)
            #pragma unroll
            for (int jj = 0; jj < 2; ++jj) {
                float s = sc[i][jj] * 0.125f;
                if (kg + jj > qg + i) s = -1e30f;
                Ps[(tx << 1) + jj][(ty << 2) + i] = s;
            }
        __syncthreads();

        {
            int q = tid >> 2, part = tid & 3;
            float mold = m_s[q];
            float mx = mold;
            float vals[8];
            #pragma unroll
            for (int jj = 0; jj < 8; ++jj) {
                vals[jj] = Ps[(part << 3) + jj][q];
                mx = fmaxf(mx, vals[jj]);
            }
            mx = fmaxf(mx, __shfl_xor_sync(0xffffffffu, mx, 1));
            mx = fmaxf(mx, __shfl_xor_sync(0xffffffffu, mx, 2));
            float sum = 0.f;
            #pragma unroll
            for (int jj = 0; jj < 8; ++jj) {
                float p = __expf(vals[jj] - mx);
                Ps[(part << 3) + jj][q] = p;
                sum += p;
            }
            sum += __shfl_xor_sync(0xffffffffu, sum, 1);
            sum += __shfl_xor_sync(0xffffffffu, sum, 2);
            if (part == 0) {
                float corr = __expf(mold - mx);
                d_s[q] = d_s[q] * corr + sum;
                m_s[q] = mx;
                corr_s[q] = corr;
            }
        }
        __syncthreads();

        {
            float c0 = corr_s[(ty << 2) + 0];
            float c1 = corr_s[(ty << 2) + 1];
            float c2 = corr_s[(ty << 2) + 2];
            float c3 = corr_s[(ty << 2) + 3];
            #pragma unroll
            for (int j4 = 0; j4 < 4; ++j4) {
                O[0][j4] *= c0; O[1][j4] *= c1; O[2][j4] *= c2; O[3][j4] *= c3;
            }
            #pragma unroll 4
            for (int j = 0; j < KT_; ++j) {
                float4 p4 = *(const float4*)&Ps[j][ty << 2];
                float4 v4 = *(const float4*)&Vs[j][tx << 2];
                O[0][0] = fmaf(p4.x, v4.x, O[0][0]);
                O[0][1] = fmaf(p4.x, v4.y, O[0][1]);
                O[0][2] = fmaf(p4.x, v4.z, O[0][2]);
                O[0][3] = fmaf(p4.x, v4.w, O[0][3]);
                O[1][0] = fmaf(p4.y, v4.x, O[1][0]);
                O[1][1] = fmaf(p4.y, v4.y, O[1][1]);
                O[1][2] = fmaf(p4.y, v4.z, O[1][2]);
                O[1][3] = fmaf(p4.y, v4.w, O[1][3]);
                O[2][0] = fmaf(p4.z, v4.x, O[2][0]);
                O[2][1] = fmaf(p4.z, v4.y, O[2][1]);
                O[2][2] = fmaf(p4.z, v4.z, O[2][2]);
                O[2][3] = fmaf(p4.z, v4.w, O[2][3]);
                O[3][0] = fmaf(p4.w, v4.x, O[3][0]);
                O[3][1] = fmaf(p4.w, v4.y, O[3][1]);
                O[3][2] = fmaf(p4.w, v4.z, O[3][2]);
                O[3][3] = fmaf(p4.w, v4.w, O[3][3]);
            }
        }
        __syncthreads();
    }

    #pragma unroll
    for (int i = 0; i < 4; ++i) {
        int q = (ty << 2) + i;
        float inv = 1.f / d_s[q];
        size_t base = (size_t)(b * S_ + qb * 64 + q) * D_ + h * 64 + (tx << 2);
        #pragma unroll
        for (int j = 0; j < 4; ++j) {
            float v = O[i][j] * inv;
            __nv_bfloat16 hh, ll; split1(v, hh, ll);
            oh[base + j] = hh;
            ol[base + j] = ll;
        }
    }
}

// ---------------- fused residual add + LayerNorm (+ split out) ------------
__global__ void add_ln_kernel(float* __restrict__ x,
                              const float* __restrict__ r,
                              const float* __restrict__ g,
                              const float* __restrict__ bb,
                              __nv_bfloat16* __restrict__ xh,
                              __nv_bfloat16* __restrict__ xl) {
    int row = blockIdx.x;
    int tid = threadIdx.x;
    size_t base = (size_t)row * D_;
    float v[4];
    float s = 0.f;
    #pragma unroll
    for (int j = 0; j < 4; ++j) {
        int c = tid + j * 256;
        v[j] = x[base + c] + r[base + c];
        s += v[j];
    }
    __shared__ float sh[8];
    #pragma unroll
    for (int off = 16; off > 0; off >>= 1) s += __shfl_xor_sync(0xffffffffu, s, off);
    if ((tid & 31) == 0) sh[tid >> 5] = s;
    __syncthreads();
    if (tid < 32) {
        float t = (tid < 8) ? sh[tid] : 0.f;
        #pragma unroll
        for (int off = 4; off > 0; off >>= 1) t += __shfl_xor_sync(0xffffffffu, t, off);
        if (tid == 0) sh[0] = t;
    }
    __syncthreads();
    float mu = sh[0] * (1.f / 1024.f);
    __syncthreads();
    float ss = 0.f;
    #pragma unroll
    for (int j = 0; j < 4; ++j) { float d = v[j] - mu; ss += d * d; }
    #pragma unroll
    for (int off = 16; off > 0; off >>= 1) ss += __shfl_xor_sync(0xffffffffu, ss, off);
    if ((tid & 31) == 0) sh[tid >> 5] = ss;
    __syncthreads();
    if (tid < 32) {
        float t = (tid < 8) ? sh[tid] : 0.f;
        #pragma unroll
        for (int off = 4; off > 0; off >>= 1) t += __shfl_xor_sync(0xffffffffu, t, off);
        if (tid == 0) sh[0] = t;
    }
    __syncthreads();
    float var = sh[0] * (1.f / 1024.f);
    float rstd = rsqrtf(var + 1e-5f);
    #pragma unroll
    for (int j = 0; j < 4; ++j) {
        int c = tid + j * 256;
        float y = (v[j] - mu) * rstd * g[c] + bb[c];
        x[base + c] = y;
        __nv_bfloat16 h, l; split1(y, h, l);
        xh[base + c] = h; xl[base + c] = l;
    }
}

// ---------------------------------------------------------------------------
extern "C" void kernel_launch(void* const* d_in, const int* in_sizes, int n_in,
                              void* d_out, int out_size) {
    const int*   tokens = (const int*)  d_in[0];
    const float* emb    = (const float*)d_in[1];
    const float* qkv_w  = (const float*)d_in[2];
    const float* qkv_b  = (const float*)d_in[3];
    const float* out_w  = (const float*)d_in[4];
    const float* out_b  = (const float*)d_in[5];
    const float* fc1_w  = (const float*)d_in[6];
    const float* fc1_b  = (const float*)d_in[7];
    const float* fc2_w  = (const float*)d_in[8];
    const float* fc2_b  = (const float*)d_in[9];
    const float* ln1_g  = (const float*)d_in[10];
    const float* ln1_b  = (const float*)d_in[11];
    const float* ln2_g  = (const float*)d_in[12];
    const float* ln2_b  = (const float*)d_in[13];
    const float* w_out  = (const float*)d_in[14];
    const float* b_out  = (const float*)d_in[15];
    float* out = (float*)d_out;

    float *x, *tmp, *o;
    __nv_bfloat16 *xh, *xl, *oh, *ol, *hh, *hl, *wh, *wl;
    cudaGetSymbolAddress((void**)&x,   g_x);
    cudaGetSymbolAddress((void**)&tmp, g_tmp);
    cudaGetSymbolAddress((void**)&o,   g_o);
    cudaGetSymbolAddress((void**)&xh,  g_xh);
    cudaGetSymbolAddress((void**)&xl,  g_xl);
    cudaGetSymbolAddress((void**)&oh,  g_oh);
    cudaGetSymbolAddress((void**)&ol,  g_ol);
    cudaGetSymbolAddress((void**)&hh,  g_hh);
    cudaGetSymbolAddress((void**)&hl,  g_hl);
    cudaGetSymbolAddress((void**)&wh,  g_wh);
    cudaGetSymbolAddress((void**)&wl,  g_wl);

    cudaFuncSetAttribute(mma_gemm, cudaFuncAttributeMaxDynamicSharedMemorySize,
                         GEMM_SMEM);

    embed_kernel<<<TOK_, 256>>>(tokens, emb, x, xh, xl);

    for (int l = 0; l < L_; ++l) {
        // qkv = x @ qkv_w + b
        int nqkv = D_ * 3 * D_;
        split_kernel<<<nqkv / 1024, 256>>>(qkv_w + (size_t)l * nqkv, wh, wl, nqkv);
        mma_gemm<<<dim3(3072 / 128, TOK_ / 128), 512, GEMM_SMEM>>>(
            xh, xl, wh, wl, qkv_b + (size_t)l * 3 * D_,
            tmp, nullptr, nullptr, TOK_, 3 * D_, D_, 0);
        // attention
        attn_kernel<<<dim3(S_ / 64, B_ * H_), 256>>>(tmp, oh, ol);
        // out proj
        int nout = D_ * D_;
        split_kernel<<<nout / 1024, 256>>>(out_w + (size_t)l * nout, wh, wl, nout);
        mma_gemm<<<dim3(D_ / 128, TOK_ / 128), 512, GEMM_SMEM>>>(
            oh, ol, wh, wl, out_b + (size_t)l * D_,
            tmp, nullptr, nullptr, TOK_, D_, D_, 0);
        add_ln_kernel<<<TOK_, 256>>>(x, tmp, ln1_g + l * D_, ln1_b + l * D_, xh, xl);
        // fc1 (relu, split output)
        int nfc1 = D_ * FF_;
        split_kernel<<<nfc1 / 1024, 256>>>(fc1_w + (size_t)l * nfc1, wh, wl, nfc1);
        mma_gemm<<<dim3(FF_ / 128, TOK_ / 128), 512, GEMM_SMEM>>>(
            xh, xl, wh, wl, fc1_b + (size_t)l * FF_,
            nullptr, hh, hl, TOK_, FF_, D_, 1);
        // fc2
        int nfc2 = FF_ * D_;
        split_kernel<<<nfc2 / 1024, 256>>>(fc2_w + (size_t)l * nfc2, wh, wl, nfc2);
        mma_gemm<<<dim3(D_ / 128, TOK_ / 128), 512, GEMM_SMEM>>>(
            hh, hl, wh, wl, fc2_b + (size_t)l * D_,
            o, nullptr, nullptr, TOK_, D_, FF_, 0);
        add_ln_kernel<<<TOK_, 256>>>(x, o, ln2_g + l * D_, ln2_b + l * D_, xh, xl);
    }

    // logits
    int nlog = D_ * V_;
    split_kernel<<<nlog / 1024, 256>>>(w_out, wh, wl, nlog);
    mma_gemm<<<dim3(V_ / 128, TOK_ / 128), 512, GEMM_SMEM>>>(
        xh, xl, wh, wl, b_out, out, nullptr, nullptr, TOK_, V_, D_, 0);
}

// round 6
// speedup vs baseline: 5.1345x; 1.3492x over previous
#include <cuda_runtime.h>
#include <cuda_bf16.h>
#include <math.h>
#include <stdint.h>

#define B_ 2
#define S_ 2048
#define D_ 1024
#define L_ 6
#define H_ 16
#define HD_ 64
#define FF_ 4096
#define V_ 32000
#define TOK_ (B_ * S_)          // 4096 token rows

// ---------------- scratch (static device globals; no allocation) ----------
__device__ float g_x[TOK_ * D_];                    // fp32 residual stream
__device__ float g_tmp[TOK_ * FF_];                 // out-proj / fc2 fp32 out
__device__ float g_o[TOK_ * D_];                    // fc2 out (pre-LN2)
__device__ __nv_bfloat16 g_xh[TOK_ * D_];           // x split
__device__ __nv_bfloat16 g_xl[TOK_ * D_];
__device__ __nv_bfloat16 g_oh[TOK_ * D_];           // attention out split
__device__ __nv_bfloat16 g_ol[TOK_ * D_];
__device__ __nv_bfloat16 g_hh[TOK_ * FF_];          // ffn hidden / qkv split
__device__ __nv_bfloat16 g_hl[TOK_ * FF_];
__device__ __nv_bfloat16 g_wh[(size_t)D_ * V_];     // weight split (reused)
__device__ __nv_bfloat16 g_wl[(size_t)D_ * V_];

__device__ __forceinline__ void split1(float x, __nv_bfloat16& h, __nv_bfloat16& l) {
    h = __float2bfloat16(x);
    l = __float2bfloat16(x - __bfloat162float(h));
}
__device__ __forceinline__ void split2u(float x, float y, uint32_t& h, uint32_t& l) {
    __nv_bfloat16 hx, lx, hy, ly;
    split1(x, hx, lx); split1(y, hy, ly);
    __nv_bfloat162 th{hx, hy}, tl{lx, ly};
    h = *reinterpret_cast<uint32_t*>(&th);
    l = *reinterpret_cast<uint32_t*>(&tl);
}

// ---------------- weight split: fp32 -> bf16 hi/lo (same layout) ----------
__global__ void split_kernel(const float* __restrict__ in,
                             __nv_bfloat16* __restrict__ hi,
                             __nv_bfloat16* __restrict__ lo, int n) {
    int i = (blockIdx.x * 256 + threadIdx.x) * 4;
    if (i >= n) return;
    float4 v = *(const float4*)(in + i);
    __nv_bfloat16 h[4], l[4];
    split1(v.x, h[0], l[0]); split1(v.y, h[1], l[1]);
    split1(v.z, h[2], l[2]); split1(v.w, h[3], l[3]);
    *(__nv_bfloat162*)(hi + i)     = __nv_bfloat162{h[0], h[1]};
    *(__nv_bfloat162*)(hi + i + 2) = __nv_bfloat162{h[2], h[3]};
    *(__nv_bfloat162*)(lo + i)     = __nv_bfloat162{l[0], l[1]};
    *(__nv_bfloat162*)(lo + i + 2) = __nv_bfloat162{l[2], l[3]};
}

// ---------------- embedding + positional encoding (+ split out) -----------
__global__ void embed_kernel(const int* __restrict__ tokens,
                             const float* __restrict__ emb,
                             float* __restrict__ x,
                             __nv_bfloat16* __restrict__ xh,
                             __nv_bfloat16* __restrict__ xl) {
    int row = blockIdx.x;
    int s   = row & (S_ - 1);
    int tok = tokens[row];
    const float* erow = emb + (size_t)tok * D_;
    size_t base = (size_t)row * D_;
    const float kfac = -0.00899447301950812f;   // -ln(10000)/1024
    #pragma unroll
    for (int j = 0; j < 4; ++j) {
        int c = threadIdx.x + j * 256;
        float freq = expf(kfac * (float)(c & ~1));
        float arg  = (float)s * freq;
        float pe   = (c & 1) ? cosf(arg) : sinf(arg);
        float v = erow[c] + pe;
        x[base + c] = v;
        __nv_bfloat16 h, l; split1(v, h, l);
        xh[base + c] = h; xl[base + c] = l;
    }
}

// ===================== bf16 hi/lo tensor-core GEMM =========================
__device__ __forceinline__ uint32_t sptr(const void* p) {
    return (uint32_t)__cvta_generic_to_shared(p);
}

#define LDSM4(R0, R1, R2, R3, ADDR) \
    asm volatile("ldmatrix.sync.aligned.m8n8.x4.shared.b16 {%0,%1,%2,%3}, [%4];" \
                 : "=r"(R0), "=r"(R1), "=r"(R2), "=r"(R3) : "r"(ADDR))
#define LDSM4T(R0, R1, R2, R3, ADDR) \
    asm volatile("ldmatrix.sync.aligned.m8n8.x4.trans.shared.b16 {%0,%1,%2,%3}, [%4];" \
                 : "=r"(R0), "=r"(R1), "=r"(R2), "=r"(R3) : "r"(ADDR))
#define MMA16816(Cv, Ar, Bb0, Bb1) \
    asm volatile("mma.sync.aligned.m16n8k16.row.col.f32.bf16.bf16.f32 " \
                 "{%0,%1,%2,%3},{%4,%5,%6,%7},{%8,%9},{%0,%1,%2,%3};" \
                 : "+f"(Cv[0]), "+f"(Cv[1]), "+f"(Cv[2]), "+f"(Cv[3]) \
                 : "r"(Ar[0]), "r"(Ar[1]), "r"(Ar[2]), "r"(Ar[3]), \
                   "r"(Bb0), "r"(Bb1))
#define CP16(DST, SRC) \
    asm volatile("cp.async.cg.shared.global [%0], [%1], 16;" :: "r"(DST), "l"(SRC))
#define CPCOMMIT() asm volatile("cp.async.commit_group;")
#define CPWAIT1()  asm volatile("cp.async.wait_group 1;")
#define CPWAIT2()  asm volatile("cp.async.wait_group 2;")
#define CPWAITALL() asm volatile("cp.async.wait_all;")

#define AST 40
#define BST 136
#define A_ELEM (128 * AST)
#define B_ELEM (32 * BST)
#define STAGE_E (2 * A_ELEM + 2 * B_ELEM)
#define GEMM_SMEM (3 * STAGE_E * 2)

#define ISSUE_STAGE(SIDX, K0) do {                                          \
    __nv_bfloat16* _b = sm + (SIDX) * STAGE_E;                              \
    uint32_t _da = sptr(_b + arow * AST + ak);                              \
    CP16(_da,                 gAh + (K0));                                  \
    CP16(_da + A_ELEM * 2,    gAl + (K0));                                  \
    uint32_t _db = sptr(_b + 2 * A_ELEM + brow * BST + bn);                 \
    CP16(_db,                 gBh + (size_t)(K0) * N);                      \
    CP16(_db + B_ELEM * 2,    gBl + (size_t)(K0) * N);                      \
} while (0)

// mode 0: fp32 C. mode 1: relu + bf16 hi/lo split. mode 2: split, no relu.
__global__ void __launch_bounds__(512, 1)
mma_gemm(const __nv_bfloat16* __restrict__ Ah, const __nv_bfloat16* __restrict__ Al,
         const __nv_bfloat16* __restrict__ Bh, const __nv_bfloat16* __restrict__ Bl,
         const float* __restrict__ bias,
         float* __restrict__ C,
         __nv_bfloat16* __restrict__ Ch, __nv_bfloat16* __restrict__ Cl,
         int M, int N, int K, int mode) {
    extern __shared__ __nv_bfloat16 sm[];

    const int tid = threadIdx.x;
    const int wid = tid >> 5, lane = tid & 31;
    const int wm = (wid >> 2) << 5;
    const int wn = (wid & 3) << 5;
    const int bx = blockIdx.x, by = blockIdx.y;

    const int arow = tid >> 2;
    const int ak   = (tid & 3) << 3;
    const int brow = tid >> 4;
    const int bn   = (tid & 15) << 3;

    const __nv_bfloat16* gAh = Ah + (size_t)(by * 128 + arow) * K + ak;
    const __nv_bfloat16* gAl = Al + (size_t)(by * 128 + arow) * K + ak;
    const __nv_bfloat16* gBh = Bh + (size_t)brow * N + bx * 128 + bn;
    const __nv_bfloat16* gBl = Bl + (size_t)brow * N + bx * 128 + bn;

    float acc[2][4][4];
    #pragma unroll
    for (int i = 0; i < 2; ++i)
        #pragma unroll
        for (int j = 0; j < 4; ++j)
            #pragma unroll
            for (int t = 0; t < 4; ++t) acc[i][j][t] = 0.f;

    ISSUE_STAGE(0, 0); CPCOMMIT();
    ISSUE_STAGE(1, 32); CPCOMMIT();

    const int ntile = K >> 5;
    int buf = 0;
    for (int it = 0; it < ntile; ++it) {
        CPWAIT1();
        __syncthreads();

        int nk = (it + 2) << 5;
        if (nk < K) {
            int s = (buf + 2) % 3;
            ISSUE_STAGE(s, nk);
        }
        CPCOMMIT();

        const __nv_bfloat16* ah = sm + buf * STAGE_E;
        const __nv_bfloat16* al = ah + A_ELEM;
        const __nv_bfloat16* bh = ah + 2 * A_ELEM;
        const __nv_bfloat16* bl = bh + B_ELEM;

        #pragma unroll
        for (int kc = 0; kc < 2; ++kc) {
            uint32_t a_h[2][4], a_l[2][4], b_h[4][2], b_l[4][2];
            int af = (lane & 15);
            int ac = kc * 16 + ((lane >> 4) << 3);
            #pragma unroll
            for (int mt = 0; mt < 2; ++mt) {
                uint32_t ad = sptr(ah + (wm + mt * 16 + af) * AST + ac);
                LDSM4(a_h[mt][0], a_h[mt][1], a_h[mt][2], a_h[mt][3], ad);
                ad = sptr(al + (wm + mt * 16 + af) * AST + ac);
                LDSM4(a_l[mt][0], a_l[mt][1], a_l[mt][2], a_l[mt][3], ad);
            }
            int bkr = kc * 16 + (lane & 15);
            #pragma unroll
            for (int p = 0; p < 2; ++p) {
                int bnc = wn + p * 16 + ((lane >> 4) << 3);
                uint32_t bd = sptr(bh + bkr * BST + bnc);
                LDSM4T(b_h[2*p][0], b_h[2*p][1], b_h[2*p+1][0], b_h[2*p+1][1], bd);
                bd = sptr(bl + bkr * BST + bnc);
                LDSM4T(b_l[2*p][0], b_l[2*p][1], b_l[2*p+1][0], b_l[2*p+1][1], bd);
            }
            #pragma unroll
            for (int mt = 0; mt < 2; ++mt)
                #pragma unroll
                for (int nt = 0; nt < 4; ++nt) {
                    MMA16816(acc[mt][nt], a_h[mt], b_h[nt][0], b_h[nt][1]);
                    MMA16816(acc[mt][nt], a_h[mt], b_l[nt][0], b_l[nt][1]);
                    MMA16816(acc[mt][nt], a_l[mt], b_h[nt][0], b_h[nt][1]);
                }
        }
        buf = (buf + 1) % 3;
        __syncthreads();
    }

    #pragma unroll
    for (int mt = 0; mt < 2; ++mt) {
        int row = by * 128 + wm + mt * 16 + (lane >> 2);
        #pragma unroll
        for (int nt = 0; nt < 4; ++nt) {
            int col = bx * 128 + wn + nt * 8 + ((lane & 3) << 1);
            float2 bv = *(const float2*)(bias + col);
            float v0 = acc[mt][nt][0] + bv.x;
            float v1 = acc[mt][nt][1] + bv.y;
            float v2 = acc[mt][nt][2] + bv.x;
            float v3 = acc[mt][nt][3] + bv.y;
            if (mode == 0) {
                float2 o0 = {v0, v1}, o1 = {v2, v3};
                *(float2*)(C + (size_t)row * N + col)       = o0;
                *(float2*)(C + (size_t)(row + 8) * N + col) = o1;
            } else {
                if (mode == 1) {
                    v0 = fmaxf(v0, 0.f); v1 = fmaxf(v1, 0.f);
                    v2 = fmaxf(v2, 0.f); v3 = fmaxf(v3, 0.f);
                }
                uint32_t h01, l01, h23, l23;
                split2u(v0, v1, h01, l01);
                split2u(v2, v3, h23, l23);
                *(uint32_t*)(Ch + (size_t)row * N + col)       = h01;
                *(uint32_t*)(Ch + (size_t)(row + 8) * N + col) = h23;
                *(uint32_t*)(Cl + (size_t)row * N + col)       = l01;
                *(uint32_t*)(Cl + (size_t)(row + 8) * N + col) = l23;
            }
        }
    }
}

// ===================== tensor-core causal flash attention ==================
// Block: 128 threads (4 warps), 64 queries of one (b,h), 64-key tiles,
// double-buffered K/V, bf16 hi/lo 3-term splits for QK^T and PV.
#define APAD 72
#define AQBUF 4608                    // 64*72
#define AKV0 (2 * AQBUF)              // after Qh, Ql
#define AKVSTRIDE (4 * AQBUF)         // kh,kl,vh,vl per stage
#define ATT_SMEM ((2 * AQBUF + 2 * AKVSTRIDE) * 2)   // 92160 bytes

__global__ void __launch_bounds__(128, 2)
attn_mma(const __nv_bfloat16* __restrict__ qh,
         const __nv_bfloat16* __restrict__ ql,
         __nv_bfloat16* __restrict__ oh,
         __nv_bfloat16* __restrict__ ol) {
    extern __shared__ __nv_bfloat16 sm[];
    const int tid = threadIdx.x;
    const int wid = tid >> 5, lane = tid & 31;
    const int qb = gridDim.x - 1 - blockIdx.x;     // heavy blocks first
    const int bh = blockIdx.y;
    const int h = bh & (H_ - 1), b = bh >> 4;
    const int wq0 = wid << 4;                      // warp query offset

    const size_t seqbase = (size_t)(b * S_) * 3072 + h * 64;

    // ---- issue Q tile (hi+lo), then KV tiles 0 and 1
    {
        #pragma unroll
        for (int i = 0; i < 4; ++i) {
            int id = tid + i * 128;
            int row = id >> 3, col = (id & 7) << 3;
            size_t src = seqbase + (size_t)(qb * 64 + row) * 3072 + col;
            uint32_t dst = sptr(sm + row * APAD + col);
            CP16(dst, qh + src);
            CP16(dst + AQBUF * 2, ql + src);
        }
        CPCOMMIT();
    }
    #define ISSUE_KV(STG, KT0) do {                                         \
        __nv_bfloat16* _kb = sm + AKV0 + (STG) * AKVSTRIDE;                 \
        _Pragma("unroll")                                                   \
        for (int i = 0; i < 4; ++i) {                                       \
            int id = tid + i * 128;                                         \
            int row = id >> 3, col = (id & 7) << 3;                         \
            size_t src = seqbase + (size_t)((KT0) * 64 + row) * 3072 + col; \
            uint32_t dst = sptr(_kb + row * APAD + col);                    \
            CP16(dst,                 qh + src + 1024);                     \
            CP16(dst + AQBUF * 2,     ql + src + 1024);                     \
            CP16(dst + AQBUF * 4,     qh + src + 2048);                     \
            CP16(dst + AQBUF * 6,     ql + src + 2048);                     \
        }                                                                   \
        CPCOMMIT();                                                         \
    } while (0)

    ISSUE_KV(0, 0);
    ISSUE_KV(1, (qb >= 1 ? 1 : 0));

    // ---- Q fragments (hoisted)
    CPWAIT2();
    __syncthreads();
    uint32_t qf_h[4][4], qf_l[4][4];
    {
        int af = lane & 15;
        #pragma unroll
        for (int kc = 0; kc < 4; ++kc) {
            int ac = kc * 16 + ((lane >> 4) << 3);
            uint32_t ad = sptr(sm + (wq0 + af) * APAD + ac);
            LDSM4(qf_h[kc][0], qf_h[kc][1], qf_h[kc][2], qf_h[kc][3], ad);
            ad = sptr(sm + AQBUF + (wq0 + af) * APAD + ac);
            LDSM4(qf_l[kc][0], qf_l[kc][1], qf_l[kc][2], qf_l[kc][3], ad);
        }
    }

    float Od[8][4];
    #pragma unroll
    for (int i = 0; i < 8; ++i)
        #pragma unroll
        for (int j = 0; j < 4; ++j) Od[i][j] = 0.f;
    float m_a = -1e30f, m_b = -1e30f, den_a = 0.f, den_b = 0.f;

    int buf = 0;
    const int ntk = qb + 1;
    for (int kt = 0; kt < ntk; ++kt) {
        CPWAIT1();
        __syncthreads();

        const __nv_bfloat16* kh = sm + AKV0 + buf * AKVSTRIDE;
        const __nv_bfloat16* kl = kh + AQBUF;
        const __nv_bfloat16* vh = kh + 2 * AQBUF;
        const __nv_bfloat16* vl = kh + 3 * AQBUF;

        // ---- scores = (Qh+Ql)(Kh+Kl)^T
        float sreg[8][4];
        #pragma unroll
        for (int i = 0; i < 8; ++i)
            #pragma unroll
            for (int j = 0; j < 4; ++j) sreg[i][j] = 0.f;

        #pragma unroll
        for (int kc = 0; kc < 4; ++kc) {
            int krow = ((lane >> 4) << 3) + (lane & 7);
            int kcol = kc * 16 + (((lane >> 3) & 1) << 3);
            #pragma unroll
            for (int ng = 0; ng < 4; ++ng) {
                uint32_t bh0, bh1, bh2, bh3, bl0, bl1, bl2, bl3;
                uint32_t ad = sptr(kh + (ng * 16 + krow) * APAD + kcol);
                LDSM4(bh0, bh1, bh2, bh3, ad);
                ad = sptr(kl + (ng * 16 + krow) * APAD + kcol);
                LDSM4(bl0, bl1, bl2, bl3, ad);
                MMA16816(sreg[2*ng],   qf_h[kc], bh0, bh1);
                MMA16816(sreg[2*ng],   qf_h[kc], bl0, bl1);
                MMA16816(sreg[2*ng],   qf_l[kc], bh0, bh1);
                MMA16816(sreg[2*ng+1], qf_h[kc], bh2, bh3);
                MMA16816(sreg[2*ng+1], qf_h[kc], bl2, bl3);
                MMA16816(sreg[2*ng+1], qf_l[kc], bh2, bh3);
            }
        }

        // ---- softmax (fp32, online)
        int ra = wq0 + (lane >> 2);       // row in 0..63
        int cb = (lane & 3) << 1;         // col base within n8
        #pragma unroll
        for (int nt = 0; nt < 8; ++nt) {
            #pragma unroll
            for (int j = 0; j < 4; ++j) {
                float s = sreg[nt][j] * 0.125f;
                if (kt == qb) {
                    int col = nt * 8 + cb + (j & 1);
                    int row = ra + ((j >> 1) << 3);
                    if (col > row) s = -1e30f;
                }
                sreg[nt][j] = s;
            }
        }
        float mxa = -1e30f, mxb = -1e30f;
        #pragma unroll
        for (int nt = 0; nt < 8; ++nt) {
            mxa = fmaxf(mxa, fmaxf(sreg[nt][0], sreg[nt][1]));
            mxb = fmaxf(mxb, fmaxf(sreg[nt][2], sreg[nt][3]));
        }
        mxa = fmaxf(mxa, __shfl_xor_sync(0xffffffffu, mxa, 1));
        mxa = fmaxf(mxa, __shfl_xor_sync(0xffffffffu, mxa, 2));
        mxb = fmaxf(mxb, __shfl_xor_sync(0xffffffffu, mxb, 1));
        mxb = fmaxf(mxb, __shfl_xor_sync(0xffffffffu, mxb, 2));
        float mna = fmaxf(m_a, mxa), mnb = fmaxf(m_b, mxb);
        float ca = __expf(m_a - mna), cbr = __expf(m_b - mnb);
        m_a = mna; m_b = mnb;
        float sa = 0.f, sb = 0.f;
        #pragma unroll
        for (int nt = 0; nt < 8; ++nt) {
            float p0 = __expf(sreg[nt][0] - mna);
            float p1 = __expf(sreg[nt][1] - mna);
            float p2 = __expf(sreg[nt][2] - mnb);
            float p3 = __expf(sreg[nt][3] - mnb);
            sreg[nt][0] = p0; sreg[nt][1] = p1; sreg[nt][2] = p2; sreg[nt][3] = p3;
            sa += p0 + p1; sb += p2 + p3;
        }
        sa += __shfl_xor_sync(0xffffffffu, sa, 1);
        sa += __shfl_xor_sync(0xffffffffu, sa, 2);
        sb += __shfl_xor_sync(0xffffffffu, sb, 1);
        sb += __shfl_xor_sync(0xffffffffu, sb, 2);
        den_a = den_a * ca + sa;
        den_b = den_b * cbr + sb;
        #pragma unroll
        for (int nt = 0; nt < 8; ++nt) {
            Od[nt][0] *= ca;  Od[nt][1] *= ca;
            Od[nt][2] *= cbr; Od[nt][3] *= cbr;
        }

        // ---- O += P @ V  (P hi/lo from regs, V hi/lo via ldmatrix.trans)
        #pragma unroll
        for (int kc2 = 0; kc2 < 4; ++kc2) {
            uint32_t pah[4], pal[4];
            split2u(sreg[2*kc2][0],   sreg[2*kc2][1],   pah[0], pal[0]);
            split2u(sreg[2*kc2][2],   sreg[2*kc2][3],   pah[1], pal[1]);
            split2u(sreg[2*kc2+1][0], sreg[2*kc2+1][1], pah[2], pal[2]);
            split2u(sreg[2*kc2+1][2], sreg[2*kc2+1][3], pah[3], pal[3]);
            int vr = kc2 * 16 + (lane & 15);
            #pragma unroll
            for (int ng = 0; ng < 4; ++ng) {
                int vc = ng * 16 + ((lane >> 4) << 3);
                uint32_t vh0, vh1, vh2, vh3, vl0, vl1, vl2, vl3;
                uint32_t ad = sptr(vh + vr * APAD + vc);
                LDSM4T(vh0, vh1, vh2, vh3, ad);
                ad = sptr(vl + vr * APAD + vc);
                LDSM4T(vl0, vl1, vl2, vl3, ad);
                MMA16816(Od[2*ng],   pah, vh0, vh1);
                MMA16816(Od[2*ng],   pah, vl0, vl1);
                MMA16816(Od[2*ng],   pal, vh0, vh1);
                MMA16816(Od[2*ng+1], pah, vh2, vh3);
                MMA16816(Od[2*ng+1], pah, vl2, vl3);
                MMA16816(Od[2*ng+1], pal, vh2, vh3);
            }
        }
        __syncthreads();
        if (kt + 2 <= qb) ISSUE_KV(buf, kt + 2);
        CPCOMMIT();
        buf ^= 1;
    }

    CPWAITALL();

    // ---- normalize + split write
    float inva = 1.f / den_a, invb = 1.f / den_b;
    int gq_a = qb * 64 + wq0 + (lane >> 2);
    size_t oa = (size_t)(b * S_ + gq_a) * D_ + h * 64 + ((lane & 3) << 1);
    size_t ob = oa + (size_t)8 * D_;
    #pragma unroll
    for (int nt = 0; nt < 8; ++nt) {
        uint32_t hA, lA, hB, lB;
        split2u(Od[nt][0] * inva, Od[nt][1] * inva, hA, lA);
        split2u(Od[nt][2] * invb, Od[nt][3] * invb, hB, lB);
        *(uint32_t*)(oh + oa + nt * 8) = hA;
        *(uint32_t*)(ol + oa + nt * 8) = lA;
        *(uint32_t*)(oh + ob + nt * 8) = hB;
        *(uint32_t*)(ol + ob + nt * 8) = lB;
    }
}

// ---------------- fused residual add + LayerNorm (+ split out) ------------
__global__ void add_ln_kernel(float* __restrict__ x,
                              const float* __restrict__ r,
                              const float* __restrict__ g,
                              const float* __restrict__ bb,
                              __nv_bfloat16* __restrict__ xh,
                              __nv_bfloat16* __restrict__ xl) {
    int row = blockIdx.x;
    int tid = threadIdx.x;
    size_t base = (size_t)row * D_;
    float v[4];
    float s = 0.f;
    #pragma unroll
    for (int j = 0; j < 4; ++j) {
        int c = tid + j * 256;
        v[j] = x[base + c] + r[base + c];
        s += v[j];
    }
    __shared__ float sh[8];
    #pragma unroll
    for (int off = 16; off > 0; off >>= 1) s += __shfl_xor_sync(0xffffffffu, s, off);
    if ((tid & 31) == 0) sh[tid >> 5] = s;
    __syncthreads();
    if (tid < 32) {
        float t = (tid < 8) ? sh[tid] : 0.f;
        #pragma unroll
        for (int off = 4; off > 0; off >>= 1) t += __shfl_xor_sync(0xffffffffu, t, off);
        if (tid == 0) sh[0] = t;
    }
    __syncthreads();
    float mu = sh[0] * (1.f / 1024.f);
    __syncthreads();
    float ss = 0.f;
    #pragma unroll
    for (int j = 0; j < 4; ++j) { float d = v[j] - mu; ss += d * d; }
    #pragma unroll
    for (int off = 16; off > 0; off >>= 1) ss += __shfl_xor_sync(0xffffffffu, ss, off);
    if ((tid & 31) == 0) sh[tid >> 5] = ss;
    __syncthreads();
    if (tid < 32) {
        float t = (tid < 8) ? sh[tid] : 0.f;
        #pragma unroll
        for (int off = 4; off > 0; off >>= 1) t += __shfl_xor_sync(0xffffffffu, t, off);
        if (tid == 0) sh[0] = t;
    }
    __syncthreads();
    float var = sh[0] * (1.f / 1024.f);
    float rstd = rsqrtf(var + 1e-5f);
    #pragma unroll
    for (int j = 0; j < 4; ++j) {
        int c = tid + j * 256;
        float y = (v[j] - mu) * rstd * g[c] + bb[c];
        x[base + c] = y;
        __nv_bfloat16 h, l; split1(y, h, l);
        xh[base + c] = h; xl[base + c] = l;
    }
}

// ---------------------------------------------------------------------------
extern "C" void kernel_launch(void* const* d_in, const int* in_sizes, int n_in,
                              void* d_out, int out_size) {
    const int*   tokens = (const int*)  d_in[0];
    const float* emb    = (const float*)d_in[1];
    const float* qkv_w  = (const float*)d_in[2];
    const float* qkv_b  = (const float*)d_in[3];
    const float* out_w  = (const float*)d_in[4];
    const float* out_b  = (const float*)d_in[5];
    const float* fc1_w  = (const float*)d_in[6];
    const float* fc1_b  = (const float*)d_in[7];
    const float* fc2_w  = (const float*)d_in[8];
    const float* fc2_b  = (const float*)d_in[9];
    const float* ln1_g  = (const float*)d_in[10];
    const float* ln1_b  = (const float*)d_in[11];
    const float* ln2_g  = (const float*)d_in[12];
    const float* ln2_b  = (const float*)d_in[13];
    const float* w_out  = (const float*)d_in[14];
    const float* b_out  = (const float*)d_in[15];
    float* out = (float*)d_out;

    float *x, *tmp, *o;
    __nv_bfloat16 *xh, *xl, *oh, *ol, *hh, *hl, *wh, *wl;
    cudaGetSymbolAddress((void**)&x,   g_x);
    cudaGetSymbolAddress((void**)&tmp, g_tmp);
    cudaGetSymbolAddress((void**)&o,   g_o);
    cudaGetSymbolAddress((void**)&xh,  g_xh);
    cudaGetSymbolAddress((void**)&xl,  g_xl);
    cudaGetSymbolAddress((void**)&oh,  g_oh);
    cudaGetSymbolAddress((void**)&ol,  g_ol);
    cudaGetSymbolAddress((void**)&hh,  g_hh);
    cudaGetSymbolAddress((void**)&hl,  g_hl);
    cudaGetSymbolAddress((void**)&wh,  g_wh);
    cudaGetSymbolAddress((void**)&wl,  g_wl);

    cudaFuncSetAttribute(mma_gemm, cudaFuncAttributeMaxDynamicSharedMemorySize,
                         GEMM_SMEM);
    cudaFuncSetAttribute(attn_mma, cudaFuncAttributeMaxDynamicSharedMemorySize,
                         ATT_SMEM);

    embed_kernel<<<TOK_, 256>>>(tokens, emb, x, xh, xl);

    for (int l = 0; l < L_; ++l) {
        // qkv = x @ qkv_w + b  -> bf16 hi/lo split (mode 2) into hh/hl
        int nqkv = D_ * 3 * D_;
        split_kernel<<<nqkv / 1024, 256>>>(qkv_w + (size_t)l * nqkv, wh, wl, nqkv);
        mma_gemm<<<dim3(3072 / 128, TOK_ / 128), 512, GEMM_SMEM>>>(
            xh, xl, wh, wl, qkv_b + (size_t)l * 3 * D_,
            nullptr, hh, hl, TOK_, 3 * D_, D_, 2);
        // attention (tensor core) -> oh/ol
        attn_mma<<<dim3(S_ / 64, B_ * H_), 128, ATT_SMEM>>>(hh, hl, oh, ol);
        // out proj -> tmp fp32
        int nout = D_ * D_;
        split_kernel<<<nout / 1024, 256>>>(out_w + (size_t)l * nout, wh, wl, nout);
        mma_gemm<<<dim3(D_ / 128, TOK_ / 128), 512, GEMM_SMEM>>>(
            oh, ol, wh, wl, out_b + (size_t)l * D_,
            tmp, nullptr, nullptr, TOK_, D_, D_, 0);
        add_ln_kernel<<<TOK_, 256>>>(x, tmp, ln1_g + l * D_, ln1_b + l * D_, xh, xl);
        // fc1 (relu + split)
        int nfc1 = D_ * FF_;
        split_kernel<<<nfc1 / 1024, 256>>>(fc1_w + (size_t)l * nfc1, wh, wl, nfc1);
        mma_gemm<<<dim3(FF_ / 128, TOK_ / 128), 512, GEMM_SMEM>>>(
            xh, xl, wh, wl, fc1_b + (size_t)l * FF_,
            nullptr, hh, hl, TOK_, FF_, D_, 1);
        // fc2
        int nfc2 = FF_ * D_;
        split_kernel<<<nfc2 / 1024, 256>>>(fc2_w + (size_t)l * nfc2, wh, wl, nfc2);
        mma_gemm<<<dim3(D_ / 128, TOK_ / 128), 512, GEMM_SMEM>>>(
            hh, hl, wh, wl, fc2_b + (size_t)l * D_,
            o, nullptr, nullptr, TOK_, D_, FF_, 0);
        add_ln_kernel<<<TOK_, 256>>>(x, o, ln2_g + l * D_, ln2_b + l * D_, xh, xl);
    }

    // logits
    int nlog = D_ * V_;
    split_kernel<<<nlog / 1024, 256>>>(w_out, wh, wl, nlog);
    mma_gemm<<<dim3(V_ / 128, TOK_ / 128), 512, GEMM_SMEM>>>(
        xh, xl, wh, wl, b_out, out, nullptr, nullptr, TOK_, V_, D_, 0);
}

// round 8
// speedup vs baseline: 6.9697x; 1.3574x over previous
#include <cuda_runtime.h>
#include <cuda_fp16.h>
#include <math.h>
#include <stdint.h>

#define B_ 2
#define S_ 2048
#define D_ 1024
#define L_ 6
#define H_ 16
#define HD_ 64
#define FF_ 4096
#define V_ 32000
#define TOK_ (B_ * S_)          // 4096 token rows

// ---------------- scratch (static device globals; no allocation) ----------
__device__ float g_x[TOK_ * D_];                 // fp32 residual stream
__device__ float g_tmp[TOK_ * FF_];              // out-proj / fc2 fp32 out
__device__ float g_o[TOK_ * D_];                 // fc2 out (pre-LN2)
__device__ __half g_xh[TOK_ * D_];               // x (fp16 hi plane)
__device__ __half g_oh[TOK_ * D_];               // attention out (hi plane)
__device__ __half g_hh[TOK_ * FF_];              // qkv / ffn hidden hi
__device__ __half g_hl[TOK_ * FF_];              // qkv lo (K/V lo planes)
__device__ __half g_wh[(size_t)D_ * V_];         // weight hi, layout [K][N]
__device__ __half g_wl[(size_t)D_ * V_];         // weight lo

__device__ __forceinline__ void split1h(float x, __half& h, __half& l) {
    h = __float2half_rn(x);
    l = __float2half_rn(x - __half2float(h));
}
__device__ __forceinline__ uint32_t packh2(float x, float y) {
    __half2 t = __floats2half2_rn(x, y);
    return *reinterpret_cast<uint32_t*>(&t);
}
__device__ __forceinline__ void split2uh(float x, float y, uint32_t& h, uint32_t& l) {
    __half hx, lx, hy, ly;
    split1h(x, hx, lx); split1h(y, hy, ly);
    __half2 th{hx, hy}, tl{lx, ly};
    h = *reinterpret_cast<uint32_t*>(&th);
    l = *reinterpret_cast<uint32_t*>(&tl);
}

// ---------------- PTX helpers ----------------------------------------------
__device__ __forceinline__ uint32_t sptr(const void* p) {
    return (uint32_t)__cvta_generic_to_shared(p);
}
#define LDSM4(R0, R1, R2, R3, ADDR) \
    asm volatile("ldmatrix.sync.aligned.m8n8.x4.shared.b16 {%0,%1,%2,%3}, [%4];" \
                 : "=r"(R0), "=r"(R1), "=r"(R2), "=r"(R3) : "r"(ADDR))
#define LDSM4T(R0, R1, R2, R3, ADDR) \
    asm volatile("ldmatrix.sync.aligned.m8n8.x4.trans.shared.b16 {%0,%1,%2,%3}, [%4];" \
                 : "=r"(R0), "=r"(R1), "=r"(R2), "=r"(R3) : "r"(ADDR))
#define MMA16816(Cv, Ar, Bb0, Bb1) \
    asm volatile("mma.sync.aligned.m16n8k16.row.col.f32.f16.f16.f32 " \
                 "{%0,%1,%2,%3},{%4,%5,%6,%7},{%8,%9},{%0,%1,%2,%3};" \
                 : "+f"(Cv[0]), "+f"(Cv[1]), "+f"(Cv[2]), "+f"(Cv[3]) \
                 : "r"(Ar[0]), "r"(Ar[1]), "r"(Ar[2]), "r"(Ar[3]), \
                   "r"(Bb0), "r"(Bb1))
#define CP16(DST, SRC) \
    asm volatile("cp.async.cg.shared.global [%0], [%1], 16;" :: "r"(DST), "l"(SRC))
#define CPCOMMIT() asm volatile("cp.async.commit_group;")
#define CPWAIT1()  asm volatile("cp.async.wait_group 1;")
#define CPWAIT2()  asm volatile("cp.async.wait_group 2;")
#define CPWAITALL() asm volatile("cp.async.wait_all;")

// ---------------- weight split: fp32 -> fp16 hi/lo (same [K][N] layout) ---
__global__ void split_kernel(const float* __restrict__ in,
                             __half* __restrict__ hi,
                             __half* __restrict__ lo, int n) {
    int i = (blockIdx.x * 256 + threadIdx.x) * 4;
    if (i >= n) return;
    float4 v = *(const float4*)(in + i);
    uint32_t h01, l01, h23, l23;
    split2uh(v.x, v.y, h01, l01);
    split2uh(v.z, v.w, h23, l23);
    *(uint32_t*)(hi + i)     = h01;
    *(uint32_t*)(hi + i + 2) = h23;
    *(uint32_t*)(lo + i)     = l01;
    *(uint32_t*)(lo + i + 2) = l23;
}

// ---------------- embedding + positional encoding (+ fp16 out) ------------
__global__ void embed_kernel(const int* __restrict__ tokens,
                             const float* __restrict__ emb,
                             float* __restrict__ x,
                             __half* __restrict__ xh) {
    int row = blockIdx.x;
    int s   = row & (S_ - 1);
    int tok = tokens[row];
    const float* erow = emb + (size_t)tok * D_;
    size_t base = (size_t)row * D_;
    const float kfac = -0.00899447301950812f;   // -ln(10000)/1024
    #pragma unroll
    for (int j = 0; j < 4; ++j) {
        int c = threadIdx.x + j * 256;
        float freq = expf(kfac * (float)(c & ~1));
        float arg  = (float)s * freq;
        float pe   = (c & 1) ? cosf(arg) : sinf(arg);
        float v = erow[c] + pe;
        x[base + c] = v;
        xh[base + c] = __float2half_rn(v);
    }
}

// ===================== fp16 2-term tensor-core GEMM ========================
// C = Ah[MxK] @ (Bh+Bl)[KxN] + bias.  A single fp16 plane; B hi/lo.
// 512 threads = 16 warps (4x4), warp tile 32x32, block tile 128x128x64.
// 3-stage cp.async pipeline. A smem [128][72], B smem [64][136] per plane.
#define AST2 72
#define BST 136
#define A_EL (128 * AST2)                 // 9216
#define B_EL (64 * BST)                   // 8704
#define STG_E (A_EL + 2 * B_EL)           // 26624 elems
#define GEMM_SMEM (3 * STG_E * 2)         // 159744 bytes

#define ISSUE_STAGE(SIDX, K0) do {                                           \
    __half* _b = sm + (SIDX) * STG_E;                                        \
    _Pragma("unroll")                                                        \
    for (int _i = 0; _i < 2; ++_i) {                                         \
        int _id = tid + _i * 512;                                            \
        int _r = _id >> 3, _c = (_id & 7) << 3;                              \
        CP16(sptr(_b + _r * AST2 + _c), gA + (size_t)_r * K + (K0) + _c);    \
    }                                                                        \
    _Pragma("unroll")                                                        \
    for (int _i = 0; _i < 2; ++_i) {                                         \
        int _id = tid + _i * 512;                                            \
        int _r = _id >> 4, _c = (_id & 15) << 3;                             \
        uint32_t _d = sptr(_b + A_EL + _r * BST + _c);                       \
        CP16(_d,            gBh + (size_t)((K0) + _r) * N + _c);             \
        CP16(_d + B_EL * 2, gBl + (size_t)((K0) + _r) * N + _c);             \
    }                                                                        \
} while (0)

// mode 0: fp32 C. mode 1: relu + fp16 hi only. mode 2: fp16 hi + lo.
__global__ void __launch_bounds__(512, 1)
mma_gemm(const __half* __restrict__ Ah,
         const __half* __restrict__ Bh, const __half* __restrict__ Bl,
         const float* __restrict__ bias,
         float* __restrict__ C,
         __half* __restrict__ Ch, __half* __restrict__ Cl,
         int N, int K, int mode) {
    extern __shared__ __half sm[];

    const int tid = threadIdx.x;
    const int wid = tid >> 5, lane = tid & 31;
    const int wm = (wid >> 2) << 5;
    const int wn = (wid & 3) << 5;
    const int bx = blockIdx.x, by = blockIdx.y;

    const __half* gA  = Ah + (size_t)(by * 128) * K;
    const __half* gBh = Bh + bx * 128;
    const __half* gBl = Bl + bx * 128;

    float acc[2][4][4];
    #pragma unroll
    for (int i = 0; i < 2; ++i)
        #pragma unroll
        for (int j = 0; j < 4; ++j)
            #pragma unroll
            for (int t = 0; t < 4; ++t) acc[i][j][t] = 0.f;

    ISSUE_STAGE(0, 0);  CPCOMMIT();
    ISSUE_STAGE(1, 64); CPCOMMIT();

    const int ntile = K >> 6;
    int buf = 0;
    for (int it = 0; it < ntile; ++it) {
        CPWAIT1();
        __syncthreads();

        int nk = (it + 2) << 6;
        if (nk < K) {
            int s = (buf + 2) % 3;
            ISSUE_STAGE(s, nk);
        }
        CPCOMMIT();

        const __half* ah = sm + buf * STG_E;
        const __half* bh = ah + A_EL;
        const __half* bl = bh + B_EL;

        #pragma unroll
        for (int kc = 0; kc < 4; ++kc) {
            uint32_t a_f[2][4], b_h[4][2], b_l[4][2];
            int af = lane & 15;
            int ac = kc * 16 + ((lane >> 4) << 3);
            #pragma unroll
            for (int mt = 0; mt < 2; ++mt) {
                uint32_t ad = sptr(ah + (wm + mt * 16 + af) * AST2 + ac);
                LDSM4(a_f[mt][0], a_f[mt][1], a_f[mt][2], a_f[mt][3], ad);
            }
            int bkr = kc * 16 + (lane & 15);
            #pragma unroll
            for (int p = 0; p < 2; ++p) {
                int bnc = wn + p * 16 + ((lane >> 4) << 3);
                uint32_t bd = sptr(bh + bkr * BST + bnc);
                LDSM4T(b_h[2*p][0], b_h[2*p][1], b_h[2*p+1][0], b_h[2*p+1][1], bd);
                bd = sptr(bl + bkr * BST + bnc);
                LDSM4T(b_l[2*p][0], b_l[2*p][1], b_l[2*p+1][0], b_l[2*p+1][1], bd);
            }
            #pragma unroll
            for (int mt = 0; mt < 2; ++mt)
                #pragma unroll
                for (int nt = 0; nt < 4; ++nt) {
                    MMA16816(acc[mt][nt], a_f[mt], b_h[nt][0], b_h[nt][1]);
                    MMA16816(acc[mt][nt], a_f[mt], b_l[nt][0], b_l[nt][1]);
                }
        }
        buf = (buf + 1) % 3;
        __syncthreads();
    }

    #pragma unroll
    for (int mt = 0; mt < 2; ++mt) {
        int row = by * 128 + wm + mt * 16 + (lane >> 2);
        #pragma unroll
        for (int nt = 0; nt < 4; ++nt) {
            int col = bx * 128 + wn + nt * 8 + ((lane & 3) << 1);
            float2 bv = *(const float2*)(bias + col);
            float v0 = acc[mt][nt][0] + bv.x;
            float v1 = acc[mt][nt][1] + bv.y;
            float v2 = acc[mt][nt][2] + bv.x;
            float v3 = acc[mt][nt][3] + bv.y;
            if (mode == 0) {
                float2 o0 = {v0, v1}, o1 = {v2, v3};
                *(float2*)(C + (size_t)row * N + col)       = o0;
                *(float2*)(C + (size_t)(row + 8) * N + col) = o1;
            } else if (mode == 1) {
                v0 = fmaxf(v0, 0.f); v1 = fmaxf(v1, 0.f);
                v2 = fmaxf(v2, 0.f); v3 = fmaxf(v3, 0.f);
                *(uint32_t*)(Ch + (size_t)row * N + col)       = packh2(v0, v1);
                *(uint32_t*)(Ch + (size_t)(row + 8) * N + col) = packh2(v2, v3);
            } else {
                uint32_t h01, l01, h23, l23;
                split2uh(v0, v1, h01, l01);
                split2uh(v2, v3, h23, l23);
                *(uint32_t*)(Ch + (size_t)row * N + col)       = h01;
                *(uint32_t*)(Ch + (size_t)(row + 8) * N + col) = h23;
                *(uint32_t*)(Cl + (size_t)row * N + col)       = l01;
                *(uint32_t*)(Cl + (size_t)(row + 8) * N + col) = l23;
            }
        }
    }
}

// ===================== tensor-core causal flash attention ==================
// 128 threads (4 warps), 64 queries of one (b,h), 64-key tiles, double-buffered.
// 2-term fp16: S = Qh(Kh+Kl)^T,  O += Ph(Vh+Vl).
#define APAD 72
#define AQBUF 4608                    // 64*72
#define AKV0 AQBUF                    // Q hi only
#define AKVSTRIDE (4 * AQBUF)         // kh,kl,vh,vl per stage
#define ATT_SMEM ((AQBUF + 2 * AKVSTRIDE) * 2)   // 82944 bytes

__global__ void __launch_bounds__(128, 2)
attn_mma(const __half* __restrict__ qh,
         const __half* __restrict__ ql,
         __half* __restrict__ oh) {
    extern __shared__ __half sm[];
    const int tid = threadIdx.x;
    const int wid = tid >> 5, lane = tid & 31;
    const int qb = gridDim.x - 1 - blockIdx.x;
    const int bh = blockIdx.y;
    const int h = bh & (H_ - 1), b = bh >> 4;
    const int wq0 = wid << 4;

    const size_t seqbase = (size_t)(b * S_) * 3072 + h * 64;

    // Q tile (hi only)
    {
        #pragma unroll
        for (int i = 0; i < 4; ++i) {
            int id = tid + i * 128;
            int row = id >> 3, col = (id & 7) << 3;
            size_t src = seqbase + (size_t)(qb * 64 + row) * 3072 + col;
            CP16(sptr(sm + row * APAD + col), qh + src);
        }
        CPCOMMIT();
    }
    #define ISSUE_KV(STG, KT0) do {                                         \
        __half* _kb = sm + AKV0 + (STG) * AKVSTRIDE;                        \
        _Pragma("unroll")                                                   \
        for (int i = 0; i < 4; ++i) {                                       \
            int id = tid + i * 128;                                         \
            int row = id >> 3, col = (id & 7) << 3;                         \
            size_t src = seqbase + (size_t)((KT0) * 64 + row) * 3072 + col; \
            uint32_t dst = sptr(_kb + row * APAD + col);                    \
            CP16(dst,                 qh + src + 1024);                     \
            CP16(dst + AQBUF * 2,     ql + src + 1024);                     \
            CP16(dst + AQBUF * 4,     qh + src + 2048);                     \
            CP16(dst + AQBUF * 6,     ql + src + 2048);                     \
        }                                                                   \
        CPCOMMIT();                                                         \
    } while (0)

    ISSUE_KV(0, 0);
    ISSUE_KV(1, (qb >= 1 ? 1 : 0));

    CPWAIT2();
    __syncthreads();
    uint32_t qf[4][4];
    {
        int af = lane & 15;
        #pragma unroll
        for (int kc = 0; kc < 4; ++kc) {
            int ac = kc * 16 + ((lane >> 4) << 3);
            uint32_t ad = sptr(sm + (wq0 + af) * APAD + ac);
            LDSM4(qf[kc][0], qf[kc][1], qf[kc][2], qf[kc][3], ad);
        }
    }

    float Od[8][4];
    #pragma unroll
    for (int i = 0; i < 8; ++i)
        #pragma unroll
        for (int j = 0; j < 4; ++j) Od[i][j] = 0.f;
    float m_a = -1e30f, m_b = -1e30f, den_a = 0.f, den_b = 0.f;

    int buf = 0;
    const int ntk = qb + 1;
    for (int kt = 0; kt < ntk; ++kt) {
        CPWAIT1();
        __syncthreads();

        const __half* kh = sm + AKV0 + buf * AKVSTRIDE;
        const __half* kl = kh + AQBUF;
        const __half* vh = kh + 2 * AQBUF;
        const __half* vl = kh + 3 * AQBUF;

        float sreg[8][4];
        #pragma unroll
        for (int i = 0; i < 8; ++i)
            #pragma unroll
            for (int j = 0; j < 4; ++j) sreg[i][j] = 0.f;

        #pragma unroll
        for (int kc = 0; kc < 4; ++kc) {
            int krow = ((lane >> 4) << 3) + (lane & 7);
            int kcol = kc * 16 + (((lane >> 3) & 1) << 3);
            #pragma unroll
            for (int ng = 0; ng < 4; ++ng) {
                uint32_t bh0, bh1, bh2, bh3, bl0, bl1, bl2, bl3;
                uint32_t ad = sptr(kh + (ng * 16 + krow) * APAD + kcol);
                LDSM4(bh0, bh1, bh2, bh3, ad);
                ad = sptr(kl + (ng * 16 + krow) * APAD + kcol);
                LDSM4(bl0, bl1, bl2, bl3, ad);
                MMA16816(sreg[2*ng],   qf[kc], bh0, bh1);
                MMA16816(sreg[2*ng],   qf[kc], bl0, bl1);
                MMA16816(sreg[2*ng+1], qf[kc], bh2, bh3);
                MMA16816(sreg[2*ng+1], qf[kc], bl2, bl3);
            }
        }

        int ra = wq0 + (lane >> 2);
        int cb = (lane & 3) << 1;
        #pragma unroll
        for (int nt = 0; nt < 8; ++nt) {
            #pragma unroll
            for (int j = 0; j < 4; ++j) {
                float s = sreg[nt][j] * 0.125f;
                if (kt == qb) {
                    int col = nt * 8 + cb + (j & 1);
                    int row = ra + ((j >> 1) << 3);
                    if (col > row) s = -1e30f;
                }
                sreg[nt][j] = s;
            }
        }
        float mxa = -1e30f, mxb = -1e30f;
        #pragma unroll
        for (int nt = 0; nt < 8; ++nt) {
            mxa = fmaxf(mxa, fmaxf(sreg[nt][0], sreg[nt][1]));
            mxb = fmaxf(mxb, fmaxf(sreg[nt][2], sreg[nt][3]));
        }
        mxa = fmaxf(mxa, __shfl_xor_sync(0xffffffffu, mxa, 1));
        mxa = fmaxf(mxa, __shfl_xor_sync(0xffffffffu, mxa, 2));
        mxb = fmaxf(mxb, __shfl_xor_sync(0xffffffffu, mxb, 1));
        mxb = fmaxf(mxb, __shfl_xor_sync(0xffffffffu, mxb, 2));
        float mna = fmaxf(m_a, mxa), mnb = fmaxf(m_b, mxb);
        float ca = __expf(m_a - mna), cbr = __expf(m_b - mnb);
        m_a = mna; m_b = mnb;
        float sa = 0.f, sb = 0.f;
        #pragma unroll
        for (int nt = 0; nt < 8; ++nt) {
            float p0 = __expf(sreg[nt][0] - mna);
            float p1 = __expf(sreg[nt][1] - mna);
            float p2 = __expf(sreg[nt][2] - mnb);
            float p3 = __expf(sreg[nt][3] - mnb);
            sreg[nt][0] = p0; sreg[nt][1] = p1; sreg[nt][2] = p2; sreg[nt][3] = p3;
            sa += p0 + p1; sb += p2 + p3;
        }
        sa += __shfl_xor_sync(0xffffffffu, sa, 1);
        sa += __shfl_xor_sync(0xffffffffu, sa, 2);
        sb += __shfl_xor_sync(0xffffffffu, sb, 1);
        sb += __shfl_xor_sync(0xffffffffu, sb, 2);
        den_a = den_a * ca + sa;
        den_b = den_b * cbr + sb;
        #pragma unroll
        for (int nt = 0; nt < 8; ++nt) {
            Od[nt][0] *= ca;  Od[nt][1] *= ca;
            Od[nt][2] *= cbr; Od[nt][3] *= cbr;
        }

        // O += P @ (Vh + Vl), P fp16-rounded in registers
        #pragma unroll
        for (int kc2 = 0; kc2 < 4; ++kc2) {
            uint32_t ph[4];
            ph[0] = packh2(sreg[2*kc2][0],   sreg[2*kc2][1]);
            ph[1] = packh2(sreg[2*kc2][2],   sreg[2*kc2][3]);
            ph[2] = packh2(sreg[2*kc2+1][0], sreg[2*kc2+1][1]);
            ph[3] = packh2(sreg[2*kc2+1][2], sreg[2*kc2+1][3]);
            int vr = kc2 * 16 + (lane & 15);
            #pragma unroll
            for (int ng = 0; ng < 4; ++ng) {
                int vc = ng * 16 + ((lane >> 4) << 3);
                uint32_t vh0, vh1, vh2, vh3, vl0, vl1, vl2, vl3;
                uint32_t ad = sptr(vh + vr * APAD + vc);
                LDSM4T(vh0, vh1, vh2, vh3, ad);
                ad = sptr(vl + vr * APAD + vc);
                LDSM4T(vl0, vl1, vl2, vl3, ad);
                MMA16816(Od[2*ng],   ph, vh0, vh1);
                MMA16816(Od[2*ng],   ph, vl0, vl1);
                MMA16816(Od[2*ng+1], ph, vh2, vh3);
                MMA16816(Od[2*ng+1], ph, vl2, vl3);
            }
        }
        __syncthreads();
        if (kt + 2 <= qb) ISSUE_KV(buf, kt + 2);
        CPCOMMIT();
        buf ^= 1;
    }

    CPWAITALL();

    float inva = 1.f / den_a, invb = 1.f / den_b;
    int gq_a = qb * 64 + wq0 + (lane >> 2);
    size_t oa = (size_t)(b * S_ + gq_a) * D_ + h * 64 + ((lane & 3) << 1);
    size_t ob = oa + (size_t)8 * D_;
    #pragma unroll
    for (int nt = 0; nt < 8; ++nt) {
        *(uint32_t*)(oh + oa + nt * 8) = packh2(Od[nt][0] * inva, Od[nt][1] * inva);
        *(uint32_t*)(oh + ob + nt * 8) = packh2(Od[nt][2] * invb, Od[nt][3] * invb);
    }
}

// ---------------- fused residual add + LayerNorm (+ fp16 out) -------------
__global__ void add_ln_kernel(float* __restrict__ x,
                              const float* __restrict__ r,
                              const float* __restrict__ g,
                              const float* __restrict__ bb,
                              __half* __restrict__ xh) {
    int row = blockIdx.x;
    int tid = threadIdx.x;
    size_t base = (size_t)row * D_;
    float v[4];
    float s = 0.f;
    #pragma unroll
    for (int j = 0; j < 4; ++j) {
        int c = tid + j * 256;
        v[j] = x[base + c] + r[base + c];
        s += v[j];
    }
    __shared__ float sh[8];
    #pragma unroll
    for (int off = 16; off > 0; off >>= 1) s += __shfl_xor_sync(0xffffffffu, s, off);
    if ((tid & 31) == 0) sh[tid >> 5] = s;
    __syncthreads();
    if (tid < 32) {
        float t = (tid < 8) ? sh[tid] : 0.f;
        #pragma unroll
        for (int off = 4; off > 0; off >>= 1) t += __shfl_xor_sync(0xffffffffu, t, off);
        if (tid == 0) sh[0] = t;
    }
    __syncthreads();
    float mu = sh[0] * (1.f / 1024.f);
    __syncthreads();
    float ss = 0.f;
    #pragma unroll
    for (int j = 0; j < 4; ++j) { float d = v[j] - mu; ss += d * d; }
    #pragma unroll
    for (int off = 16; off > 0; off >>= 1) ss += __shfl_xor_sync(0xffffffffu, ss, off);
    if ((tid & 31) == 0) sh[tid >> 5] = ss;
    __syncthreads();
    if (tid < 32) {
        float t = (tid < 8) ? sh[tid] : 0.f;
        #pragma unroll
        for (int off = 4; off > 0; off >>= 1) t += __shfl_xor_sync(0xffffffffu, t, off);
        if (tid == 0) sh[0] = t;
    }
    __syncthreads();
    float var = sh[0] * (1.f / 1024.f);
    float rstd = rsqrtf(var + 1e-5f);
    #pragma unroll
    for (int j = 0; j < 4; ++j) {
        int c = tid + j * 256;
        float y = (v[j] - mu) * rstd * g[c] + bb[c];
        x[base + c] = y;
        xh[base + c] = __float2half_rn(y);
    }
}

// ---------------------------------------------------------------------------
extern "C" void kernel_launch(void* const* d_in, const int* in_sizes, int n_in,
                              void* d_out, int out_size) {
    const int*   tokens = (const int*)  d_in[0];
    const float* emb    = (const float*)d_in[1];
    const float* qkv_w  = (const float*)d_in[2];
    const float* qkv_b  = (const float*)d_in[3];
    const float* out_w  = (const float*)d_in[4];
    const float* out_b  = (const float*)d_in[5];
    const float* fc1_w  = (const float*)d_in[6];
    const float* fc1_b  = (const float*)d_in[7];
    const float* fc2_w  = (const float*)d_in[8];
    const float* fc2_b  = (const float*)d_in[9];
    const float* ln1_g  = (const float*)d_in[10];
    const float* ln1_b  = (const float*)d_in[11];
    const float* ln2_g  = (const float*)d_in[12];
    const float* ln2_b  = (const float*)d_in[13];
    const float* w_out  = (const float*)d_in[14];
    const float* b_out  = (const float*)d_in[15];
    float* out = (float*)d_out;

    float *x, *tmp, *o;
    __half *xh, *oh, *hh, *hl, *wh, *wl;
    cudaGetSymbolAddress((void**)&x,   g_x);
    cudaGetSymbolAddress((void**)&tmp, g_tmp);
    cudaGetSymbolAddress((void**)&o,   g_o);
    cudaGetSymbolAddress((void**)&xh,  g_xh);
    cudaGetSymbolAddress((void**)&oh,  g_oh);
    cudaGetSymbolAddress((void**)&hh,  g_hh);
    cudaGetSymbolAddress((void**)&hl,  g_hl);
    cudaGetSymbolAddress((void**)&wh,  g_wh);
    cudaGetSymbolAddress((void**)&wl,  g_wl);

    cudaFuncSetAttribute(mma_gemm, cudaFuncAttributeMaxDynamicSharedMemorySize,
                         GEMM_SMEM);
    cudaFuncSetAttribute(attn_mma, cudaFuncAttributeMaxDynamicSharedMemorySize,
                         ATT_SMEM);

    embed_kernel<<<TOK_, 256>>>(tokens, emb, x, xh);

    for (int l = 0; l < L_; ++l) {
        // qkv = x @ qkv_w + b -> fp16 hi/lo (mode 2) into hh/hl
        int nqkv = D_ * 3 * D_;
        split_kernel<<<nqkv / 1024, 256>>>(qkv_w + (size_t)l * nqkv, wh, wl, nqkv);
        mma_gemm<<<dim3(3072 / 128, TOK_ / 128), 512, GEMM_SMEM>>>(
            xh, wh, wl, qkv_b + (size_t)l * 3 * D_,
            nullptr, hh, hl, 3 * D_, D_, 2);
        // attention -> oh
        attn_mma<<<dim3(S_ / 64, B_ * H_), 128, ATT_SMEM>>>(hh, hl, oh);
        // out proj -> tmp fp32
        int nout = D_ * D_;
        split_kernel<<<nout / 1024, 256>>>(out_w + (size_t)l * nout, wh, wl, nout);
        mma_gemm<<<dim3(D_ / 128, TOK_ / 128), 512, GEMM_SMEM>>>(
            oh, wh, wl, out_b + (size_t)l * D_,
            tmp, nullptr, nullptr, D_, D_, 0);
        add_ln_kernel<<<TOK_, 256>>>(x, tmp, ln1_g + l * D_, ln1_b + l * D_, xh);
        // fc1 (relu, fp16 hi only)
        int nfc1 = D_ * FF_;
        split_kernel<<<nfc1 / 1024, 256>>>(fc1_w + (size_t)l * nfc1, wh, wl, nfc1);
        mma_gemm<<<dim3(FF_ / 128, TOK_ / 128), 512, GEMM_SMEM>>>(
            xh, wh, wl, fc1_b + (size_t)l * FF_,
            nullptr, hh, nullptr, FF_, D_, 1);
        // fc2
        int nfc2 = FF_ * D_;
        split_kernel<<<nfc2 / 1024, 256>>>(fc2_w + (size_t)l * nfc2, wh, wl, nfc2);
        mma_gemm<<<dim3(D_ / 128, TOK_ / 128), 512, GEMM_SMEM>>>(
            hh, wh, wl, fc2_b + (size_t)l * D_,
            o, nullptr, nullptr, D_, FF_, 0);
        add_ln_kernel<<<TOK_, 256>>>(x, o, ln2_g + l * D_, ln2_b + l * D_, xh);
    }

    // logits
    int nlog = D_ * V_;
    split_kernel<<<nlog / 1024, 256>>>(w_out, wh, wl, nlog);
    mma_gemm<<<dim3(V_ / 128, TOK_ / 128), 512, GEMM_SMEM>>>(
        xh, wh, wl, b_out, out, nullptr, nullptr, V_, D_, 0);
}

// round 9
// speedup vs baseline: 7.0322x; 1.0090x over previous
#include <cuda_runtime.h>
#include <cuda_fp16.h>
#include <math.h>
#include <stdint.h>

#define B_ 2
#define S_ 2048
#define D_ 1024
#define L_ 6
#define H_ 16
#define HD_ 64
#define FF_ 4096
#define V_ 32000
#define TOK_ (B_ * S_)          // 4096 token rows

// ---------------- scratch (static device globals; no allocation) ----------
__device__ float g_x[TOK_ * D_];                 // fp32 residual stream
__device__ float g_tmp[TOK_ * FF_];              // out-proj / fc2 fp32 out
__device__ float g_o[TOK_ * D_];                 // fc2 out (pre-LN2)
__device__ __half g_xh[TOK_ * D_];               // x (fp16 hi plane)
__device__ __half g_oh[TOK_ * D_];               // attention out (hi plane)
__device__ __half g_hh[TOK_ * FF_];              // qkv / ffn hidden hi
__device__ __half g_hl[TOK_ * FF_];              // qkv lo (K/V lo planes)
__device__ __half g_wh[(size_t)D_ * V_];         // weight hi, layout [K][N]
__device__ __half g_wl[(size_t)D_ * V_];         // weight lo

__device__ __forceinline__ void split1h(float x, __half& h, __half& l) {
    h = __float2half_rn(x);
    l = __float2half_rn(x - __half2float(h));
}
__device__ __forceinline__ uint32_t packh2(float x, float y) {
    __half2 t = __floats2half2_rn(x, y);
    return *reinterpret_cast<uint32_t*>(&t);
}
__device__ __forceinline__ void split2uh(float x, float y, uint32_t& h, uint32_t& l) {
    __half hx, lx, hy, ly;
    split1h(x, hx, lx); split1h(y, hy, ly);
    __half2 th{hx, hy}, tl{lx, ly};
    h = *reinterpret_cast<uint32_t*>(&th);
    l = *reinterpret_cast<uint32_t*>(&tl);
}

// ---------------- PTX helpers ----------------------------------------------
__device__ __forceinline__ uint32_t sptr(const void* p) {
    return (uint32_t)__cvta_generic_to_shared(p);
}
#define LDSM4(R0, R1, R2, R3, ADDR) \
    asm volatile("ldmatrix.sync.aligned.m8n8.x4.shared.b16 {%0,%1,%2,%3}, [%4];" \
                 : "=r"(R0), "=r"(R1), "=r"(R2), "=r"(R3) : "r"(ADDR))
#define LDSM4T(R0, R1, R2, R3, ADDR) \
    asm volatile("ldmatrix.sync.aligned.m8n8.x4.trans.shared.b16 {%0,%1,%2,%3}, [%4];" \
                 : "=r"(R0), "=r"(R1), "=r"(R2), "=r"(R3) : "r"(ADDR))
#define MMA16816(Cv, Ar, Bb0, Bb1) \
    asm volatile("mma.sync.aligned.m16n8k16.row.col.f32.f16.f16.f32 " \
                 "{%0,%1,%2,%3},{%4,%5,%6,%7},{%8,%9},{%0,%1,%2,%3};" \
                 : "+f"(Cv[0]), "+f"(Cv[1]), "+f"(Cv[2]), "+f"(Cv[3]) \
                 : "r"(Ar[0]), "r"(Ar[1]), "r"(Ar[2]), "r"(Ar[3]), \
                   "r"(Bb0), "r"(Bb1))
#define CP16(DST, SRC) \
    asm volatile("cp.async.cg.shared.global [%0], [%1], 16;" :: "r"(DST), "l"(SRC))
#define CPCOMMIT() asm volatile("cp.async.commit_group;")
#define CPWAIT1()  asm volatile("cp.async.wait_group 1;")
#define CPWAIT2()  asm volatile("cp.async.wait_group 2;")
#define CPWAITALL() asm volatile("cp.async.wait_all;")

// ---------------- weight split: fp32 -> fp16 hi/lo (same [K][N] layout) ---
__global__ void split_kernel(const float* __restrict__ in,
                             __half* __restrict__ hi,
                             __half* __restrict__ lo, int n) {
    int i = (blockIdx.x * 256 + threadIdx.x) * 4;
    if (i >= n) return;
    float4 v = *(const float4*)(in + i);
    uint32_t h01, l01, h23, l23;
    split2uh(v.x, v.y, h01, l01);
    split2uh(v.z, v.w, h23, l23);
    *(uint32_t*)(hi + i)     = h01;
    *(uint32_t*)(hi + i + 2) = h23;
    *(uint32_t*)(lo + i)     = l01;
    *(uint32_t*)(lo + i + 2) = l23;
}

// ---------------- embedding + positional encoding (+ fp16 out) ------------
__global__ void embed_kernel(const int* __restrict__ tokens,
                             const float* __restrict__ emb,
                             float* __restrict__ x,
                             __half* __restrict__ xh) {
    int row = blockIdx.x;
    int s   = row & (S_ - 1);
    int tok = tokens[row];
    const float* erow = emb + (size_t)tok * D_;
    size_t base = (size_t)row * D_;
    const float kfac = -0.00899447301950812f;   // -ln(10000)/1024
    #pragma unroll
    for (int j = 0; j < 4; ++j) {
        int c = threadIdx.x + j * 256;
        float freq = expf(kfac * (float)(c & ~1));
        float arg  = (float)s * freq;
        float pe   = (c & 1) ? cosf(arg) : sinf(arg);
        float v = erow[c] + pe;
        x[base + c] = v;
        xh[base + c] = __float2half_rn(v);
    }
}

// ===================== fp16 2-term tensor-core GEMM ========================
// C = Ah[MxK] @ (Bh+Bl)[KxN] + bias.  A single fp16 plane; B hi/lo.
// 512 threads = 16 warps (4x4), warp tile 32x32, block tile 128x128x64.
// 4-stage cp.async pipeline, one __syncthreads per k-chunk.
#define AST2 72
#define BST 136
#define A_EL (128 * AST2)                 // 9216
#define B_EL (64 * BST)                   // 8704
#define STG_E (A_EL + 2 * B_EL)           // 26624 elems
#define GEMM_SMEM (4 * STG_E * 2)         // 212992 bytes

#define ISSUE_STAGE(SIDX, K0) do {                                           \
    __half* _b = sm + (SIDX) * STG_E;                                        \
    _Pragma("unroll")                                                        \
    for (int _i = 0; _i < 2; ++_i) {                                         \
        int _id = tid + _i * 512;                                            \
        int _r = _id >> 3, _c = (_id & 7) << 3;                              \
        CP16(sptr(_b + _r * AST2 + _c), gA + (size_t)_r * K + (K0) + _c);    \
    }                                                                        \
    _Pragma("unroll")                                                        \
    for (int _i = 0; _i < 2; ++_i) {                                         \
        int _id = tid + _i * 512;                                            \
        int _r = _id >> 4, _c = (_id & 15) << 3;                             \
        uint32_t _d = sptr(_b + A_EL + _r * BST + _c);                       \
        CP16(_d,            gBh + (size_t)((K0) + _r) * N + _c);             \
        CP16(_d + B_EL * 2, gBl + (size_t)((K0) + _r) * N + _c);             \
    }                                                                        \
} while (0)

// mode 0: fp32 C. mode 1: relu + fp16 hi only. mode 2: fp16 hi + lo.
__global__ void __launch_bounds__(512, 1)
mma_gemm(const __half* __restrict__ Ah,
         const __half* __restrict__ Bh, const __half* __restrict__ Bl,
         const float* __restrict__ bias,
         float* __restrict__ C,
         __half* __restrict__ Ch, __half* __restrict__ Cl,
         int N, int K, int mode) {
    extern __shared__ __half sm[];

    const int tid = threadIdx.x;
    const int wid = tid >> 5, lane = tid & 31;
    const int wm = (wid >> 2) << 5;
    const int wn = (wid & 3) << 5;
    const int bx = blockIdx.x, by = blockIdx.y;

    const __half* gA  = Ah + (size_t)(by * 128) * K;
    const __half* gBh = Bh + bx * 128;
    const __half* gBl = Bl + bx * 128;

    float acc[2][4][4];
    #pragma unroll
    for (int i = 0; i < 2; ++i)
        #pragma unroll
        for (int j = 0; j < 4; ++j)
            #pragma unroll
            for (int t = 0; t < 4; ++t) acc[i][j][t] = 0.f;

    ISSUE_STAGE(0, 0);   CPCOMMIT();
    ISSUE_STAGE(1, 64);  CPCOMMIT();
    ISSUE_STAGE(2, 128); CPCOMMIT();

    const int ntile = K >> 6;
    for (int it = 0; it < ntile; ++it) {
        CPWAIT2();
        __syncthreads();

        int nk = (it + 3) << 6;
        if (nk < K) {
            ISSUE_STAGE((it + 3) & 3, nk);
        }
        CPCOMMIT();

        const __half* ah = sm + (it & 3) * STG_E;
        const __half* bh = ah + A_EL;
        const __half* bl = bh + B_EL;

        #pragma unroll
        for (int kc = 0; kc < 4; ++kc) {
            uint32_t a_f[2][4], b_h[4][2], b_l[4][2];
            int af = lane & 15;
            int ac = kc * 16 + ((lane >> 4) << 3);
            #pragma unroll
            for (int mt = 0; mt < 2; ++mt) {
                uint32_t ad = sptr(ah + (wm + mt * 16 + af) * AST2 + ac);
                LDSM4(a_f[mt][0], a_f[mt][1], a_f[mt][2], a_f[mt][3], ad);
            }
            int bkr = kc * 16 + (lane & 15);
            #pragma unroll
            for (int p = 0; p < 2; ++p) {
                int bnc = wn + p * 16 + ((lane >> 4) << 3);
                uint32_t bd = sptr(bh + bkr * BST + bnc);
                LDSM4T(b_h[2*p][0], b_h[2*p][1], b_h[2*p+1][0], b_h[2*p+1][1], bd);
                bd = sptr(bl + bkr * BST + bnc);
                LDSM4T(b_l[2*p][0], b_l[2*p][1], b_l[2*p+1][0], b_l[2*p+1][1], bd);
            }
            #pragma unroll
            for (int mt = 0; mt < 2; ++mt)
                #pragma unroll
                for (int nt = 0; nt < 4; ++nt) {
                    MMA16816(acc[mt][nt], a_f[mt], b_h[nt][0], b_h[nt][1]);
                    MMA16816(acc[mt][nt], a_f[mt], b_l[nt][0], b_l[nt][1]);
                }
        }
        // no trailing sync: stage (it&3) is rewritten only in iteration it+1,
        // after that iteration's top-of-loop __syncthreads.
    }

    #pragma unroll
    for (int mt = 0; mt < 2; ++mt) {
        int row = by * 128 + wm + mt * 16 + (lane >> 2);
        #pragma unroll
        for (int nt = 0; nt < 4; ++nt) {
            int col = bx * 128 + wn + nt * 8 + ((lane & 3) << 1);
            float2 bv = *(const float2*)(bias + col);
            float v0 = acc[mt][nt][0] + bv.x;
            float v1 = acc[mt][nt][1] + bv.y;
            float v2 = acc[mt][nt][2] + bv.x;
            float v3 = acc[mt][nt][3] + bv.y;
            if (mode == 0) {
                float2 o0 = {v0, v1}, o1 = {v2, v3};
                *(float2*)(C + (size_t)row * N + col)       = o0;
                *(float2*)(C + (size_t)(row + 8) * N + col) = o1;
            } else if (mode == 1) {
                v0 = fmaxf(v0, 0.f); v1 = fmaxf(v1, 0.f);
                v2 = fmaxf(v2, 0.f); v3 = fmaxf(v3, 0.f);
                *(uint32_t*)(Ch + (size_t)row * N + col)       = packh2(v0, v1);
                *(uint32_t*)(Ch + (size_t)(row + 8) * N + col) = packh2(v2, v3);
            } else {
                uint32_t h01, l01, h23, l23;
                split2uh(v0, v1, h01, l01);
                split2uh(v2, v3, h23, l23);
                *(uint32_t*)(Ch + (size_t)row * N + col)       = h01;
                *(uint32_t*)(Ch + (size_t)(row + 8) * N + col) = h23;
                *(uint32_t*)(Cl + (size_t)row * N + col)       = l01;
                *(uint32_t*)(Cl + (size_t)(row + 8) * N + col) = l23;
            }
        }
    }
}

// ===================== tensor-core causal flash attention ==================
// 256 threads (8 warps), 128 queries of one (b,h), 64-key tiles, double-buffered.
// 2-term fp16: S = Qh(Kh+Kl)^T,  O += Ph(Vh+Vl).
#define APAD 72
#define KVPL 4608                     // 64*72 elems per K/V plane
#define AQ_EL (128 * APAD)            // 9216 elems (Q hi, 128 rows)
#define AKV0 AQ_EL
#define AKVSTRIDE (4 * KVPL)          // kh,kl,vh,vl per stage
#define ATT_SMEM ((AQ_EL + 2 * AKVSTRIDE) * 2)   // 92160 bytes

__global__ void __launch_bounds__(256, 2)
attn_mma(const __half* __restrict__ qh,
         const __half* __restrict__ ql,
         __half* __restrict__ oh) {
    extern __shared__ __half sm[];
    const int tid = threadIdx.x;
    const int wid = tid >> 5, lane = tid & 31;
    const int qb = gridDim.x - 1 - blockIdx.x;     // 0..15, heavy first
    const int bh = blockIdx.y;
    const int h = bh & (H_ - 1), b = bh >> 4;
    const int wq0 = wid << 4;                      // 0..112

    const size_t seqbase = (size_t)(b * S_) * 3072 + h * 64;

    // Q tile: 128 rows, hi plane only
    {
        #pragma unroll
        for (int i = 0; i < 4; ++i) {
            int id = tid + i * 256;
            int row = id >> 3, col = (id & 7) << 3;
            size_t src = seqbase + (size_t)(qb * 128 + row) * 3072 + col;
            CP16(sptr(sm + row * APAD + col), qh + src);
        }
        CPCOMMIT();
    }
    #define ISSUE_KV(STG, KT0) do {                                         \
        __half* _kb = sm + AKV0 + (STG) * AKVSTRIDE;                        \
        _Pragma("unroll")                                                   \
        for (int i = 0; i < 2; ++i) {                                       \
            int id = tid + i * 256;                                         \
            int row = id >> 3, col = (id & 7) << 3;                         \
            size_t src = seqbase + (size_t)((KT0) * 64 + row) * 3072 + col; \
            uint32_t dst = sptr(_kb + row * APAD + col);                    \
            CP16(dst,              qh + src + 1024);                        \
            CP16(dst + KVPL * 2,   ql + src + 1024);                        \
            CP16(dst + KVPL * 4,   qh + src + 2048);                        \
            CP16(dst + KVPL * 6,   ql + src + 2048);                        \
        }                                                                   \
        CPCOMMIT();                                                         \
    } while (0)

    ISSUE_KV(0, 0);
    ISSUE_KV(1, 1);

    CPWAIT2();
    __syncthreads();
    uint32_t qf[4][4];
    {
        int af = lane & 15;
        #pragma unroll
        for (int kc = 0; kc < 4; ++kc) {
            int ac = kc * 16 + ((lane >> 4) << 3);
            uint32_t ad = sptr(sm + (wq0 + af) * APAD + ac);
            LDSM4(qf[kc][0], qf[kc][1], qf[kc][2], qf[kc][3], ad);
        }
    }

    float Od[8][4];
    #pragma unroll
    for (int i = 0; i < 8; ++i)
        #pragma unroll
        for (int j = 0; j < 4; ++j) Od[i][j] = 0.f;
    float m_a = -1e30f, m_b = -1e30f, den_a = 0.f, den_b = 0.f;

    int buf = 0;
    const int ntk = 2 * qb + 2;
    for (int kt = 0; kt < ntk; ++kt) {
        CPWAIT1();
        __syncthreads();

        const __half* kh = sm + AKV0 + buf * AKVSTRIDE;
        const __half* kl = kh + KVPL;
        const __half* vh = kh + 2 * KVPL;
        const __half* vl = kh + 3 * KVPL;

        float sreg[8][4];
        #pragma unroll
        for (int i = 0; i < 8; ++i)
            #pragma unroll
            for (int j = 0; j < 4; ++j) sreg[i][j] = 0.f;

        #pragma unroll
        for (int kc = 0; kc < 4; ++kc) {
            int krow = ((lane >> 4) << 3) + (lane & 7);
            int kcol = kc * 16 + (((lane >> 3) & 1) << 3);
            #pragma unroll
            for (int ng = 0; ng < 4; ++ng) {
                uint32_t bh0, bh1, bh2, bh3, bl0, bl1, bl2, bl3;
                uint32_t ad = sptr(kh + (ng * 16 + krow) * APAD + kcol);
                LDSM4(bh0, bh1, bh2, bh3, ad);
                ad = sptr(kl + (ng * 16 + krow) * APAD + kcol);
                LDSM4(bl0, bl1, bl2, bl3, ad);
                MMA16816(sreg[2*ng],   qf[kc], bh0, bh1);
                MMA16816(sreg[2*ng],   qf[kc], bl0, bl1);
                MMA16816(sreg[2*ng+1], qf[kc], bh2, bh3);
                MMA16816(sreg[2*ng+1], qf[kc], bl2, bl3);
            }
        }

        int ra = wq0 + (lane >> 2);       // query row in 0..127
        int cb = (lane & 3) << 1;
        #pragma unroll
        for (int nt = 0; nt < 8; ++nt) {
            #pragma unroll
            for (int j = 0; j < 4; ++j) {
                float s = sreg[nt][j] * 0.125f;
                if (kt >= 2 * qb) {
                    int col = ((kt - 2 * qb) << 6) + nt * 8 + cb + (j & 1);
                    int row = ra + ((j >> 1) << 3);
                    if (col > row) s = -1e30f;
                }
                sreg[nt][j] = s;
            }
        }
        float mxa = -1e30f, mxb = -1e30f;
        #pragma unroll
        for (int nt = 0; nt < 8; ++nt) {
            mxa = fmaxf(mxa, fmaxf(sreg[nt][0], sreg[nt][1]));
            mxb = fmaxf(mxb, fmaxf(sreg[nt][2], sreg[nt][3]));
        }
        mxa = fmaxf(mxa, __shfl_xor_sync(0xffffffffu, mxa, 1));
        mxa = fmaxf(mxa, __shfl_xor_sync(0xffffffffu, mxa, 2));
        mxb = fmaxf(mxb, __shfl_xor_sync(0xffffffffu, mxb, 1));
        mxb = fmaxf(mxb, __shfl_xor_sync(0xffffffffu, mxb, 2));
        float mna = fmaxf(m_a, mxa), mnb = fmaxf(m_b, mxb);
        float ca = __expf(m_a - mna), cbr = __expf(m_b - mnb);
        m_a = mna; m_b = mnb;
        float sa = 0.f, sb = 0.f;
        #pragma unroll
        for (int nt = 0; nt < 8; ++nt) {
            float p0 = __expf(sreg[nt][0] - mna);
            float p1 = __expf(sreg[nt][1] - mna);
            float p2 = __expf(sreg[nt][2] - mnb);
            float p3 = __expf(sreg[nt][3] - mnb);
            sreg[nt][0] = p0; sreg[nt][1] = p1; sreg[nt][2] = p2; sreg[nt][3] = p3;
            sa += p0 + p1; sb += p2 + p3;
        }
        sa += __shfl_xor_sync(0xffffffffu, sa, 1);
        sa += __shfl_xor_sync(0xffffffffu, sa, 2);
        sb += __shfl_xor_sync(0xffffffffu, sb, 1);
        sb += __shfl_xor_sync(0xffffffffu, sb, 2);
        den_a = den_a * ca + sa;
        den_b = den_b * cbr + sb;
        #pragma unroll
        for (int nt = 0; nt < 8; ++nt) {
            Od[nt][0] *= ca;  Od[nt][1] *= ca;
            Od[nt][2] *= cbr; Od[nt][3] *= cbr;
        }

        // O += P @ (Vh + Vl), P fp16-rounded in registers
        #pragma unroll
        for (int kc2 = 0; kc2 < 4; ++kc2) {
            uint32_t ph[4];
            ph[0] = packh2(sreg[2*kc2][0],   sreg[2*kc2][1]);
            ph[1] = packh2(sreg[2*kc2][2],   sreg[2*kc2][3]);
            ph[2] = packh2(sreg[2*kc2+1][0], sreg[2*kc2+1][1]);
            ph[3] = packh2(sreg[2*kc2+1][2], sreg[2*kc2+1][3]);
            int vr = kc2 * 16 + (lane & 15);
            #pragma unroll
            for (int ng = 0; ng < 4; ++ng) {
                int vc = ng * 16 + ((lane >> 4) << 3);
                uint32_t vh0, vh1, vh2, vh3, vl0, vl1, vl2, vl3;
                uint32_t ad = sptr(vh + vr * APAD + vc);
                LDSM4T(vh0, vh1, vh2, vh3, ad);
                ad = sptr(vl + vr * APAD + vc);
                LDSM4T(vl0, vl1, vl2, vl3, ad);
                MMA16816(Od[2*ng],   ph, vh0, vh1);
                MMA16816(Od[2*ng],   ph, vl0, vl1);
                MMA16816(Od[2*ng+1], ph, vh2, vh3);
                MMA16816(Od[2*ng+1], ph, vl2, vl3);
            }
        }
        __syncthreads();
        if (kt + 2 < ntk) ISSUE_KV(buf, kt + 2);
        CPCOMMIT();
        buf ^= 1;
    }

    CPWAITALL();

    float inva = 1.f / den_a, invb = 1.f / den_b;
    int gq_a = qb * 128 + wq0 + (lane >> 2);
    size_t oa = (size_t)(b * S_ + gq_a) * D_ + h * 64 + ((lane & 3) << 1);
    size_t ob = oa + (size_t)8 * D_;
    #pragma unroll
    for (int nt = 0; nt < 8; ++nt) {
        *(uint32_t*)(oh + oa + nt * 8) = packh2(Od[nt][0] * inva, Od[nt][1] * inva);
        *(uint32_t*)(oh + ob + nt * 8) = packh2(Od[nt][2] * invb, Od[nt][3] * invb);
    }
}

// ---------------- fused residual add + LayerNorm (+ fp16 out) -------------
__global__ void add_ln_kernel(float* __restrict__ x,
                              const float* __restrict__ r,
                              const float* __restrict__ g,
                              const float* __restrict__ bb,
                              __half* __restrict__ xh) {
    int row = blockIdx.x;
    int tid = threadIdx.x;
    size_t base = (size_t)row * D_;
    float v[4];
    float s = 0.f;
    #pragma unroll
    for (int j = 0; j < 4; ++j) {
        int c = tid + j * 256;
        v[j] = x[base + c] + r[base + c];
        s += v[j];
    }
    __shared__ float sh[8];
    #pragma unroll
    for (int off = 16; off > 0; off >>= 1) s += __shfl_xor_sync(0xffffffffu, s, off);
    if ((tid & 31) == 0) sh[tid >> 5] = s;
    __syncthreads();
    if (tid < 32) {
        float t = (tid < 8) ? sh[tid] : 0.f;
        #pragma unroll
        for (int off = 4; off > 0; off >>= 1) t += __shfl_xor_sync(0xffffffffu, t, off);
        if (tid == 0) sh[0] = t;
    }
    __syncthreads();
    float mu = sh[0] * (1.f / 1024.f);
    __syncthreads();
    float ss = 0.f;
    #pragma unroll
    for (int j = 0; j < 4; ++j) { float d = v[j] - mu; ss += d * d; }
    #pragma unroll
    for (int off = 16; off > 0; off >>= 1) ss += __shfl_xor_sync(0xffffffffu, ss, off);
    if ((tid & 31) == 0) sh[tid >> 5] = ss;
    __syncthreads();
    if (tid < 32) {
        float t = (tid < 8) ? sh[tid] : 0.f;
        #pragma unroll
        for (int off = 4; off > 0; off >>= 1) t += __shfl_xor_sync(0xffffffffu, t, off);
        if (tid == 0) sh[0] = t;
    }
    __syncthreads();
    float var = sh[0] * (1.f / 1024.f);
    float rstd = rsqrtf(var + 1e-5f);
    #pragma unroll
    for (int j = 0; j < 4; ++j) {
        int c = tid + j * 256;
        float y = (v[j] - mu) * rstd * g[c] + bb[c];
        x[base + c] = y;
        xh[base + c] = __float2half_rn(y);
    }
}

// ---------------------------------------------------------------------------
extern "C" void kernel_launch(void* const* d_in, const int* in_sizes, int n_in,
                              void* d_out, int out_size) {
    const int*   tokens = (const int*)  d_in[0];
    const float* emb    = (const float*)d_in[1];
    const float* qkv_w  = (const float*)d_in[2];
    const float* qkv_b  = (const float*)d_in[3];
    const float* out_w  = (const float*)d_in[4];
    const float* out_b  = (const float*)d_in[5];
    const float* fc1_w  = (const float*)d_in[6];
    const float* fc1_b  = (const float*)d_in[7];
    const float* fc2_w  = (const float*)d_in[8];
    const float* fc2_b  = (const float*)d_in[9];
    const float* ln1_g  = (const float*)d_in[10];
    const float* ln1_b  = (const float*)d_in[11];
    const float* ln2_g  = (const float*)d_in[12];
    const float* ln2_b  = (const float*)d_in[13];
    const float* w_out  = (const float*)d_in[14];
    const float* b_out  = (const float*)d_in[15];
    float* out = (float*)d_out;

    float *x, *tmp, *o;
    __half *xh, *oh, *hh, *hl, *wh, *wl;
    cudaGetSymbolAddress((void**)&x,   g_x);
    cudaGetSymbolAddress((void**)&tmp, g_tmp);
    cudaGetSymbolAddress((void**)&o,   g_o);
    cudaGetSymbolAddress((void**)&xh,  g_xh);
    cudaGetSymbolAddress((void**)&oh,  g_oh);
    cudaGetSymbolAddress((void**)&hh,  g_hh);
    cudaGetSymbolAddress((void**)&hl,  g_hl);
    cudaGetSymbolAddress((void**)&wh,  g_wh);
    cudaGetSymbolAddress((void**)&wl,  g_wl);

    cudaFuncSetAttribute(mma_gemm, cudaFuncAttributeMaxDynamicSharedMemorySize,
                         GEMM_SMEM);
    cudaFuncSetAttribute(attn_mma, cudaFuncAttributeMaxDynamicSharedMemorySize,
                         ATT_SMEM);

    embed_kernel<<<TOK_, 256>>>(tokens, emb, x, xh);

    for (int l = 0; l < L_; ++l) {
        // qkv = x @ qkv_w + b -> fp16 hi/lo (mode 2) into hh/hl
        int nqkv = D_ * 3 * D_;
        split_kernel<<<nqkv / 1024, 256>>>(qkv_w + (size_t)l * nqkv, wh, wl, nqkv);
        mma_gemm<<<dim3(3072 / 128, TOK_ / 128), 512, GEMM_SMEM>>>(
            xh, wh, wl, qkv_b + (size_t)l * 3 * D_,
            nullptr, hh, hl, 3 * D_, D_, 2);
        // attention -> oh
        attn_mma<<<dim3(S_ / 128, B_ * H_), 256, ATT_SMEM>>>(hh, hl, oh);
        // out proj -> tmp fp32
        int nout = D_ * D_;
        split_kernel<<<nout / 1024, 256>>>(out_w + (size_t)l * nout, wh, wl, nout);
        mma_gemm<<<dim3(D_ / 128, TOK_ / 128), 512, GEMM_SMEM>>>(
            oh, wh, wl, out_b + (size_t)l * D_,
            tmp, nullptr, nullptr, D_, D_, 0);
        add_ln_kernel<<<TOK_, 256>>>(x, tmp, ln1_g + l * D_, ln1_b + l * D_, xh);
        // fc1 (relu, fp16 hi only)
        int nfc1 = D_ * FF_;
        split_kernel<<<nfc1 / 1024, 256>>>(fc1_w + (size_t)l * nfc1, wh, wl, nfc1);
        mma_gemm<<<dim3(FF_ / 128, TOK_ / 128), 512, GEMM_SMEM>>>(
            xh, wh, wl, fc1_b + (size_t)l * FF_,
            nullptr, hh, nullptr, FF_, D_, 1);
        // fc2
        int nfc2 = FF_ * D_;
        split_kernel<<<nfc2 / 1024, 256>>>(fc2_w + (size_t)l * nfc2, wh, wl, nfc2);
        mma_gemm<<<dim3(D_ / 128, TOK_ / 128), 512, GEMM_SMEM>>>(
            hh, wh, wl, fc2_b + (size_t)l * D_,
            o, nullptr, nullptr, D_, FF_, 0);
        add_ln_kernel<<<TOK_, 256>>>(x, o, ln2_g + l * D_, ln2_b + l * D_, xh);
    }

    // logits
    int nlog = D_ * V_;
    split_kernel<<<nlog / 1024, 256>>>(w_out, wh, wl, nlog);
    mma_gemm<<<dim3(V_ / 128, TOK_ / 128), 512, GEMM_SMEM>>>(
        xh, wh, wl, b_out, out, nullptr, nullptr, V_, D_, 0);
}

// round 10
// speedup vs baseline: 11.0178x; 1.5668x over previous
#include <cuda_runtime.h>
#include <cuda_fp16.h>
#include <math.h>
#include <stdint.h>

#define B_ 2
#define S_ 2048
#define D_ 1024
#define L_ 6
#define H_ 16
#define HD_ 64
#define FF_ 4096
#define V_ 32000
#define TOK_ (B_ * S_)          // 4096 token rows

// ---------------- scratch (static device globals; no allocation) ----------
__device__ float g_x[TOK_ * D_];                 // fp32 residual stream
__device__ float g_tmp[TOK_ * FF_];              // out-proj / fc2 fp32 out
__device__ float g_o[TOK_ * D_];                 // fc2 out (pre-LN2)
__device__ __half g_xh[TOK_ * D_];               // x (fp16 plane)
__device__ __half g_oh[TOK_ * D_];               // attention out
__device__ __half g_hh[TOK_ * FF_];              // qkv / ffn hidden hi
__device__ __half g_hl[TOK_ * FF_];              // qkv lo (K/V lo planes)
__device__ __half g_wh[(size_t)D_ * V_];         // weight fp16, layout [K][N]

__device__ __forceinline__ void split1h(float x, __half& h, __half& l) {
    h = __float2half_rn(x);
    l = __float2half_rn(x - __half2float(h));
}
__device__ __forceinline__ uint32_t packh2(float x, float y) {
    __half2 t = __floats2half2_rn(x, y);
    return *reinterpret_cast<uint32_t*>(&t);
}
__device__ __forceinline__ void split2uh(float x, float y, uint32_t& h, uint32_t& l) {
    __half hx, lx, hy, ly;
    split1h(x, hx, lx); split1h(y, hy, ly);
    __half2 th{hx, hy}, tl{lx, ly};
    h = *reinterpret_cast<uint32_t*>(&th);
    l = *reinterpret_cast<uint32_t*>(&tl);
}

// ---------------- PTX helpers ----------------------------------------------
__device__ __forceinline__ uint32_t sptr(const void* p) {
    return (uint32_t)__cvta_generic_to_shared(p);
}
#define LDSM4(R0, R1, R2, R3, ADDR) \
    asm volatile("ldmatrix.sync.aligned.m8n8.x4.shared.b16 {%0,%1,%2,%3}, [%4];" \
                 : "=r"(R0), "=r"(R1), "=r"(R2), "=r"(R3) : "r"(ADDR))
#define LDSM4T(R0, R1, R2, R3, ADDR) \
    asm volatile("ldmatrix.sync.aligned.m8n8.x4.trans.shared.b16 {%0,%1,%2,%3}, [%4];" \
                 : "=r"(R0), "=r"(R1), "=r"(R2), "=r"(R3) : "r"(ADDR))
#define MMA16816(Cv, Ar, Bb0, Bb1) \
    asm volatile("mma.sync.aligned.m16n8k16.row.col.f32.f16.f16.f32 " \
                 "{%0,%1,%2,%3},{%4,%5,%6,%7},{%8,%9},{%0,%1,%2,%3};" \
                 : "+f"(Cv[0]), "+f"(Cv[1]), "+f"(Cv[2]), "+f"(Cv[3]) \
                 : "r"(Ar[0]), "r"(Ar[1]), "r"(Ar[2]), "r"(Ar[3]), \
                   "r"(Bb0), "r"(Bb1))
#define CP16(DST, SRC) \
    asm volatile("cp.async.cg.shared.global [%0], [%1], 16;" :: "r"(DST), "l"(SRC))
#define CPCOMMIT() asm volatile("cp.async.commit_group;")
#define CPWAIT1()  asm volatile("cp.async.wait_group 1;")
#define CPWAIT2()  asm volatile("cp.async.wait_group 2;")
#define CPWAITALL() asm volatile("cp.async.wait_all;")

// ---------------- weight convert: fp32 -> fp16 (same [K][N] layout) -------
__global__ void cvt_kernel(const float* __restrict__ in,
                           __half* __restrict__ hi, int n) {
    int i = (blockIdx.x * 256 + threadIdx.x) * 4;
    if (i >= n) return;
    float4 v = *(const float4*)(in + i);
    *(uint32_t*)(hi + i)     = packh2(v.x, v.y);
    *(uint32_t*)(hi + i + 2) = packh2(v.z, v.w);
}

// ---------------- embedding + positional encoding (+ fp16 out) ------------
__global__ void embed_kernel(const int* __restrict__ tokens,
                             const float* __restrict__ emb,
                             float* __restrict__ x,
                             __half* __restrict__ xh) {
    int row = blockIdx.x;
    int s   = row & (S_ - 1);
    int tok = tokens[row];
    const float* erow = emb + (size_t)tok * D_;
    size_t base = (size_t)row * D_;
    const float kfac = -0.00899447301950812f;   // -ln(10000)/1024
    #pragma unroll
    for (int j = 0; j < 4; ++j) {
        int c = threadIdx.x + j * 256;
        float freq = expf(kfac * (float)(c & ~1));
        float arg  = (float)s * freq;
        float pe   = (c & 1) ? cosf(arg) : sinf(arg);
        float v = erow[c] + pe;
        x[base + c] = v;
        xh[base + c] = __float2half_rn(v);
    }
}

// ===================== fp16 tensor-core GEMM (single-term) =================
// C = Ah[MxK] @ Bh[KxN] + bias, fp32 accum.
// 512 threads = 16 warps (4m x 4n), warp tile 32x64, block tile 128x256x64.
// 4-stage cp.async pipeline, one __syncthreads per k-chunk.
#define AST2 72
#define BST2 264
#define A_EL (128 * AST2)                 // 9216
#define B_EL2 (64 * BST2)                 // 16896
#define STG_E (A_EL + B_EL2)              // 26112 elems
#define GEMM_SMEM (4 * STG_E * 2)         // 208896 bytes

#define ISSUE_STAGE(SIDX, K0) do {                                           \
    __half* _b = sm + (SIDX) * STG_E;                                        \
    _Pragma("unroll")                                                        \
    for (int _i = 0; _i < 2; ++_i) {                                         \
        int _id = tid + _i * 512;                                            \
        int _r = _id >> 3, _c = (_id & 7) << 3;                              \
        CP16(sptr(_b + _r * AST2 + _c), gA + (size_t)_r * K + (K0) + _c);    \
    }                                                                        \
    _Pragma("unroll")                                                        \
    for (int _i = 0; _i < 4; ++_i) {                                         \
        int _id = tid + _i * 512;                                            \
        int _r = _id >> 5, _c = (_id & 31) << 3;                             \
        CP16(sptr(_b + A_EL + _r * BST2 + _c),                               \
             gB + (size_t)((K0) + _r) * N + _c);                             \
    }                                                                        \
} while (0)

// mode 0: fp32 C. mode 1: relu + fp16 hi only. mode 2: fp16 hi + lo.
__global__ void __launch_bounds__(512, 1)
mma_gemm(const __half* __restrict__ Ah,
         const __half* __restrict__ Bh,
         const float* __restrict__ bias,
         float* __restrict__ C,
         __half* __restrict__ Ch, __half* __restrict__ Cl,
         int N, int K, int mode) {
    extern __shared__ __half sm[];

    const int tid = threadIdx.x;
    const int wid = tid >> 5, lane = tid & 31;
    const int wm = (wid >> 2) << 5;     // 0..96
    const int wn = (wid & 3) << 6;      // 0..192
    const int bx = blockIdx.x, by = blockIdx.y;

    const __half* gA = Ah + (size_t)(by * 128) * K;
    const __half* gB = Bh + bx * 256;

    float acc[2][8][4];
    #pragma unroll
    for (int i = 0; i < 2; ++i)
        #pragma unroll
        for (int j = 0; j < 8; ++j)
            #pragma unroll
            for (int t = 0; t < 4; ++t) acc[i][j][t] = 0.f;

    ISSUE_STAGE(0, 0);   CPCOMMIT();
    ISSUE_STAGE(1, 64);  CPCOMMIT();
    ISSUE_STAGE(2, 128); CPCOMMIT();

    const int ntile = K >> 6;
    for (int it = 0; it < ntile; ++it) {
        CPWAIT2();
        __syncthreads();

        int nk = (it + 3) << 6;
        if (nk < K) {
            ISSUE_STAGE((it + 3) & 3, nk);
        }
        CPCOMMIT();

        const __half* ah = sm + (it & 3) * STG_E;
        const __half* bsh = ah + A_EL;

        #pragma unroll
        for (int kc = 0; kc < 4; ++kc) {
            uint32_t a_f[2][4];
            int af = lane & 15;
            int ac = kc * 16 + ((lane >> 4) << 3);
            #pragma unroll
            for (int mt = 0; mt < 2; ++mt) {
                uint32_t ad = sptr(ah + (wm + mt * 16 + af) * AST2 + ac);
                LDSM4(a_f[mt][0], a_f[mt][1], a_f[mt][2], a_f[mt][3], ad);
            }
            int bkr = kc * 16 + (lane & 15);
            #pragma unroll
            for (int p = 0; p < 4; ++p) {
                int bnc = wn + p * 16 + ((lane >> 4) << 3);
                uint32_t b0, b1, b2, b3;
                uint32_t bd = sptr(bsh + bkr * BST2 + bnc);
                LDSM4T(b0, b1, b2, b3, bd);
                MMA16816(acc[0][2*p],   a_f[0], b0, b1);
                MMA16816(acc[0][2*p+1], a_f[0], b2, b3);
                MMA16816(acc[1][2*p],   a_f[1], b0, b1);
                MMA16816(acc[1][2*p+1], a_f[1], b2, b3);
            }
        }
        // no trailing sync: stage (it&3) is rewritten only in iteration it+1,
        // after that iteration's top-of-loop __syncthreads.
    }

    #pragma unroll
    for (int mt = 0; mt < 2; ++mt) {
        int row = by * 128 + wm + mt * 16 + (lane >> 2);
        #pragma unroll
        for (int nt = 0; nt < 8; ++nt) {
            int col = bx * 256 + wn + nt * 8 + ((lane & 3) << 1);
            float2 bv = *(const float2*)(bias + col);
            float v0 = acc[mt][nt][0] + bv.x;
            float v1 = acc[mt][nt][1] + bv.y;
            float v2 = acc[mt][nt][2] + bv.x;
            float v3 = acc[mt][nt][3] + bv.y;
            if (mode == 0) {
                float2 o0 = {v0, v1}, o1 = {v2, v3};
                *(float2*)(C + (size_t)row * N + col)       = o0;
                *(float2*)(C + (size_t)(row + 8) * N + col) = o1;
            } else if (mode == 1) {
                v0 = fmaxf(v0, 0.f); v1 = fmaxf(v1, 0.f);
                v2 = fmaxf(v2, 0.f); v3 = fmaxf(v3, 0.f);
                *(uint32_t*)(Ch + (size_t)row * N + col)       = packh2(v0, v1);
                *(uint32_t*)(Ch + (size_t)(row + 8) * N + col) = packh2(v2, v3);
            } else {
                uint32_t h01, l01, h23, l23;
                split2uh(v0, v1, h01, l01);
                split2uh(v2, v3, h23, l23);
                *(uint32_t*)(Ch + (size_t)row * N + col)       = h01;
                *(uint32_t*)(Ch + (size_t)(row + 8) * N + col) = h23;
                *(uint32_t*)(Cl + (size_t)row * N + col)       = l01;
                *(uint32_t*)(Cl + (size_t)(row + 8) * N + col) = l23;
            }
        }
    }
}

// ===================== tensor-core causal flash attention ==================
// 128 threads (4 warps), 64 queries of one (b,h), 64-key tiles, double-buffered.
// 2-term fp16: S = Qh(Kh+Kl)^T,  O += Ph(Vh+Vl).
#define APAD 72
#define AQBUF 4608                    // 64*72
#define AKV0 AQBUF                    // Q hi only
#define AKVSTRIDE (4 * AQBUF)         // kh,kl,vh,vl per stage
#define ATT_SMEM ((AQBUF + 2 * AKVSTRIDE) * 2)   // 82944 bytes

__global__ void __launch_bounds__(128, 2)
attn_mma(const __half* __restrict__ qh,
         const __half* __restrict__ ql,
         __half* __restrict__ oh) {
    extern __shared__ __half sm[];
    const int tid = threadIdx.x;
    const int wid = tid >> 5, lane = tid & 31;
    const int qb = gridDim.x - 1 - blockIdx.x;
    const int bh = blockIdx.y;
    const int h = bh & (H_ - 1), b = bh >> 4;
    const int wq0 = wid << 4;

    const size_t seqbase = (size_t)(b * S_) * 3072 + h * 64;

    // Q tile (hi only)
    {
        #pragma unroll
        for (int i = 0; i < 4; ++i) {
            int id = tid + i * 128;
            int row = id >> 3, col = (id & 7) << 3;
            size_t src = seqbase + (size_t)(qb * 64 + row) * 3072 + col;
            CP16(sptr(sm + row * APAD + col), qh + src);
        }
        CPCOMMIT();
    }
    #define ISSUE_KV(STG, KT0) do {                                         \
        __half* _kb = sm + AKV0 + (STG) * AKVSTRIDE;                        \
        _Pragma("unroll")                                                   \
        for (int i = 0; i < 4; ++i) {                                       \
            int id = tid + i * 128;                                         \
            int row = id >> 3, col = (id & 7) << 3;                         \
            size_t src = seqbase + (size_t)((KT0) * 64 + row) * 3072 + col; \
            uint32_t dst = sptr(_kb + row * APAD + col);                    \
            CP16(dst,                 qh + src + 1024);                     \
            CP16(dst + AQBUF * 2,     ql + src + 1024);                     \
            CP16(dst + AQBUF * 4,     qh + src + 2048);                     \
            CP16(dst + AQBUF * 6,     ql + src + 2048);                     \
        }                                                                   \
        CPCOMMIT();                                                         \
    } while (0)

    ISSUE_KV(0, 0);
    ISSUE_KV(1, (qb >= 1 ? 1 : 0));

    CPWAIT2();
    __syncthreads();
    uint32_t qf[4][4];
    {
        int af = lane & 15;
        #pragma unroll
        for (int kc = 0; kc < 4; ++kc) {
            int ac = kc * 16 + ((lane >> 4) << 3);
            uint32_t ad = sptr(sm + (wq0 + af) * APAD + ac);
            LDSM4(qf[kc][0], qf[kc][1], qf[kc][2], qf[kc][3], ad);
        }
    }

    float Od[8][4];
    #pragma unroll
    for (int i = 0; i < 8; ++i)
        #pragma unroll
        for (int j = 0; j < 4; ++j) Od[i][j] = 0.f;
    float m_a = -1e30f, m_b = -1e30f, den_a = 0.f, den_b = 0.f;

    int buf = 0;
    const int ntk = qb + 1;
    for (int kt = 0; kt < ntk; ++kt) {
        CPWAIT1();
        __syncthreads();

        const __half* kh = sm + AKV0 + buf * AKVSTRIDE;
        const __half* kl = kh + AQBUF;
        const __half* vh = kh + 2 * AQBUF;
        const __half* vl = kh + 3 * AQBUF;

        float sreg[8][4];
        #pragma unroll
        for (int i = 0; i < 8; ++i)
            #pragma unroll
            for (int j = 0; j < 4; ++j) sreg[i][j] = 0.f;

        #pragma unroll
        for (int kc = 0; kc < 4; ++kc) {
            int krow = ((lane >> 4) << 3) + (lane & 7);
            int kcol = kc * 16 + (((lane >> 3) & 1) << 3);
            #pragma unroll
            for (int ng = 0; ng < 4; ++ng) {
                uint32_t bh0, bh1, bh2, bh3, bl0, bl1, bl2, bl3;
                uint32_t ad = sptr(kh + (ng * 16 + krow) * APAD + kcol);
                LDSM4(bh0, bh1, bh2, bh3, ad);
                ad = sptr(kl + (ng * 16 + krow) * APAD + kcol);
                LDSM4(bl0, bl1, bl2, bl3, ad);
                MMA16816(sreg[2*ng],   qf[kc], bh0, bh1);
                MMA16816(sreg[2*ng],   qf[kc], bl0, bl1);
                MMA16816(sreg[2*ng+1], qf[kc], bh2, bh3);
                MMA16816(sreg[2*ng+1], qf[kc], bl2, bl3);
            }
        }

        int ra = wq0 + (lane >> 2);
        int cb = (lane & 3) << 1;
        #pragma unroll
        for (int nt = 0; nt < 8; ++nt) {
            #pragma unroll
            for (int j = 0; j < 4; ++j) {
                float s = sreg[nt][j] * 0.125f;
                if (kt == qb) {
                    int col = nt * 8 + cb + (j & 1);
                    int row = ra + ((j >> 1) << 3);
                    if (col > row) s = -1e30f;
                }
                sreg[nt][j] = s;
            }
        }
        float mxa = -1e30f, mxb = -1e30f;
        #pragma unroll
        for (int nt = 0; nt < 8; ++nt) {
            mxa = fmaxf(mxa, fmaxf(sreg[nt][0], sreg[nt][1]));
            mxb = fmaxf(mxb, fmaxf(sreg[nt][2], sreg[nt][3]));
        }
        mxa = fmaxf(mxa, __shfl_xor_sync(0xffffffffu, mxa, 1));
        mxa = fmaxf(mxa, __shfl_xor_sync(0xffffffffu, mxa, 2));
        mxb = fmaxf(mxb, __shfl_xor_sync(0xffffffffu, mxb, 1));
        mxb = fmaxf(mxb, __shfl_xor_sync(0xffffffffu, mxb, 2));
        float mna = fmaxf(m_a, mxa), mnb = fmaxf(m_b, mxb);
        float ca = __expf(m_a - mna), cbr = __expf(m_b - mnb);
        m_a = mna; m_b = mnb;
        float sa = 0.f, sb = 0.f;
        #pragma unroll
        for (int nt = 0; nt < 8; ++nt) {
            float p0 = __expf(sreg[nt][0] - mna);
            float p1 = __expf(sreg[nt][1] - mna);
            float p2 = __expf(sreg[nt][2] - mnb);
            float p3 = __expf(sreg[nt][3] - mnb);
            sreg[nt][0] = p0; sreg[nt][1] = p1; sreg[nt][2] = p2; sreg[nt][3] = p3;
            sa += p0 + p1; sb += p2 + p3;
        }
        sa += __shfl_xor_sync(0xffffffffu, sa, 1);
        sa += __shfl_xor_sync(0xffffffffu, sa, 2);
        sb += __shfl_xor_sync(0xffffffffu, sb, 1);
        sb += __shfl_xor_sync(0xffffffffu, sb, 2);
        den_a = den_a * ca + sa;
        den_b = den_b * cbr + sb;
        #pragma unroll
        for (int nt = 0; nt < 8; ++nt) {
            Od[nt][0] *= ca;  Od[nt][1] *= ca;
            Od[nt][2] *= cbr; Od[nt][3] *= cbr;
        }

        // O += P @ (Vh + Vl), P fp16-rounded in registers
        #pragma unroll
        for (int kc2 = 0; kc2 < 4; ++kc2) {
            uint32_t ph[4];
            ph[0] = packh2(sreg[2*kc2][0],   sreg[2*kc2][1]);
            ph[1] = packh2(sreg[2*kc2][2],   sreg[2*kc2][3]);
            ph[2] = packh2(sreg[2*kc2+1][0], sreg[2*kc2+1][1]);
            ph[3] = packh2(sreg[2*kc2+1][2], sreg[2*kc2+1][3]);
            int vr = kc2 * 16 + (lane & 15);
            #pragma unroll
            for (int ng = 0; ng < 4; ++ng) {
                int vc = ng * 16 + ((lane >> 4) << 3);
                uint32_t vh0, vh1, vh2, vh3, vl0, vl1, vl2, vl3;
                uint32_t ad = sptr(vh + vr * APAD + vc);
                LDSM4T(vh0, vh1, vh2, vh3, ad);
                ad = sptr(vl + vr * APAD + vc);
                LDSM4T(vl0, vl1, vl2, vl3, ad);
                MMA16816(Od[2*ng],   ph, vh0, vh1);
                MMA16816(Od[2*ng],   ph, vl0, vl1);
                MMA16816(Od[2*ng+1], ph, vh2, vh3);
                MMA16816(Od[2*ng+1], ph, vl2, vl3);
            }
        }
        __syncthreads();
        if (kt + 2 <= qb) ISSUE_KV(buf, kt + 2);
        CPCOMMIT();
        buf ^= 1;
    }

    CPWAITALL();

    float inva = 1.f / den_a, invb = 1.f / den_b;
    int gq_a = qb * 64 + wq0 + (lane >> 2);
    size_t oa = (size_t)(b * S_ + gq_a) * D_ + h * 64 + ((lane & 3) << 1);
    size_t ob = oa + (size_t)8 * D_;
    #pragma unroll
    for (int nt = 0; nt < 8; ++nt) {
        *(uint32_t*)(oh + oa + nt * 8) = packh2(Od[nt][0] * inva, Od[nt][1] * inva);
        *(uint32_t*)(oh + ob + nt * 8) = packh2(Od[nt][2] * invb, Od[nt][3] * invb);
    }
}

// ---------------- fused residual add + LayerNorm (+ fp16 out) -------------
__global__ void add_ln_kernel(float* __restrict__ x,
                              const float* __restrict__ r,
                              const float* __restrict__ g,
                              const float* __restrict__ bb,
                              __half* __restrict__ xh) {
    int row = blockIdx.x;
    int tid = threadIdx.x;
    size_t base = (size_t)row * D_;
    float v[4];
    float s = 0.f;
    #pragma unroll
    for (int j = 0; j < 4; ++j) {
        int c = tid + j * 256;
        v[j] = x[base + c] + r[base + c];
        s += v[j];
    }
    __shared__ float sh[8];
    #pragma unroll
    for (int off = 16; off > 0; off >>= 1) s += __shfl_xor_sync(0xffffffffu, s, off);
    if ((tid & 31) == 0) sh[tid >> 5] = s;
    __syncthreads();
    if (tid < 32) {
        float t = (tid < 8) ? sh[tid] : 0.f;
        #pragma unroll
        for (int off = 4; off > 0; off >>= 1) t += __shfl_xor_sync(0xffffffffu, t, off);
        if (tid == 0) sh[0] = t;
    }
    __syncthreads();
    float mu = sh[0] * (1.f / 1024.f);
    __syncthreads();
    float ss = 0.f;
    #pragma unroll
    for (int j = 0; j < 4; ++j) { float d = v[j] - mu; ss += d * d; }
    #pragma unroll
    for (int off = 16; off > 0; off >>= 1) ss += __shfl_xor_sync(0xffffffffu, ss, off);
    if ((tid & 31) == 0) sh[tid >> 5] = ss;
    __syncthreads();
    if (tid < 32) {
        float t = (tid < 8) ? sh[tid] : 0.f;
        #pragma unroll
        for (int off = 4; off > 0; off >>= 1) t += __shfl_xor_sync(0xffffffffu, t, off);
        if (tid == 0) sh[0] = t;
    }
    __syncthreads();
    float var = sh[0] * (1.f / 1024.f);
    float rstd = rsqrtf(var + 1e-5f);
    #pragma unroll
    for (int j = 0; j < 4; ++j) {
        int c = tid + j * 256;
        float y = (v[j] - mu) * rstd * g[c] + bb[c];
        x[base + c] = y;
        xh[base + c] = __float2half_rn(y);
    }
}

// ---------------------------------------------------------------------------
extern "C" void kernel_launch(void* const* d_in, const int* in_sizes, int n_in,
                              void* d_out, int out_size) {
    const int*   tokens = (const int*)  d_in[0];
    const float* emb    = (const float*)d_in[1];
    const float* qkv_w  = (const float*)d_in[2];
    const float* qkv_b  = (const float*)d_in[3];
    const float* out_w  = (const float*)d_in[4];
    const float* out_b  = (const float*)d_in[5];
    const float* fc1_w  = (const float*)d_in[6];
    const float* fc1_b  = (const float*)d_in[7];
    const float* fc2_w  = (const float*)d_in[8];
    const float* fc2_b  = (const float*)d_in[9];
    const float* ln1_g  = (const float*)d_in[10];
    const float* ln1_b  = (const float*)d_in[11];
    const float* ln2_g  = (const float*)d_in[12];
    const float* ln2_b  = (const float*)d_in[13];
    const float* w_out  = (const float*)d_in[14];
    const float* b_out  = (const float*)d_in[15];
    float* out = (float*)d_out;

    float *x, *tmp, *o;
    __half *xh, *oh, *hh, *hl, *wh;
    cudaGetSymbolAddress((void**)&x,   g_x);
    cudaGetSymbolAddress((void**)&tmp, g_tmp);
    cudaGetSymbolAddress((void**)&o,   g_o);
    cudaGetSymbolAddress((void**)&xh,  g_xh);
    cudaGetSymbolAddress((void**)&oh,  g_oh);
    cudaGetSymbolAddress((void**)&hh,  g_hh);
    cudaGetSymbolAddress((void**)&hl,  g_hl);
    cudaGetSymbolAddress((void**)&wh,  g_wh);

    cudaFuncSetAttribute(mma_gemm, cudaFuncAttributeMaxDynamicSharedMemorySize,
                         GEMM_SMEM);
    cudaFuncSetAttribute(attn_mma, cudaFuncAttributeMaxDynamicSharedMemorySize,
                         ATT_SMEM);

    embed_kernel<<<TOK_, 256>>>(tokens, emb, x, xh);

    for (int l = 0; l < L_; ++l) {
        // qkv = x @ qkv_w + b -> fp16 hi/lo (mode 2) into hh/hl
        int nqkv = D_ * 3 * D_;
        cvt_kernel<<<nqkv / 1024, 256>>>(qkv_w + (size_t)l * nqkv, wh, nqkv);
        mma_gemm<<<dim3(3072 / 256, TOK_ / 128), 512, GEMM_SMEM>>>(
            xh, wh, qkv_b + (size_t)l * 3 * D_,
            nullptr, hh, hl, 3 * D_, D_, 2);
        // attention -> oh
        attn_mma<<<dim3(S_ / 64, B_ * H_), 128, ATT_SMEM>>>(hh, hl, oh);
        // out proj -> tmp fp32
        int nout = D_ * D_;
        cvt_kernel<<<nout / 1024, 256>>>(out_w + (size_t)l * nout, wh, nout);
        mma_gemm<<<dim3(D_ / 256, TOK_ / 128), 512, GEMM_SMEM>>>(
            oh, wh, out_b + (size_t)l * D_,
            tmp, nullptr, nullptr, D_, D_, 0);
        add_ln_kernel<<<TOK_, 256>>>(x, tmp, ln1_g + l * D_, ln1_b + l * D_, xh);
        // fc1 (relu, fp16 hi only)
        int nfc1 = D_ * FF_;
        cvt_kernel<<<nfc1 / 1024, 256>>>(fc1_w + (size_t)l * nfc1, wh, nfc1);
        mma_gemm<<<dim3(FF_ / 256, TOK_ / 128), 512, GEMM_SMEM>>>(
            xh, wh, fc1_b + (size_t)l * FF_,
            nullptr, hh, nullptr, FF_, D_, 1);
        // fc2
        int nfc2 = FF_ * D_;
        cvt_kernel<<<nfc2 / 1024, 256>>>(fc2_w + (size_t)l * nfc2, wh, nfc2);
        mma_gemm<<<dim3(D_ / 256, TOK_ / 128), 512, GEMM_SMEM>>>(
            hh, wh, fc2_b + (size_t)l * D_,
            o, nullptr, nullptr, D_, FF_, 0);
        add_ln_kernel<<<TOK_, 256>>>(x, o, ln2_g + l * D_, ln2_b + l * D_, xh);
    }

    // logits
    int nlog = D_ * V_;
    cvt_kernel<<<nlog / 1024, 256>>>(w_out, wh, nlog);
    mma_gemm<<<dim3(V_ / 256, TOK_ / 128), 512, GEMM_SMEM>>>(
        xh, wh, b_out, out, nullptr, nullptr, V_, D_, 0);
}

// round 11
// speedup vs baseline: 12.6453x; 1.1477x over previous
#include <cuda_runtime.h>
#include <cuda_fp16.h>
#include <math.h>
#include <stdint.h>

#define B_ 2
#define S_ 2048
#define D_ 1024
#define L_ 6
#define H_ 16
#define HD_ 64
#define FF_ 4096
#define V_ 32000
#define TOK_ (B_ * S_)          // 4096 token rows

// ---------------- scratch (static device globals; no allocation) ----------
__device__ float g_x[TOK_ * D_];                 // fp32 residual stream
__device__ float g_tmp[TOK_ * FF_];              // out-proj / fc2 fp32 out
__device__ float g_o[TOK_ * D_];                 // fc2 out (pre-LN2)
__device__ __half g_xh[TOK_ * D_];               // x (fp16 plane)
__device__ __half g_oh[TOK_ * D_];               // attention out
__device__ __half g_hh[TOK_ * FF_];              // qkv / ffn hidden (fp16)
__device__ __half g_wh[(size_t)D_ * V_];         // weight fp16, layout [K][N]

__device__ __forceinline__ uint32_t packh2(float x, float y) {
    __half2 t = __floats2half2_rn(x, y);
    return *reinterpret_cast<uint32_t*>(&t);
}

// ---------------- PTX helpers ----------------------------------------------
__device__ __forceinline__ uint32_t sptr(const void* p) {
    return (uint32_t)__cvta_generic_to_shared(p);
}
#define LDSM4(R0, R1, R2, R3, ADDR) \
    asm volatile("ldmatrix.sync.aligned.m8n8.x4.shared.b16 {%0,%1,%2,%3}, [%4];" \
                 : "=r"(R0), "=r"(R1), "=r"(R2), "=r"(R3) : "r"(ADDR))
#define LDSM4T(R0, R1, R2, R3, ADDR) \
    asm volatile("ldmatrix.sync.aligned.m8n8.x4.trans.shared.b16 {%0,%1,%2,%3}, [%4];" \
                 : "=r"(R0), "=r"(R1), "=r"(R2), "=r"(R3) : "r"(ADDR))
#define MMA16816(Cv, Ar, Bb0, Bb1) \
    asm volatile("mma.sync.aligned.m16n8k16.row.col.f32.f16.f16.f32 " \
                 "{%0,%1,%2,%3},{%4,%5,%6,%7},{%8,%9},{%0,%1,%2,%3};" \
                 : "+f"(Cv[0]), "+f"(Cv[1]), "+f"(Cv[2]), "+f"(Cv[3]) \
                 : "r"(Ar[0]), "r"(Ar[1]), "r"(Ar[2]), "r"(Ar[3]), \
                   "r"(Bb0), "r"(Bb1))
#define CP16(DST, SRC) \
    asm volatile("cp.async.cg.shared.global [%0], [%1], 16;" :: "r"(DST), "l"(SRC))
#define CPCOMMIT() asm volatile("cp.async.commit_group;")
#define CPWAIT1()  asm volatile("cp.async.wait_group 1;")
#define CPWAIT2()  asm volatile("cp.async.wait_group 2;")
#define CPWAITALL() asm volatile("cp.async.wait_all;")

// ---------------- weight convert: fp32 -> fp16 (same [K][N] layout) -------
__global__ void cvt_kernel(const float* __restrict__ in,
                           __half* __restrict__ hi, int n) {
    int i = (blockIdx.x * 256 + threadIdx.x) * 4;
    if (i >= n) return;
    float4 v = *(const float4*)(in + i);
    *(uint32_t*)(hi + i)     = packh2(v.x, v.y);
    *(uint32_t*)(hi + i + 2) = packh2(v.z, v.w);
}

// ---------------- embedding + positional encoding (+ fp16 out) ------------
__global__ void embed_kernel(const int* __restrict__ tokens,
                             const float* __restrict__ emb,
                             float* __restrict__ x,
                             __half* __restrict__ xh) {
    int row = blockIdx.x;
    int s   = row & (S_ - 1);
    int tok = tokens[row];
    const float* erow = emb + (size_t)tok * D_;
    size_t base = (size_t)row * D_;
    const float kfac = -0.00899447301950812f;   // -ln(10000)/1024
    #pragma unroll
    for (int j = 0; j < 4; ++j) {
        int c = threadIdx.x + j * 256;
        float freq = expf(kfac * (float)(c & ~1));
        float arg  = (float)s * freq;
        float pe   = (c & 1) ? cosf(arg) : sinf(arg);
        float v = erow[c] + pe;
        x[base + c] = v;
        xh[base + c] = __float2half_rn(v);
    }
}

// ===================== fp16 tensor-core GEMM (single-term) =================
// C = Ah[MxK] @ Bh[KxN] + bias, fp32 accum.
// 512 threads = 16 warps (4m x 4n), warp tile 32x64, block tile 128x256x64.
// 4-stage cp.async pipeline, one __syncthreads per k-chunk.
#define AST2 72
#define BST2 264
#define A_EL (128 * AST2)                 // 9216
#define B_EL2 (64 * BST2)                 // 16896
#define STG_E (A_EL + B_EL2)              // 26112 elems
#define GEMM_SMEM (4 * STG_E * 2)         // 208896 bytes

#define ISSUE_STAGE(SIDX, K0) do {                                           \
    __half* _b = sm + (SIDX) * STG_E;                                        \
    _Pragma("unroll")                                                        \
    for (int _i = 0; _i < 2; ++_i) {                                         \
        int _id = tid + _i * 512;                                            \
        int _r = _id >> 3, _c = (_id & 7) << 3;                              \
        CP16(sptr(_b + _r * AST2 + _c), gA + (size_t)_r * K + (K0) + _c);    \
    }                                                                        \
    _Pragma("unroll")                                                        \
    for (int _i = 0; _i < 4; ++_i) {                                         \
        int _id = tid + _i * 512;                                            \
        int _r = _id >> 5, _c = (_id & 31) << 3;                             \
        CP16(sptr(_b + A_EL + _r * BST2 + _c),                               \
             gB + (size_t)((K0) + _r) * N + _c);                             \
    }                                                                        \
} while (0)

// mode 0: fp32 C. mode 1: relu + fp16. mode 2: fp16 (no relu).
__global__ void __launch_bounds__(512, 1)
mma_gemm(const __half* __restrict__ Ah,
         const __half* __restrict__ Bh,
         const float* __restrict__ bias,
         float* __restrict__ C,
         __half* __restrict__ Ch,
         int N, int K, int mode) {
    extern __shared__ __half sm[];

    const int tid = threadIdx.x;
    const int wid = tid >> 5, lane = tid & 31;
    const int wm = (wid >> 2) << 5;     // 0..96
    const int wn = (wid & 3) << 6;      // 0..192
    const int bx = blockIdx.x, by = blockIdx.y;

    const __half* gA = Ah + (size_t)(by * 128) * K;
    const __half* gB = Bh + bx * 256;

    float acc[2][8][4];
    #pragma unroll
    for (int i = 0; i < 2; ++i)
        #pragma unroll
        for (int j = 0; j < 8; ++j)
            #pragma unroll
            for (int t = 0; t < 4; ++t) acc[i][j][t] = 0.f;

    ISSUE_STAGE(0, 0);   CPCOMMIT();
    ISSUE_STAGE(1, 64);  CPCOMMIT();
    ISSUE_STAGE(2, 128); CPCOMMIT();

    const int ntile = K >> 6;
    for (int it = 0; it < ntile; ++it) {
        CPWAIT2();
        __syncthreads();

        int nk = (it + 3) << 6;
        if (nk < K) {
            ISSUE_STAGE((it + 3) & 3, nk);
        }
        CPCOMMIT();

        const __half* ah = sm + (it & 3) * STG_E;
        const __half* bsh = ah + A_EL;

        #pragma unroll
        for (int kc = 0; kc < 4; ++kc) {
            uint32_t a_f[2][4];
            int af = lane & 15;
            int ac = kc * 16 + ((lane >> 4) << 3);
            #pragma unroll
            for (int mt = 0; mt < 2; ++mt) {
                uint32_t ad = sptr(ah + (wm + mt * 16 + af) * AST2 + ac);
                LDSM4(a_f[mt][0], a_f[mt][1], a_f[mt][2], a_f[mt][3], ad);
            }
            int bkr = kc * 16 + (lane & 15);
            #pragma unroll
            for (int p = 0; p < 4; ++p) {
                int bnc = wn + p * 16 + ((lane >> 4) << 3);
                uint32_t b0, b1, b2, b3;
                uint32_t bd = sptr(bsh + bkr * BST2 + bnc);
                LDSM4T(b0, b1, b2, b3, bd);
                MMA16816(acc[0][2*p],   a_f[0], b0, b1);
                MMA16816(acc[0][2*p+1], a_f[0], b2, b3);
                MMA16816(acc[1][2*p],   a_f[1], b0, b1);
                MMA16816(acc[1][2*p+1], a_f[1], b2, b3);
            }
        }
        // no trailing sync: stage (it&3) is rewritten only in iteration it+1,
        // after that iteration's top-of-loop __syncthreads.
    }

    #pragma unroll
    for (int mt = 0; mt < 2; ++mt) {
        int row = by * 128 + wm + mt * 16 + (lane >> 2);
        #pragma unroll
        for (int nt = 0; nt < 8; ++nt) {
            int col = bx * 256 + wn + nt * 8 + ((lane & 3) << 1);
            float2 bv = *(const float2*)(bias + col);
            float v0 = acc[mt][nt][0] + bv.x;
            float v1 = acc[mt][nt][1] + bv.y;
            float v2 = acc[mt][nt][2] + bv.x;
            float v3 = acc[mt][nt][3] + bv.y;
            if (mode == 0) {
                float2 o0 = {v0, v1}, o1 = {v2, v3};
                *(float2*)(C + (size_t)row * N + col)       = o0;
                *(float2*)(C + (size_t)(row + 8) * N + col) = o1;
            } else {
                if (mode == 1) {
                    v0 = fmaxf(v0, 0.f); v1 = fmaxf(v1, 0.f);
                    v2 = fmaxf(v2, 0.f); v3 = fmaxf(v3, 0.f);
                }
                *(uint32_t*)(Ch + (size_t)row * N + col)       = packh2(v0, v1);
                *(uint32_t*)(Ch + (size_t)(row + 8) * N + col) = packh2(v2, v3);
            }
        }
    }
}

// ===================== tensor-core causal flash attention ==================
// 128 threads (4 warps), 64 queries of one (b,h), 64-key tiles, double-buffered.
// Single fp16 planes: S = Qh Kh^T,  O += Ph Vh.
#define APAD 72
#define AQBUF 4608                    // 64*72
#define AKV0 AQBUF                    // after Q
#define AKVSTRIDE (2 * AQBUF)         // kh, vh per stage
#define ATT_SMEM ((AQBUF + 2 * AKVSTRIDE) * 2)   // 46080 bytes

__global__ void __launch_bounds__(128, 3)
attn_mma(const __half* __restrict__ qh,
         __half* __restrict__ oh) {
    extern __shared__ __half sm[];
    const int tid = threadIdx.x;
    const int wid = tid >> 5, lane = tid & 31;
    const int qb = gridDim.x - 1 - blockIdx.x;
    const int bh = blockIdx.y;
    const int h = bh & (H_ - 1), b = bh >> 4;
    const int wq0 = wid << 4;

    const size_t seqbase = (size_t)(b * S_) * 3072 + h * 64;

    // Q tile
    {
        #pragma unroll
        for (int i = 0; i < 4; ++i) {
            int id = tid + i * 128;
            int row = id >> 3, col = (id & 7) << 3;
            size_t src = seqbase + (size_t)(qb * 64 + row) * 3072 + col;
            CP16(sptr(sm + row * APAD + col), qh + src);
        }
        CPCOMMIT();
    }
    #define ISSUE_KV(STG, KT0) do {                                         \
        __half* _kb = sm + AKV0 + (STG) * AKVSTRIDE;                        \
        _Pragma("unroll")                                                   \
        for (int i = 0; i < 4; ++i) {                                       \
            int id = tid + i * 128;                                         \
            int row = id >> 3, col = (id & 7) << 3;                         \
            size_t src = seqbase + (size_t)((KT0) * 64 + row) * 3072 + col; \
            uint32_t dst = sptr(_kb + row * APAD + col);                    \
            CP16(dst,              qh + src + 1024);                        \
            CP16(dst + AQBUF * 2,  qh + src + 2048);                        \
        }                                                                   \
        CPCOMMIT();                                                         \
    } while (0)

    ISSUE_KV(0, 0);
    ISSUE_KV(1, (qb >= 1 ? 1 : 0));

    CPWAIT2();
    __syncthreads();
    uint32_t qf[4][4];
    {
        int af = lane & 15;
        #pragma unroll
        for (int kc = 0; kc < 4; ++kc) {
            int ac = kc * 16 + ((lane >> 4) << 3);
            uint32_t ad = sptr(sm + (wq0 + af) * APAD + ac);
            LDSM4(qf[kc][0], qf[kc][1], qf[kc][2], qf[kc][3], ad);
        }
    }

    float Od[8][4];
    #pragma unroll
    for (int i = 0; i < 8; ++i)
        #pragma unroll
        for (int j = 0; j < 4; ++j) Od[i][j] = 0.f;
    float m_a = -1e30f, m_b = -1e30f, den_a = 0.f, den_b = 0.f;

    int buf = 0;
    const int ntk = qb + 1;
    for (int kt = 0; kt < ntk; ++kt) {
        CPWAIT1();
        __syncthreads();

        const __half* kh = sm + AKV0 + buf * AKVSTRIDE;
        const __half* vh = kh + AQBUF;

        float sreg[8][4];
        #pragma unroll
        for (int i = 0; i < 8; ++i)
            #pragma unroll
            for (int j = 0; j < 4; ++j) sreg[i][j] = 0.f;

        #pragma unroll
        for (int kc = 0; kc < 4; ++kc) {
            int krow = ((lane >> 4) << 3) + (lane & 7);
            int kcol = kc * 16 + (((lane >> 3) & 1) << 3);
            #pragma unroll
            for (int ng = 0; ng < 4; ++ng) {
                uint32_t bh0, bh1, bh2, bh3;
                uint32_t ad = sptr(kh + (ng * 16 + krow) * APAD + kcol);
                LDSM4(bh0, bh1, bh2, bh3, ad);
                MMA16816(sreg[2*ng],   qf[kc], bh0, bh1);
                MMA16816(sreg[2*ng+1], qf[kc], bh2, bh3);
            }
        }

        int ra = wq0 + (lane >> 2);
        int cb = (lane & 3) << 1;
        #pragma unroll
        for (int nt = 0; nt < 8; ++nt) {
            #pragma unroll
            for (int j = 0; j < 4; ++j) {
                float s = sreg[nt][j] * 0.125f;
                if (kt == qb) {
                    int col = nt * 8 + cb + (j & 1);
                    int row = ra + ((j >> 1) << 3);
                    if (col > row) s = -1e30f;
                }
                sreg[nt][j] = s;
            }
        }
        float mxa = -1e30f, mxb = -1e30f;
        #pragma unroll
        for (int nt = 0; nt < 8; ++nt) {
            mxa = fmaxf(mxa, fmaxf(sreg[nt][0], sreg[nt][1]));
            mxb = fmaxf(mxb, fmaxf(sreg[nt][2], sreg[nt][3]));
        }
        mxa = fmaxf(mxa, __shfl_xor_sync(0xffffffffu, mxa, 1));
        mxa = fmaxf(mxa, __shfl_xor_sync(0xffffffffu, mxa, 2));
        mxb = fmaxf(mxb, __shfl_xor_sync(0xffffffffu, mxb, 1));
        mxb = fmaxf(mxb, __shfl_xor_sync(0xffffffffu, mxb, 2));
        float mna = fmaxf(m_a, mxa), mnb = fmaxf(m_b, mxb);
        float ca = __expf(m_a - mna), cbr = __expf(m_b - mnb);
        m_a = mna; m_b = mnb;
        float sa = 0.f, sb = 0.f;
        #pragma unroll
        for (int nt = 0; nt < 8; ++nt) {
            float p0 = __expf(sreg[nt][0] - mna);
            float p1 = __expf(sreg[nt][1] - mna);
            float p2 = __expf(sreg[nt][2] - mnb);
            float p3 = __expf(sreg[nt][3] - mnb);
            sreg[nt][0] = p0; sreg[nt][1] = p1; sreg[nt][2] = p2; sreg[nt][3] = p3;
            sa += p0 + p1; sb += p2 + p3;
        }
        sa += __shfl_xor_sync(0xffffffffu, sa, 1);
        sa += __shfl_xor_sync(0xffffffffu, sa, 2);
        sb += __shfl_xor_sync(0xffffffffu, sb, 1);
        sb += __shfl_xor_sync(0xffffffffu, sb, 2);
        den_a = den_a * ca + sa;
        den_b = den_b * cbr + sb;
        #pragma unroll
        for (int nt = 0; nt < 8; ++nt) {
            Od[nt][0] *= ca;  Od[nt][1] *= ca;
            Od[nt][2] *= cbr; Od[nt][3] *= cbr;
        }

        // O += P @ Vh, P fp16-rounded in registers
        #pragma unroll
        for (int kc2 = 0; kc2 < 4; ++kc2) {
            uint32_t ph[4];
            ph[0] = packh2(sreg[2*kc2][0],   sreg[2*kc2][1]);
            ph[1] = packh2(sreg[2*kc2][2],   sreg[2*kc2][3]);
            ph[2] = packh2(sreg[2*kc2+1][0], sreg[2*kc2+1][1]);
            ph[3] = packh2(sreg[2*kc2+1][2], sreg[2*kc2+1][3]);
            int vr = kc2 * 16 + (lane & 15);
            #pragma unroll
            for (int ng = 0; ng < 4; ++ng) {
                int vc = ng * 16 + ((lane >> 4) << 3);
                uint32_t v0, v1, v2, v3;
                uint32_t ad = sptr(vh + vr * APAD + vc);
                LDSM4T(v0, v1, v2, v3, ad);
                MMA16816(Od[2*ng],   ph, v0, v1);
                MMA16816(Od[2*ng+1], ph, v2, v3);
            }
        }
        __syncthreads();
        if (kt + 2 <= qb) ISSUE_KV(buf, kt + 2);
        CPCOMMIT();
        buf ^= 1;
    }

    CPWAITALL();

    float inva = 1.f / den_a, invb = 1.f / den_b;
    int gq_a = qb * 64 + wq0 + (lane >> 2);
    size_t oa = (size_t)(b * S_ + gq_a) * D_ + h * 64 + ((lane & 3) << 1);
    size_t ob = oa + (size_t)8 * D_;
    #pragma unroll
    for (int nt = 0; nt < 8; ++nt) {
        *(uint32_t*)(oh + oa + nt * 8) = packh2(Od[nt][0] * inva, Od[nt][1] * inva);
        *(uint32_t*)(oh + ob + nt * 8) = packh2(Od[nt][2] * invb, Od[nt][3] * invb);
    }
}

// ---------------- fused residual add + LayerNorm (+ fp16 out) -------------
__global__ void add_ln_kernel(float* __restrict__ x,
                              const float* __restrict__ r,
                              const float* __restrict__ g,
                              const float* __restrict__ bb,
                              __half* __restrict__ xh) {
    int row = blockIdx.x;
    int tid = threadIdx.x;
    size_t base = (size_t)row * D_;
    float v[4];
    float s = 0.f;
    #pragma unroll
    for (int j = 0; j < 4; ++j) {
        int c = tid + j * 256;
        v[j] = x[base + c] + r[base + c];
        s += v[j];
    }
    __shared__ float sh[8];
    #pragma unroll
    for (int off = 16; off > 0; off >>= 1) s += __shfl_xor_sync(0xffffffffu, s, off);
    if ((tid & 31) == 0) sh[tid >> 5] = s;
    __syncthreads();
    if (tid < 32) {
        float t = (tid < 8) ? sh[tid] : 0.f;
        #pragma unroll
        for (int off = 4; off > 0; off >>= 1) t += __shfl_xor_sync(0xffffffffu, t, off);
        if (tid == 0) sh[0] = t;
    }
    __syncthreads();
    float mu = sh[0] * (1.f / 1024.f);
    __syncthreads();
    float ss = 0.f;
    #pragma unroll
    for (int j = 0; j < 4; ++j) { float d = v[j] - mu; ss += d * d; }
    #pragma unroll
    for (int off = 16; off > 0; off >>= 1) ss += __shfl_xor_sync(0xffffffffu, ss, off);
    if ((tid & 31) == 0) sh[tid >> 5] = ss;
    __syncthreads();
    if (tid < 32) {
        float t = (tid < 8) ? sh[tid] : 0.f;
        #pragma unroll
        for (int off = 4; off > 0; off >>= 1) t += __shfl_xor_sync(0xffffffffu, t, off);
        if (tid == 0) sh[0] = t;
    }
    __syncthreads();
    float var = sh[0] * (1.f / 1024.f);
    float rstd = rsqrtf(var + 1e-5f);
    #pragma unroll
    for (int j = 0; j < 4; ++j) {
        int c = tid + j * 256;
        float y = (v[j] - mu) * rstd * g[c] + bb[c];
        x[base + c] = y;
        xh[base + c] = __float2half_rn(y);
    }
}

// ---------------------------------------------------------------------------
extern "C" void kernel_launch(void* const* d_in, const int* in_sizes, int n_in,
                              void* d_out, int out_size) {
    const int*   tokens = (const int*)  d_in[0];
    const float* emb    = (const float*)d_in[1];
    const float* qkv_w  = (const float*)d_in[2];
    const float* qkv_b  = (const float*)d_in[3];
    const float* out_w  = (const float*)d_in[4];
    const float* out_b  = (const float*)d_in[5];
    const float* fc1_w  = (const float*)d_in[6];
    const float* fc1_b  = (const float*)d_in[7];
    const float* fc2_w  = (const float*)d_in[8];
    const float* fc2_b  = (const float*)d_in[9];
    const float* ln1_g  = (const float*)d_in[10];
    const float* ln1_b  = (const float*)d_in[11];
    const float* ln2_g  = (const float*)d_in[12];
    const float* ln2_b  = (const float*)d_in[13];
    const float* w_out  = (const float*)d_in[14];
    const float* b_out  = (const float*)d_in[15];
    float* out = (float*)d_out;

    float *x, *tmp, *o;
    __half *xh, *oh, *hh, *wh;
    cudaGetSymbolAddress((void**)&x,   g_x);
    cudaGetSymbolAddress((void**)&tmp, g_tmp);
    cudaGetSymbolAddress((void**)&o,   g_o);
    cudaGetSymbolAddress((void**)&xh,  g_xh);
    cudaGetSymbolAddress((void**)&oh,  g_oh);
    cudaGetSymbolAddress((void**)&hh,  g_hh);
    cudaGetSymbolAddress((void**)&wh,  g_wh);

    cudaFuncSetAttribute(mma_gemm, cudaFuncAttributeMaxDynamicSharedMemorySize,
                         GEMM_SMEM);
    cudaFuncSetAttribute(attn_mma, cudaFuncAttributeMaxDynamicSharedMemorySize,
                         ATT_SMEM);

    embed_kernel<<<TOK_, 256>>>(tokens, emb, x, xh);

    for (int l = 0; l < L_; ++l) {
        // qkv = x @ qkv_w + b -> fp16 (mode 2) into hh
        int nqkv = D_ * 3 * D_;
        cvt_kernel<<<nqkv / 1024, 256>>>(qkv_w + (size_t)l * nqkv, wh, nqkv);
        mma_gemm<<<dim3(3072 / 256, TOK_ / 128), 512, GEMM_SMEM>>>(
            xh, wh, qkv_b + (size_t)l * 3 * D_,
            nullptr, hh, 3 * D_, D_, 2);
        // attention -> oh
        attn_mma<<<dim3(S_ / 64, B_ * H_), 128, ATT_SMEM>>>(hh, oh);
        // out proj -> tmp fp32
        int nout = D_ * D_;
        cvt_kernel<<<nout / 1024, 256>>>(out_w + (size_t)l * nout, wh, nout);
        mma_gemm<<<dim3(D_ / 256, TOK_ / 128), 512, GEMM_SMEM>>>(
            oh, wh, out_b + (size_t)l * D_,
            tmp, nullptr, D_, D_, 0);
        add_ln_kernel<<<TOK_, 256>>>(x, tmp, ln1_g + l * D_, ln1_b + l * D_, xh);
        // fc1 (relu, fp16)
        int nfc1 = D_ * FF_;
        cvt_kernel<<<nfc1 / 1024, 256>>>(fc1_w + (size_t)l * nfc1, wh, nfc1);
        mma_gemm<<<dim3(FF_ / 256, TOK_ / 128), 512, GEMM_SMEM>>>(
            xh, wh, fc1_b + (size_t)l * FF_,
            nullptr, hh, FF_, D_, 1);
        // fc2
        int nfc2 = FF_ * D_;
        cvt_kernel<<<nfc2 / 1024, 256>>>(fc2_w + (size_t)l * nfc2, wh, nfc2);
        mma_gemm<<<dim3(D_ / 256, TOK_ / 128), 512, GEMM_SMEM>>>(
            hh, wh, fc2_b + (size_t)l * D_,
            o, nullptr, D_, FF_, 0);
        add_ln_kernel<<<TOK_, 256>>>(x, o, ln2_g + l * D_, ln2_b + l * D_, xh);
    }

    // logits
    int nlog = D_ * V_;
    cvt_kernel<<<nlog / 1024, 256>>>(w_out, wh, nlog);
    mma_gemm<<<dim3(V_ / 256, TOK_ / 128), 512, GEMM_SMEM>>>(
        xh, wh, b_out, out, nullptr, V_, D_, 0);
}

// round 12
// speedup vs baseline: 12.8858x; 1.0190x over previous
#include <cuda_runtime.h>
#include <cuda_fp16.h>
#include <math.h>
#include <stdint.h>

#define B_ 2
#define S_ 2048
#define D_ 1024
#define L_ 6
#define H_ 16
#define HD_ 64
#define FF_ 4096
#define V_ 32000
#define TOK_ (B_ * S_)          // 4096 token rows

// ---------------- scratch (static device globals; no allocation) ----------
__device__ float g_x[TOK_ * D_];                 // fp32 residual stream
__device__ float g_tmp[TOK_ * FF_];              // out-proj / fc2 fp32 out
__device__ float g_o[TOK_ * D_];                 // fc2 out (pre-LN2)
__device__ __half g_xh[TOK_ * D_];               // x (fp16 plane)
__device__ __half g_oh[TOK_ * D_];               // attention out
__device__ __half g_hh[TOK_ * FF_];              // qkv / ffn hidden (fp16)
// preconverted fp16 weights, layout [K][N] per layer
__device__ __half g_wqkv[(size_t)L_ * D_ * 3 * D_];
__device__ __half g_wout[(size_t)L_ * D_ * D_];
__device__ __half g_wfc1[(size_t)L_ * D_ * FF_];
__device__ __half g_wfc2[(size_t)L_ * FF_ * D_];
__device__ __half g_wlog[(size_t)D_ * V_];

__device__ __forceinline__ uint32_t packh2(float x, float y) {
    __half2 t = __floats2half2_rn(x, y);
    return *reinterpret_cast<uint32_t*>(&t);
}

// ---------------- PTX helpers ----------------------------------------------
__device__ __forceinline__ uint32_t sptr(const void* p) {
    return (uint32_t)__cvta_generic_to_shared(p);
}
#define LDSM4(R0, R1, R2, R3, ADDR) \
    asm volatile("ldmatrix.sync.aligned.m8n8.x4.shared.b16 {%0,%1,%2,%3}, [%4];" \
                 : "=r"(R0), "=r"(R1), "=r"(R2), "=r"(R3) : "r"(ADDR))
#define LDSM4T(R0, R1, R2, R3, ADDR) \
    asm volatile("ldmatrix.sync.aligned.m8n8.x4.trans.shared.b16 {%0,%1,%2,%3}, [%4];" \
                 : "=r"(R0), "=r"(R1), "=r"(R2), "=r"(R3) : "r"(ADDR))
#define MMA16816(Cv, Ar, Bb0, Bb1) \
    asm volatile("mma.sync.aligned.m16n8k16.row.col.f32.f16.f16.f32 " \
                 "{%0,%1,%2,%3},{%4,%5,%6,%7},{%8,%9},{%0,%1,%2,%3};" \
                 : "+f"(Cv[0]), "+f"(Cv[1]), "+f"(Cv[2]), "+f"(Cv[3]) \
                 : "r"(Ar[0]), "r"(Ar[1]), "r"(Ar[2]), "r"(Ar[3]), \
                   "r"(Bb0), "r"(Bb1))
#define EX2X2(D, S) \
    asm volatile("ex2.approx.f16x2 %0, %1;" : "=r"(D) : "r"(S))
#define CP16(DST, SRC) \
    asm volatile("cp.async.cg.shared.global [%0], [%1], 16;" :: "r"(DST), "l"(SRC))
#define CPCOMMIT() asm volatile("cp.async.commit_group;")
#define CPWAIT1()  asm volatile("cp.async.wait_group 1;")
#define CPWAIT2()  asm volatile("cp.async.wait_group 2;")
#define CPWAITALL() asm volatile("cp.async.wait_all;")

#define HALF2_ONES 0x3C003C00u

// ---------------- weight convert: fp32 -> fp16 (same [K][N] layout) -------
__global__ void cvt_kernel(const float* __restrict__ in,
                           __half* __restrict__ hi, int n) {
    int i = (blockIdx.x * 256 + threadIdx.x) * 4;
    if (i >= n) return;
    float4 v = *(const float4*)(in + i);
    *(uint32_t*)(hi + i)     = packh2(v.x, v.y);
    *(uint32_t*)(hi + i + 2) = packh2(v.z, v.w);
}

// ---------------- embedding + positional encoding (+ fp16 out) ------------
__global__ void embed_kernel(const int* __restrict__ tokens,
                             const float* __restrict__ emb,
                             float* __restrict__ x,
                             __half* __restrict__ xh) {
    int row = blockIdx.x;
    int s   = row & (S_ - 1);
    int tok = tokens[row];
    const float* erow = emb + (size_t)tok * D_;
    size_t base = (size_t)row * D_;
    const float kfac = -0.00899447301950812f;   // -ln(10000)/1024
    #pragma unroll
    for (int j = 0; j < 4; ++j) {
        int c = threadIdx.x + j * 256;
        float freq = expf(kfac * (float)(c & ~1));
        float arg  = (float)s * freq;
        float pe   = (c & 1) ? cosf(arg) : sinf(arg);
        float v = erow[c] + pe;
        x[base + c] = v;
        xh[base + c] = __float2half_rn(v);
    }
}

// ===================== fp16 tensor-core GEMM (single-term) =================
// C = Ah[MxK] @ Bh[KxN] + bias, fp32 accum.
// 512 threads = 16 warps (4m x 4n), warp tile 32x64, block tile 128x256x64.
// 4-stage cp.async pipeline, one __syncthreads per k-chunk.
#define AST2 72
#define BST2 264
#define A_EL (128 * AST2)                 // 9216
#define B_EL2 (64 * BST2)                 // 16896
#define STG_E (A_EL + B_EL2)              // 26112 elems
#define GEMM_SMEM (4 * STG_E * 2)         // 208896 bytes

#define ISSUE_STAGE(SIDX, K0) do {                                           \
    __half* _b = sm + (SIDX) * STG_E;                                        \
    _Pragma("unroll")                                                        \
    for (int _i = 0; _i < 2; ++_i) {                                         \
        int _id = tid + _i * 512;                                            \
        int _r = _id >> 3, _c = (_id & 7) << 3;                              \
        CP16(sptr(_b + _r * AST2 + _c), gA + (size_t)_r * K + (K0) + _c);    \
    }                                                                        \
    _Pragma("unroll")                                                        \
    for (int _i = 0; _i < 4; ++_i) {                                         \
        int _id = tid + _i * 512;                                            \
        int _r = _id >> 5, _c = (_id & 31) << 3;                             \
        CP16(sptr(_b + A_EL + _r * BST2 + _c),                               \
             gB + (size_t)((K0) + _r) * N + _c);                             \
    }                                                                        \
} while (0)

// mode 0: fp32 C. mode 1: relu + fp16. mode 2: fp16 (no relu).
__global__ void __launch_bounds__(512, 1)
mma_gemm(const __half* __restrict__ Ah,
         const __half* __restrict__ Bh,
         const float* __restrict__ bias,
         float* __restrict__ C,
         __half* __restrict__ Ch,
         int N, int K, int mode) {
    extern __shared__ __half sm[];

    const int tid = threadIdx.x;
    const int wid = tid >> 5, lane = tid & 31;
    const int wm = (wid >> 2) << 5;     // 0..96
    const int wn = (wid & 3) << 6;      // 0..192
    const int bx = blockIdx.x, by = blockIdx.y;

    const __half* gA = Ah + (size_t)(by * 128) * K;
    const __half* gB = Bh + bx * 256;

    float acc[2][8][4];
    #pragma unroll
    for (int i = 0; i < 2; ++i)
        #pragma unroll
        for (int j = 0; j < 8; ++j)
            #pragma unroll
            for (int t = 0; t < 4; ++t) acc[i][j][t] = 0.f;

    ISSUE_STAGE(0, 0);   CPCOMMIT();
    ISSUE_STAGE(1, 64);  CPCOMMIT();
    ISSUE_STAGE(2, 128); CPCOMMIT();

    const int ntile = K >> 6;
    for (int it = 0; it < ntile; ++it) {
        CPWAIT2();
        __syncthreads();

        int nk = (it + 3) << 6;
        if (nk < K) {
            ISSUE_STAGE((it + 3) & 3, nk);
        }
        CPCOMMIT();

        const __half* ah = sm + (it & 3) * STG_E;
        const __half* bsh = ah + A_EL;

        #pragma unroll
        for (int kc = 0; kc < 4; ++kc) {
            uint32_t a_f[2][4];
            int af = lane & 15;
            int ac = kc * 16 + ((lane >> 4) << 3);
            #pragma unroll
            for (int mt = 0; mt < 2; ++mt) {
                uint32_t ad = sptr(ah + (wm + mt * 16 + af) * AST2 + ac);
                LDSM4(a_f[mt][0], a_f[mt][1], a_f[mt][2], a_f[mt][3], ad);
            }
            int bkr = kc * 16 + (lane & 15);
            #pragma unroll
            for (int p = 0; p < 4; ++p) {
                int bnc = wn + p * 16 + ((lane >> 4) << 3);
                uint32_t b0, b1, b2, b3;
                uint32_t bd = sptr(bsh + bkr * BST2 + bnc);
                LDSM4T(b0, b1, b2, b3, bd);
                MMA16816(acc[0][2*p],   a_f[0], b0, b1);
                MMA16816(acc[0][2*p+1], a_f[0], b2, b3);
                MMA16816(acc[1][2*p],   a_f[1], b0, b1);
                MMA16816(acc[1][2*p+1], a_f[1], b2, b3);
            }
        }
        // no trailing sync: stage (it&3) is rewritten only in iteration it+1,
        // after that iteration's top-of-loop __syncthreads.
    }

    #pragma unroll
    for (int mt = 0; mt < 2; ++mt) {
        int row = by * 128 + wm + mt * 16 + (lane >> 2);
        #pragma unroll
        for (int nt = 0; nt < 8; ++nt) {
            int col = bx * 256 + wn + nt * 8 + ((lane & 3) << 1);
            float2 bv = *(const float2*)(bias + col);
            float v0 = acc[mt][nt][0] + bv.x;
            float v1 = acc[mt][nt][1] + bv.y;
            float v2 = acc[mt][nt][2] + bv.x;
            float v3 = acc[mt][nt][3] + bv.y;
            if (mode == 0) {
                float2 o0 = {v0, v1}, o1 = {v2, v3};
                *(float2*)(C + (size_t)row * N + col)       = o0;
                *(float2*)(C + (size_t)(row + 8) * N + col) = o1;
            } else {
                if (mode == 1) {
                    v0 = fmaxf(v0, 0.f); v1 = fmaxf(v1, 0.f);
                    v2 = fmaxf(v2, 0.f); v3 = fmaxf(v3, 0.f);
                }
                *(uint32_t*)(Ch + (size_t)row * N + col)       = packh2(v0, v1);
                *(uint32_t*)(Ch + (size_t)(row + 8) * N + col) = packh2(v2, v3);
            }
        }
    }
}

// ===================== tensor-core causal flash attention ==================
// 128 threads (4 warps), 64 queries of one (b,h), 64-key tiles, double-buffered.
// log2-domain softmax: scale = 0.125*log2(e); P via ex2.approx.f16x2;
// denominator via extra MMA against all-ones B fragment (exact fp32).
#define APAD 72
#define AQBUF 4608                    // 64*72
#define AKV0 AQBUF                    // after Q
#define AKVSTRIDE (2 * AQBUF)         // kh, vh per stage
#define ATT_SMEM ((AQBUF + 2 * AKVSTRIDE) * 2)   // 46080 bytes
#define SCALE_LOG2 0.1803368801111f   // 0.125 * log2(e)

__global__ void __launch_bounds__(128, 3)
attn_mma(const __half* __restrict__ qh,
         __half* __restrict__ oh) {
    extern __shared__ __half sm[];
    const int tid = threadIdx.x;
    const int wid = tid >> 5, lane = tid & 31;
    const int qb = gridDim.x - 1 - blockIdx.x;
    const int bh = blockIdx.y;
    const int h = bh & (H_ - 1), b = bh >> 4;
    const int wq0 = wid << 4;

    const size_t seqbase = (size_t)(b * S_) * 3072 + h * 64;

    // Q tile
    {
        #pragma unroll
        for (int i = 0; i < 4; ++i) {
            int id = tid + i * 128;
            int row = id >> 3, col = (id & 7) << 3;
            size_t src = seqbase + (size_t)(qb * 64 + row) * 3072 + col;
            CP16(sptr(sm + row * APAD + col), qh + src);
        }
        CPCOMMIT();
    }
    #define ISSUE_KV(STG, KT0) do {                                         \
        __half* _kb = sm + AKV0 + (STG) * AKVSTRIDE;                        \
        _Pragma("unroll")                                                   \
        for (int i = 0; i < 4; ++i) {                                       \
            int id = tid + i * 128;                                         \
            int row = id >> 3, col = (id & 7) << 3;                         \
            size_t src = seqbase + (size_t)((KT0) * 64 + row) * 3072 + col; \
            uint32_t dst = sptr(_kb + row * APAD + col);                    \
            CP16(dst,              qh + src + 1024);                        \
            CP16(dst + AQBUF * 2,  qh + src + 2048);                        \
        }                                                                   \
        CPCOMMIT();                                                         \
    } while (0)

    ISSUE_KV(0, 0);
    ISSUE_KV(1, (qb >= 1 ? 1 : 0));

    CPWAIT2();
    __syncthreads();
    uint32_t qf[4][4];
    {
        int af = lane & 15;
        #pragma unroll
        for (int kc = 0; kc < 4; ++kc) {
            int ac = kc * 16 + ((lane >> 4) << 3);
            uint32_t ad = sptr(sm + (wq0 + af) * APAD + ac);
            LDSM4(qf[kc][0], qf[kc][1], qf[kc][2], qf[kc][3], ad);
        }
    }

    float Od[8][4];
    #pragma unroll
    for (int i = 0; i < 8; ++i)
        #pragma unroll
        for (int j = 0; j < 4; ++j) Od[i][j] = 0.f;
    float dacc[4] = {0.f, 0.f, 0.f, 0.f};       // denominator accumulator (MMA)
    float m_a = -1e30f, m_b = -1e30f;

    int buf = 0;
    const int ntk = qb + 1;
    for (int kt = 0; kt < ntk; ++kt) {
        CPWAIT1();
        __syncthreads();

        const __half* kh = sm + AKV0 + buf * AKVSTRIDE;
        const __half* vh = kh + AQBUF;

        float sreg[8][4];
        #pragma unroll
        for (int i = 0; i < 8; ++i)
            #pragma unroll
            for (int j = 0; j < 4; ++j) sreg[i][j] = 0.f;

        #pragma unroll
        for (int kc = 0; kc < 4; ++kc) {
            int krow = ((lane >> 4) << 3) + (lane & 7);
            int kcol = kc * 16 + (((lane >> 3) & 1) << 3);
            #pragma unroll
            for (int ng = 0; ng < 4; ++ng) {
                uint32_t bh0, bh1, bh2, bh3;
                uint32_t ad = sptr(kh + (ng * 16 + krow) * APAD + kcol);
                LDSM4(bh0, bh1, bh2, bh3, ad);
                MMA16816(sreg[2*ng],   qf[kc], bh0, bh1);
                MMA16816(sreg[2*ng+1], qf[kc], bh2, bh3);
            }
        }

        // scale to log2 domain + causal mask
        int ra = wq0 + (lane >> 2);
        int cb = (lane & 3) << 1;
        #pragma unroll
        for (int nt = 0; nt < 8; ++nt) {
            #pragma unroll
            for (int j = 0; j < 4; ++j) {
                float s = sreg[nt][j] * SCALE_LOG2;
                if (kt == qb) {
                    int col = nt * 8 + cb + (j & 1);
                    int row = ra + ((j >> 1) << 3);
                    if (col > row) s = -1e30f;
                }
                sreg[nt][j] = s;
            }
        }
        // row max (log2 domain)
        float mxa = -1e30f, mxb = -1e30f;
        #pragma unroll
        for (int nt = 0; nt < 8; ++nt) {
            mxa = fmaxf(mxa, fmaxf(sreg[nt][0], sreg[nt][1]));
            mxb = fmaxf(mxb, fmaxf(sreg[nt][2], sreg[nt][3]));
        }
        mxa = fmaxf(mxa, __shfl_xor_sync(0xffffffffu, mxa, 1));
        mxa = fmaxf(mxa, __shfl_xor_sync(0xffffffffu, mxa, 2));
        mxb = fmaxf(mxb, __shfl_xor_sync(0xffffffffu, mxb, 1));
        mxb = fmaxf(mxb, __shfl_xor_sync(0xffffffffu, mxb, 2));
        float mna = fmaxf(m_a, mxa), mnb = fmaxf(m_b, mxb);
        float ca = exp2f(m_a - mna), cbr = exp2f(m_b - mnb);
        m_a = mna; m_b = mnb;
        #pragma unroll
        for (int nt = 0; nt < 8; ++nt) {
            Od[nt][0] *= ca;  Od[nt][1] *= ca;
            Od[nt][2] *= cbr; Od[nt][3] *= cbr;
        }
        dacc[0] *= ca;  dacc[1] *= ca;
        dacc[2] *= cbr; dacc[3] *= cbr;

        // P = 2^(s - m) directly as fp16 pairs; denominator via ones-MMA;
        // O += P @ Vh
        #pragma unroll
        for (int kc2 = 0; kc2 < 4; ++kc2) {
            uint32_t ph[4];
            uint32_t t0 = packh2(sreg[2*kc2][0]   - mna, sreg[2*kc2][1]   - mna);
            uint32_t t1 = packh2(sreg[2*kc2][2]   - mnb, sreg[2*kc2][3]   - mnb);
            uint32_t t2 = packh2(sreg[2*kc2+1][0] - mna, sreg[2*kc2+1][1] - mna);
            uint32_t t3 = packh2(sreg[2*kc2+1][2] - mnb, sreg[2*kc2+1][3] - mnb);
            EX2X2(ph[0], t0);
            EX2X2(ph[1], t1);
            EX2X2(ph[2], t2);
            EX2X2(ph[3], t3);
            MMA16816(dacc, ph, HALF2_ONES, HALF2_ONES);
            int vr = kc2 * 16 + (lane & 15);
            #pragma unroll
            for (int ng = 0; ng < 4; ++ng) {
                int vc = ng * 16 + ((lane >> 4) << 3);
                uint32_t v0, v1, v2, v3;
                uint32_t ad = sptr(vh + vr * APAD + vc);
                LDSM4T(v0, v1, v2, v3, ad);
                MMA16816(Od[2*ng],   ph, v0, v1);
                MMA16816(Od[2*ng+1], ph, v2, v3);
            }
        }
        __syncthreads();
        if (kt + 2 <= qb) ISSUE_KV(buf, kt + 2);
        CPCOMMIT();
        buf ^= 1;
    }

    CPWAITALL();

    // all n-columns of the ones-MMA result are identical -> dacc[0]/dacc[2]
    // hold the row sums for rows ra and ra+8 in every thread of the quad.
    float inva = 1.f / dacc[0], invb = 1.f / dacc[2];
    int gq_a = qb * 64 + wq0 + (lane >> 2);
    size_t oa = (size_t)(b * S_ + gq_a) * D_ + h * 64 + ((lane & 3) << 1);
    size_t ob = oa + (size_t)8 * D_;
    #pragma unroll
    for (int nt = 0; nt < 8; ++nt) {
        *(uint32_t*)(oh + oa + nt * 8) = packh2(Od[nt][0] * inva, Od[nt][1] * inva);
        *(uint32_t*)(oh + ob + nt * 8) = packh2(Od[nt][2] * invb, Od[nt][3] * invb);
    }
}

// ---------------- fused residual add + LayerNorm (+ fp16 out) -------------
__global__ void add_ln_kernel(float* __restrict__ x,
                              const float* __restrict__ r,
                              const float* __restrict__ g,
                              const float* __restrict__ bb,
                              __half* __restrict__ xh) {
    int row = blockIdx.x;
    int tid = threadIdx.x;
    size_t base = (size_t)row * D_;
    float v[4];
    float s = 0.f;
    #pragma unroll
    for (int j = 0; j < 4; ++j) {
        int c = tid + j * 256;
        v[j] = x[base + c] + r[base + c];
        s += v[j];
    }
    __shared__ float sh[8];
    #pragma unroll
    for (int off = 16; off > 0; off >>= 1) s += __shfl_xor_sync(0xffffffffu, s, off);
    if ((tid & 31) == 0) sh[tid >> 5] = s;
    __syncthreads();
    if (tid < 32) {
        float t = (tid < 8) ? sh[tid] : 0.f;
        #pragma unroll
        for (int off = 4; off > 0; off >>= 1) t += __shfl_xor_sync(0xffffffffu, t, off);
        if (tid == 0) sh[0] = t;
    }
    __syncthreads();
    float mu = sh[0] * (1.f / 1024.f);
    __syncthreads();
    float ss = 0.f;
    #pragma unroll
    for (int j = 0; j < 4; ++j) { float d = v[j] - mu; ss += d * d; }
    #pragma unroll
    for (int off = 16; off > 0; off >>= 1) ss += __shfl_xor_sync(0xffffffffu, ss, off);
    if ((tid & 31) == 0) sh[tid >> 5] = ss;
    __syncthreads();
    if (tid < 32) {
        float t = (tid < 8) ? sh[tid] : 0.f;
        #pragma unroll
        for (int off = 4; off > 0; off >>= 1) t += __shfl_xor_sync(0xffffffffu, t, off);
        if (tid == 0) sh[0] = t;
    }
    __syncthreads();
    float var = sh[0] * (1.f / 1024.f);
    float rstd = rsqrtf(var + 1e-5f);
    #pragma unroll
    for (int j = 0; j < 4; ++j) {
        int c = tid + j * 256;
        float y = (v[j] - mu) * rstd * g[c] + bb[c];
        x[base + c] = y;
        xh[base + c] = __float2half_rn(y);
    }
}

// ---------------------------------------------------------------------------
extern "C" void kernel_launch(void* const* d_in, const int* in_sizes, int n_in,
                              void* d_out, int out_size) {
    const int*   tokens = (const int*)  d_in[0];
    const float* emb    = (const float*)d_in[1];
    const float* qkv_w  = (const float*)d_in[2];
    const float* qkv_b  = (const float*)d_in[3];
    const float* out_w  = (const float*)d_in[4];
    const float* out_b  = (const float*)d_in[5];
    const float* fc1_w  = (const float*)d_in[6];
    const float* fc1_b  = (const float*)d_in[7];
    const float* fc2_w  = (const float*)d_in[8];
    const float* fc2_b  = (const float*)d_in[9];
    const float* ln1_g  = (const float*)d_in[10];
    const float* ln1_b  = (const float*)d_in[11];
    const float* ln2_g  = (const float*)d_in[12];
    const float* ln2_b  = (const float*)d_in[13];
    const float* w_out  = (const float*)d_in[14];
    const float* b_out  = (const float*)d_in[15];
    float* out = (float*)d_out;

    float *x, *tmp, *o;
    __half *xh, *oh, *hh, *wqkv, *wout, *wfc1, *wfc2, *wlog;
    cudaGetSymbolAddress((void**)&x,    g_x);
    cudaGetSymbolAddress((void**)&tmp,  g_tmp);
    cudaGetSymbolAddress((void**)&o,    g_o);
    cudaGetSymbolAddress((void**)&xh,   g_xh);
    cudaGetSymbolAddress((void**)&oh,   g_oh);
    cudaGetSymbolAddress((void**)&hh,   g_hh);
    cudaGetSymbolAddress((void**)&wqkv, g_wqkv);
    cudaGetSymbolAddress((void**)&wout, g_wout);
    cudaGetSymbolAddress((void**)&wfc1, g_wfc1);
    cudaGetSymbolAddress((void**)&wfc2, g_wfc2);
    cudaGetSymbolAddress((void**)&wlog, g_wlog);

    cudaFuncSetAttribute(mma_gemm, cudaFuncAttributeMaxDynamicSharedMemorySize,
                         GEMM_SMEM);
    cudaFuncSetAttribute(attn_mma, cudaFuncAttributeMaxDynamicSharedMemorySize,
                         ATT_SMEM);

    // ---- preconvert all weights (once per replay, fully parallel)
    {
        int n;
        n = L_ * D_ * 3 * D_;  cvt_kernel<<<n / 1024, 256>>>(qkv_w, wqkv, n);
        n = L_ * D_ * D_;      cvt_kernel<<<n / 1024, 256>>>(out_w, wout, n);
        n = L_ * D_ * FF_;     cvt_kernel<<<n / 1024, 256>>>(fc1_w, wfc1, n);
        n = L_ * FF_ * D_;     cvt_kernel<<<n / 1024, 256>>>(fc2_w, wfc2, n);
        n = D_ * V_;           cvt_kernel<<<n / 1024, 256>>>(w_out, wlog, n);
    }

    embed_kernel<<<TOK_, 256>>>(tokens, emb, x, xh);

    for (int l = 0; l < L_; ++l) {
        // qkv = x @ qkv_w + b -> fp16 (mode 2) into hh
        mma_gemm<<<dim3(3072 / 256, TOK_ / 128), 512, GEMM_SMEM>>>(
            xh, wqkv + (size_t)l * D_ * 3 * D_, qkv_b + (size_t)l * 3 * D_,
            nullptr, hh, 3 * D_, D_, 2);
        // attention -> oh
        attn_mma<<<dim3(S_ / 64, B_ * H_), 128, ATT_SMEM>>>(hh, oh);
        // out proj -> tmp fp32
        mma_gemm<<<dim3(D_ / 256, TOK_ / 128), 512, GEMM_SMEM>>>(
            oh, wout + (size_t)l * D_ * D_, out_b + (size_t)l * D_,
            tmp, nullptr, D_, D_, 0);
        add_ln_kernel<<<TOK_, 256>>>(x, tmp, ln1_g + l * D_, ln1_b + l * D_, xh);
        // fc1 (relu, fp16)
        mma_gemm<<<dim3(FF_ / 256, TOK_ / 128), 512, GEMM_SMEM>>>(
            xh, wfc1 + (size_t)l * D_ * FF_, fc1_b + (size_t)l * FF_,
            nullptr, hh, FF_, D_, 1);
        // fc2
        mma_gemm<<<dim3(D_ / 256, TOK_ / 128), 512, GEMM_SMEM>>>(
            hh, wfc2 + (size_t)l * FF_ * D_, fc2_b + (size_t)l * D_,
            o, nullptr, D_, FF_, 0);
        add_ln_kernel<<<TOK_, 256>>>(x, o, ln2_g + l * D_, ln2_b + l * D_, xh);
    }

    // logits
    mma_gemm<<<dim3(V_ / 256, TOK_ / 128), 512, GEMM_SMEM>>>(
        xh, wlog, b_out, out, nullptr, V_, D_, 0);
}